// round 1
// baseline (speedup 1.0000x reference)
#include <cuda_runtime.h>

// Problem dims
#define NL   6
#define TT   128
#define NB   256
#define ND   512
#define NH   8
#define NDFF 2048
#define NSUB 64
#define NTOK (TT * NB)   // 32768 tokens

// ---------------------------------------------------------------------------
// Scratch (no allocation allowed -> __device__ globals)
// ---------------------------------------------------------------------------
__device__ float g_s   [(size_t)NTOK * ND];    // spatio act, rows (t*NB+b)
__device__ float g_t   [(size_t)NTOK * ND];    // temporal act, rows (t*NB+b)
__device__ float g_scores[NH * TT * NB];       // [h][t][b]
__device__ float g_wts   [NH * TT * NB];       // [h][t][b]
__device__ float g_wm  [(size_t)NTOK * ND];    // relu(wts*msg), rows (b*TT+t)
__device__ float g_agg [(size_t)NTOK * ND];    // rows (b*TT+t)
__device__ float g_x   [(size_t)NTOK * ND];    // rows (b*TT+t)
__device__ float g_h1  [(size_t)NTOK * NDFF];  // rows (b*TT+t)
__device__ float g_y   [(size_t)NTOK * ND];    // rows (b*TT+t)
__device__ float g_src [(size_t)NTOK * ND];    // layer output, rows (t*NB+b)

// ---------------------------------------------------------------------------
// Block reductions (256 threads)
// ---------------------------------------------------------------------------
__device__ __forceinline__ float block_reduce_sum256(float v) {
    __shared__ float sh[8];
    int lane = threadIdx.x & 31, wid = threadIdx.x >> 5;
    #pragma unroll
    for (int o = 16; o; o >>= 1) v += __shfl_xor_sync(0xffffffffu, v, o);
    if (lane == 0) sh[wid] = v;
    __syncthreads();
    float r = (lane < 8) ? sh[lane] : 0.0f;
    #pragma unroll
    for (int o = 4; o; o >>= 1) r += __shfl_xor_sync(0xffffffffu, r, o);
    r = __shfl_sync(0xffffffffu, r, 0);
    __syncthreads();   // allow smem reuse on next call
    return r;
}

__device__ __forceinline__ float block_reduce_max256(float v) {
    __shared__ float sh[8];
    int lane = threadIdx.x & 31, wid = threadIdx.x >> 5;
    #pragma unroll
    for (int o = 16; o; o >>= 1) v = fmaxf(v, __shfl_xor_sync(0xffffffffu, v, o));
    if (lane == 0) sh[wid] = v;
    __syncthreads();
    float r = (lane < 8) ? sh[lane] : -3.4e38f;
    #pragma unroll
    for (int o = 4; o; o >>= 1) r = fmaxf(r, __shfl_xor_sync(0xffffffffu, r, o));
    r = __shfl_sync(0xffffffffu, r, 0);
    __syncthreads();
    return r;
}

// ---------------------------------------------------------------------------
// SGEMM: C[M,N] = A[M,K] @ W[N,K]^T + bias[N], optional relu.
// BM=BN=128, BK=8, 256 threads, 8x8 per thread. M,N %128==0, K %8==0.
// ---------------------------------------------------------------------------
template <int RELU>
__global__ __launch_bounds__(256)
void gemm_bias(const float* __restrict__ A, const float* __restrict__ W,
               const float* __restrict__ bias, float* __restrict__ C,
               int M, int N, int K) {
    __shared__ float As[8][132];   // padded: transpose-store conflict free
    __shared__ float Ws[8][132];

    const int tid = threadIdx.x;
    const int tx  = tid & 15;      // 0..15  (N direction)
    const int ty  = tid >> 4;      // 0..15  (M direction)

    const float* Ab = A + (size_t)blockIdx.y * 128 * K;
    const float* Wb = W + (size_t)blockIdx.x * 128 * K;

    const int lrow = tid >> 1;         // 0..127
    const int lcol = (tid & 1) * 4;    // 0 or 4

    float acc[8][8] = {};

    for (int k0 = 0; k0 < K; k0 += 8) {
        float4 av = *(const float4*)(Ab + (size_t)lrow * K + k0 + lcol);
        float4 wv = *(const float4*)(Wb + (size_t)lrow * K + k0 + lcol);
        As[lcol + 0][lrow] = av.x; As[lcol + 1][lrow] = av.y;
        As[lcol + 2][lrow] = av.z; As[lcol + 3][lrow] = av.w;
        Ws[lcol + 0][lrow] = wv.x; Ws[lcol + 1][lrow] = wv.y;
        Ws[lcol + 2][lrow] = wv.z; Ws[lcol + 3][lrow] = wv.w;
        __syncthreads();
        #pragma unroll
        for (int k = 0; k < 8; k++) {
            float af[8], wf[8];
            #pragma unroll
            for (int i = 0; i < 8; i++) af[i] = As[k][ty * 8 + i];
            #pragma unroll
            for (int j = 0; j < 8; j++) wf[j] = Ws[k][tx * 8 + j];
            #pragma unroll
            for (int i = 0; i < 8; i++)
                #pragma unroll
                for (int j = 0; j < 8; j++)
                    acc[i][j] += af[i] * wf[j];
        }
        __syncthreads();
    }

    #pragma unroll
    for (int i = 0; i < 8; i++) {
        int m = blockIdx.y * 128 + ty * 8 + i;
        #pragma unroll
        for (int j = 0; j < 8; j += 4) {
            int n = blockIdx.x * 128 + tx * 8 + j;
            float4 v;
            v.x = acc[i][j + 0] + bias[n + 0];
            v.y = acc[i][j + 1] + bias[n + 1];
            v.z = acc[i][j + 2] + bias[n + 2];
            v.w = acc[i][j + 3] + bias[n + 3];
            if (RELU) {
                v.x = fmaxf(v.x, 0.f); v.y = fmaxf(v.y, 0.f);
                v.z = fmaxf(v.z, 0.f); v.w = fmaxf(v.w, 0.f);
            }
            *(float4*)(C + (size_t)m * N + n) = v;
        }
    }
}

// ---------------------------------------------------------------------------
// scores[h][t][b] = sum_u s[t,b,h*64+u]*aw[h,u] + t[t,b,h*64+u]*aw[h,64+u] + ab[h]
// one warp per (h,t,b)
// ---------------------------------------------------------------------------
__global__ __launch_bounds__(256)
void scores_kernel(const float* __restrict__ aw, const float* __restrict__ ab) {
    int w    = blockIdx.x * 8 + (threadIdx.x >> 5);
    int lane = threadIdx.x & 31;
    int h    = w / (TT * NB);
    int rem  = w % (TT * NB);
    int t    = rem / NB;
    int b    = rem % NB;
    size_t base = ((size_t)(t * NB + b)) * ND + h * NSUB;
    const float* ah = aw + h * 2 * NSUB;
    float sum = g_s[base + lane]      * ah[lane]
              + g_s[base + lane + 32] * ah[lane + 32]
              + g_t[base + lane]      * ah[NSUB + lane]
              + g_t[base + lane + 32] * ah[NSUB + lane + 32];
    #pragma unroll
    for (int o = 16; o; o >>= 1) sum += __shfl_xor_sync(0xffffffffu, sum, o);
    if (lane == 0) g_scores[(h * TT + t) * NB + b] = sum + ab[h];
}

// softmax over b (axis=1 of [H,B,T]) -> rows of [h][t][:] are contiguous
__global__ __launch_bounds__(256)
void softmax_kernel() {
    int ht = blockIdx.x;                 // h*TT + t
    float v = g_scores[(size_t)ht * NB + threadIdx.x];
    float m = block_reduce_max256(v);
    float e = __expf(v - m);
    float s = block_reduce_sum256(e);
    g_wts[(size_t)ht * NB + threadIdx.x] = e / s;
}

// ---------------------------------------------------------------------------
// Per-head message: msg[u] = mw[h] @ (s*t)[tok] + mb[h];
// wm[b,t,h*64+u] = relu(wts[h,t,b] * msg[u]).
// Block: head h x 64 tokens (token p = b*TT + t). 256 threads, 4x4 micro-tile.
// ---------------------------------------------------------------------------
__global__ __launch_bounds__(256)
void msg_kernel(const float* __restrict__ mw, const float* __restrict__ mb) {
    __shared__ float prod[64][65];   // [token][s]
    __shared__ float mws [64][65];   // [s][u]
    __shared__ float wt_s[64];
    __shared__ float mb_s[64];

    const int h  = blockIdx.y;
    const int p0 = blockIdx.x * 64;
    const int tid = threadIdx.x;

    for (int i = tid; i < 64 * 64; i += 256) {
        int u = i >> 6, s = i & 63;
        mws[s][u] = mw[((size_t)h * 64 + u) * 64 + s];
    }
    if (tid < 64) {
        mb_s[tid] = mb[h * 64 + tid];
        int p = p0 + tid, b = p / TT, t = p % TT;
        wt_s[tid] = g_wts[(h * TT + t) * NB + b];
    }
    for (int i = tid; i < 64 * 64; i += 256) {
        int tok = i >> 6, u = i & 63;
        int p = p0 + tok, b = p / TT, t = p % TT;
        size_t idx = ((size_t)(t * NB + b)) * ND + h * NSUB + u;
        prod[tok][u] = g_s[idx] * g_t[idx];
    }
    __syncthreads();

    const int tx = tid & 15, ty = tid >> 4;
    float acc[4][4] = {};
    #pragma unroll 4
    for (int s = 0; s < 64; s++) {
        float a[4], w[4];
        #pragma unroll
        for (int i = 0; i < 4; i++) a[i] = prod[ty * 4 + i][s];
        #pragma unroll
        for (int j = 0; j < 4; j++) w[j] = mws[s][tx * 4 + j];
        #pragma unroll
        for (int i = 0; i < 4; i++)
            #pragma unroll
            for (int j = 0; j < 4; j++)
                acc[i][j] += a[i] * w[j];
    }
    #pragma unroll
    for (int i = 0; i < 4; i++) {
        int tok = ty * 4 + i;
        float wt = wt_s[tok];
        #pragma unroll
        for (int j = 0; j < 4; j++) {
            int u = tx * 4 + j;
            float v = wt * (acc[i][j] + mb_s[u]);
            g_wm[((size_t)(p0 + tok)) * ND + h * NSUB + u] = fmaxf(v, 0.f);
        }
    }
}

// ---------------------------------------------------------------------------
// LN1: x[b,t,:] = LN(src[t,b,:] + agg[b,t,:]) * g + b     (block = 1 token)
// ---------------------------------------------------------------------------
__global__ __launch_bounds__(256)
void ln1_kernel(const float* __restrict__ src,
                const float* __restrict__ gam, const float* __restrict__ bet) {
    int p = blockIdx.x, b = p / TT, t = p - b * TT;
    const float* srow = src   + ((size_t)(t * NB + b)) * ND;
    const float* arow = g_agg + (size_t)p * ND;
    int i0 = threadIdx.x, i1 = i0 + 256;
    float v0 = srow[i0] + arow[i0];
    float v1 = srow[i1] + arow[i1];
    float mean = block_reduce_sum256(v0 + v1) * (1.0f / ND);
    float d0 = v0 - mean, d1 = v1 - mean;
    float var = block_reduce_sum256(d0 * d0 + d1 * d1) * (1.0f / ND);
    float rstd = rsqrtf(var + 1e-5f);
    float* xr = g_x + (size_t)p * ND;
    xr[i0] = d0 * rstd * gam[i0] + bet[i0];
    xr[i1] = d1 * rstd * gam[i1] + bet[i1];
}

// LN2: out[t,b,:] = LN(x[b,t,:] + y[b,t,:]) * g + b ; writes [T,B,D] layout
__global__ __launch_bounds__(256)
void ln2_kernel(const float* __restrict__ gam, const float* __restrict__ bet,
                float* __restrict__ out) {
    int p = blockIdx.x, b = p / TT, t = p - b * TT;
    const float* xr = g_x + (size_t)p * ND;
    const float* yr = g_y + (size_t)p * ND;
    int i0 = threadIdx.x, i1 = i0 + 256;
    float v0 = xr[i0] + yr[i0];
    float v1 = xr[i1] + yr[i1];
    float mean = block_reduce_sum256(v0 + v1) * (1.0f / ND);
    float d0 = v0 - mean, d1 = v1 - mean;
    float var = block_reduce_sum256(d0 * d0 + d1 * d1) * (1.0f / ND);
    float rstd = rsqrtf(var + 1e-5f);
    float* orow = out + ((size_t)(t * NB + b)) * ND;
    orow[i0] = d0 * rstd * gam[i0] + bet[i0];
    orow[i1] = d1 * rstd * gam[i1] + bet[i1];
}

// ---------------------------------------------------------------------------
extern "C" void kernel_launch(void* const* d_in, const int* in_sizes, int n_in,
                              void* d_out, int out_size) {
    const float* in_src  = (const float*)d_in[0];
    const float* in_srcc = (const float*)d_in[1];
    const float* w_sp = (const float*)d_in[2];
    const float* b_sp = (const float*)d_in[3];
    const float* w_tp = (const float*)d_in[4];
    const float* b_tp = (const float*)d_in[5];
    const float* w_at = (const float*)d_in[6];
    const float* b_at = (const float*)d_in[7];
    const float* w_mg = (const float*)d_in[8];
    const float* b_mg = (const float*)d_in[9];
    const float* w_ag = (const float*)d_in[10];
    const float* b_ag = (const float*)d_in[11];
    const float* w_l1 = (const float*)d_in[12];
    const float* b_l1 = (const float*)d_in[13];
    const float* w_l2 = (const float*)d_in[14];
    const float* b_l2 = (const float*)d_in[15];
    const float* g_n1 = (const float*)d_in[16];
    const float* bb_n1 = (const float*)d_in[17];
    const float* g_n2 = (const float*)d_in[18];
    const float* bb_n2 = (const float*)d_in[19];

    float *p_s, *p_t, *p_wm, *p_agg, *p_x, *p_h1, *p_y, *p_src;
    cudaGetSymbolAddress((void**)&p_s,   g_s);
    cudaGetSymbolAddress((void**)&p_t,   g_t);
    cudaGetSymbolAddress((void**)&p_wm,  g_wm);
    cudaGetSymbolAddress((void**)&p_agg, g_agg);
    cudaGetSymbolAddress((void**)&p_x,   g_x);
    cudaGetSymbolAddress((void**)&p_h1,  g_h1);
    cudaGetSymbolAddress((void**)&p_y,   g_y);
    cudaGetSymbolAddress((void**)&p_src, g_src);

    for (int l = 0; l < NL; l++) {
        const float* src = (l == 0) ? in_src : p_src;

        // s = relu(srcc @ sw^T + sb)   [rows (t,b)]
        gemm_bias<1><<<dim3(ND / 128, NTOK / 128), 256>>>(
            in_srcc, w_sp + (size_t)l * ND * ND, b_sp + l * ND, p_s, NTOK, ND, ND);
        // t = relu(src @ tw^T + tb)
        gemm_bias<1><<<dim3(ND / 128, NTOK / 128), 256>>>(
            src, w_tp + (size_t)l * ND * ND, b_tp + l * ND, p_t, NTOK, ND, ND);
        // per-head scores + softmax over batch
        scores_kernel<<<NH * TT * NB / 8, 256>>>(w_at + (size_t)l * NH * 2 * NSUB,
                                                 b_at + l * NH);
        softmax_kernel<<<NH * TT, NB>>>();
        // weighted message -> relu(wm) stored in [B,T,D]
        msg_kernel<<<dim3(NTOK / 64, NH), 256>>>(w_mg + (size_t)l * NH * NSUB * NSUB,
                                                 b_mg + l * NH * NSUB);
        // agg = wm @ gw^T + gb
        gemm_bias<0><<<dim3(ND / 128, NTOK / 128), 256>>>(
            p_wm, w_ag + (size_t)l * ND * ND, b_ag + l * ND, p_agg, NTOK, ND, ND);
        // x = LN(src^T + agg)
        ln1_kernel<<<NTOK, 256>>>(src, g_n1 + l * ND, bb_n1 + l * ND);
        // h1 = relu(x @ w1^T + b1)
        gemm_bias<1><<<dim3(NDFF / 128, NTOK / 128), 256>>>(
            p_x, w_l1 + (size_t)l * NDFF * ND, b_l1 + l * NDFF, p_h1, NTOK, NDFF, ND);
        // y = h1 @ w2^T + b2
        gemm_bias<0><<<dim3(ND / 128, NTOK / 128), 256>>>(
            p_h1, w_l2 + (size_t)l * ND * NDFF, b_l2 + l * ND, p_y, NTOK, ND, NDFF);
        // out = LN(x + y), back to [T,B,D]
        float* dst = (l == NL - 1) ? (float*)d_out : p_src;
        ln2_kernel<<<NTOK, 256>>>(g_n2 + l * ND, bb_n2 + l * ND, dst);
    }
}

// round 3
// speedup vs baseline: 4.8936x; 4.8936x over previous
#include <cuda_runtime.h>
#include <cuda_fp16.h>
#include <cstdint>
#include <cstddef>

// Problem dims
#define NL   6
#define TT   128
#define NB   256
#define ND   512
#define NH   8
#define NDFF 2048
#define NSUB 64
#define NTOK (TT * NB)   // 32768 tokens

// mma.sync GEMM tile config (fp16 in, fp32 accum)
#define BM 128
#define BN 128
#define BKH 64                         // 64 halves = 128B row
#define NSTAGE 4
#define A_BYTES (BM * BKH * 2)         // 16384
#define STAGE_BYTES (2 * A_BYTES)      // 32768
#define DYN_SMEM (NSTAGE * STAGE_BYTES)  // 131072

// ---------------------------------------------------------------------------
// Scratch (__device__ globals; no allocation allowed)
// ---------------------------------------------------------------------------
__device__ __align__(16) float  g_s   [(size_t)NTOK * ND];
__device__ __align__(16) float  g_t   [(size_t)NTOK * ND];
__device__ __align__(16) float  g_scores[NH * TT * NB];
__device__ __align__(16) float  g_wts   [NH * TT * NB];
__device__ __align__(16) __half g_wm_h[(size_t)NTOK * ND];
__device__ __align__(16) float  g_agg [(size_t)NTOK * ND];
__device__ __align__(16) float  g_x   [(size_t)NTOK * ND];
__device__ __align__(16) __half g_x_h [(size_t)NTOK * ND];
__device__ __align__(16) __half g_h1_h[(size_t)NTOK * NDFF];
__device__ __align__(16) float  g_y   [(size_t)NTOK * ND];
__device__ __align__(16) float  g_src [(size_t)NTOK * ND];
__device__ __align__(16) __half g_src_h[(size_t)NTOK * ND];
__device__ __align__(16) __half g_srcc_h[(size_t)NTOK * ND];
__device__ __align__(16) __half g_src0_h[(size_t)NTOK * ND];
// fp16 weights
__device__ __align__(16) __half g_wsp_h[(size_t)NL * ND * ND];
__device__ __align__(16) __half g_wtp_h[(size_t)NL * ND * ND];
__device__ __align__(16) __half g_wag_h[(size_t)NL * ND * ND];
__device__ __align__(16) __half g_wl1_h[(size_t)NL * NDFF * ND];
__device__ __align__(16) __half g_wl2_h[(size_t)NL * ND * NDFF];

// ---------------------------------------------------------------------------
// PTX helpers (all baseline sm_80+ instructions — no "a" features)
// ---------------------------------------------------------------------------
__device__ __forceinline__ uint32_t smem_u32(const void* p) {
    uint32_t a;
    asm("{ .reg .u64 t; cvta.to.shared.u64 t, %1; cvt.u32.u64 %0, t; }"
        : "=r"(a) : "l"(p));
    return a;
}
__device__ __forceinline__ void cp_async16(uint32_t dst, const void* src) {
    asm volatile("cp.async.cg.shared.global [%0], [%1], 16;" :: "r"(dst), "l"(src));
}
#define CP_COMMIT() asm volatile("cp.async.commit_group;" ::: "memory")
#define CP_WAIT2()  asm volatile("cp.async.wait_group 2;" ::: "memory")

__device__ __forceinline__ void ldsm_x4(uint32_t* r, uint32_t addr) {
    asm volatile("ldmatrix.sync.aligned.m8n8.x4.shared.b16 {%0,%1,%2,%3}, [%4];"
                 : "=r"(r[0]), "=r"(r[1]), "=r"(r[2]), "=r"(r[3]) : "r"(addr));
}
__device__ __forceinline__ void mma16816(float* d, const uint32_t* a,
                                         uint32_t b0, uint32_t b1) {
    asm volatile(
        "mma.sync.aligned.m16n8k16.row.col.f32.f16.f16.f32 "
        "{%0,%1,%2,%3}, {%4,%5,%6,%7}, {%8,%9}, {%0,%1,%2,%3};"
        : "+f"(d[0]), "+f"(d[1]), "+f"(d[2]), "+f"(d[3])
        : "r"(a[0]), "r"(a[1]), "r"(a[2]), "r"(a[3]), "r"(b0), "r"(b1));
}

// ---------------------------------------------------------------------------
// cooperative stage loader: A tile [128 x 64h] + B tile [128 x 64h], swizzled
// ---------------------------------------------------------------------------
__device__ __forceinline__ void load_stage(const __half* __restrict__ Ag,
                                           const __half* __restrict__ Wg,
                                           int K, uint32_t abase, uint32_t bbase,
                                           int tid) {
    #pragma unroll
    for (int it = 0; it < 4; it++) {
        int q = tid + it * 256;        // 0..1023 16B chunks per operand
        int r = q >> 3;                // row 0..127
        int c = q & 7;                 // logical 16B chunk in row
        uint32_t off = (uint32_t)(r * 128 + ((c ^ (r & 7)) << 4));
        cp_async16(abase + off, Ag + (size_t)r * K + c * 8);
        cp_async16(bbase + off, Wg + (size_t)r * K + c * 8);
    }
    CP_COMMIT();
}

// ---------------------------------------------------------------------------
// fp16 tensor-core GEMM: C[M,N] = A[M,K]@W[N,K]^T + bias, opt relu/half-out.
// grid (N/128, M/128), 256 threads (8 warps, 2x4, warp tile 64x32).
// ---------------------------------------------------------------------------
template <int RELU, int OUTH>
__global__ __launch_bounds__(256)
void tc_gemm(const __half* __restrict__ A, const __half* __restrict__ W,
             const float* __restrict__ bias, float* __restrict__ Cf,
             __half* __restrict__ Ch, int K, int N) {
    __shared__ float s_bias[BN];
    extern __shared__ __align__(1024) char dynsmem[];
    const uint32_t dynbase = smem_u32(dynsmem);

    const int tid = threadIdx.x;
    const int wid = tid >> 5, lid = tid & 31;
    const int wm_ = wid >> 2, wn_ = wid & 3;   // 2 x 4 warp grid
    const int m0 = blockIdx.y * BM, n0 = blockIdx.x * BN;

    if (tid < BN) s_bias[tid] = bias[n0 + tid];

    const __half* Abase = A + (size_t)m0 * K;
    const __half* Wbase = W + (size_t)n0 * K;
    const int NCH = K / BKH;

    // per-lane ldmatrix geometry
    const int sub = lid >> 3, wi = lid & 7;
    const int csel = sub >> 1;                       // 0/1 -> k halves 0/8
    const int arow = wm_ * 64 + (sub & 1) * 8 + wi;  // + mt*16
    const int brow = wn_ * 32 + (sub & 1) * 8 + wi;  // + np*16
    const int axor = arow & 7, bxor = brow & 7;      // invariant under +16

    // prologue: stages 0..2
    #pragma unroll
    for (int c = 0; c < NSTAGE - 1; c++)
        load_stage(Abase + c * BKH, Wbase + c * BKH, K,
                   dynbase + c * STAGE_BYTES,
                   dynbase + c * STAGE_BYTES + A_BYTES, tid);

    float acc[4][4][4] = {};

    for (int i = 0; i < NCH; i++) {
        CP_WAIT2();              // stage i resident (<=2 pending)
        __syncthreads();         // all warps done reading slot (i+3)%4 (chunk i-1's...)
        int j = i + NSTAGE - 1;
        if (j < NCH) {
            int sj = j & (NSTAGE - 1);
            load_stage(Abase + j * BKH, Wbase + j * BKH, K,
                       dynbase + sj * STAGE_BYTES,
                       dynbase + sj * STAGE_BYTES + A_BYTES, tid);
        } else {
            CP_COMMIT();         // keep group accounting uniform
        }

        const uint32_t aB = dynbase + (i & (NSTAGE - 1)) * STAGE_BYTES;
        const uint32_t bB = aB + A_BYTES;
        #pragma unroll
        for (int ks = 0; ks < 4; ks++) {
            uint32_t afr[4][4], bfr[2][4];
            #pragma unroll
            for (int mt = 0; mt < 4; mt++) {
                uint32_t addr = aB + (uint32_t)((arow + mt * 16) * 128)
                              + (uint32_t)((((ks << 1) + csel) ^ axor) << 4);
                ldsm_x4(afr[mt], addr);
            }
            #pragma unroll
            for (int np = 0; np < 2; np++) {
                uint32_t addr = bB + (uint32_t)((brow + np * 16) * 128)
                              + (uint32_t)((((ks << 1) + csel) ^ bxor) << 4);
                ldsm_x4(bfr[np], addr);
            }
            #pragma unroll
            for (int mt = 0; mt < 4; mt++)
                #pragma unroll
                for (int nt = 0; nt < 4; nt++)
                    mma16816(acc[mt][nt], afr[mt],
                             bfr[nt >> 1][nt & 1], bfr[nt >> 1][(nt & 1) + 2]);
        }
    }

    // epilogue: direct stores
    #pragma unroll
    for (int mt = 0; mt < 4; mt++) {
        int row = m0 + wm_ * 64 + mt * 16 + (lid >> 2);
        #pragma unroll
        for (int nt = 0; nt < 4; nt++) {
            int coll = wn_ * 32 + nt * 8 + (lid & 3) * 2;
            int col = n0 + coll;
            float bx = s_bias[coll], by = s_bias[coll + 1];
            float v0 = acc[mt][nt][0] + bx, v1 = acc[mt][nt][1] + by;
            float v2 = acc[mt][nt][2] + bx, v3 = acc[mt][nt][3] + by;
            if (RELU) {
                v0 = fmaxf(v0, 0.f); v1 = fmaxf(v1, 0.f);
                v2 = fmaxf(v2, 0.f); v3 = fmaxf(v3, 0.f);
            }
            if (OUTH) {
                *(__half2*)(Ch + (size_t)row * N + col)       = __floats2half2_rn(v0, v1);
                *(__half2*)(Ch + (size_t)(row + 8) * N + col) = __floats2half2_rn(v2, v3);
            } else {
                *(float2*)(Cf + (size_t)row * N + col)       = make_float2(v0, v1);
                *(float2*)(Cf + (size_t)(row + 8) * N + col) = make_float2(v2, v3);
            }
        }
    }
}

// ---------------------------------------------------------------------------
// f32 -> f16 conversion (float4 -> half2x2)
// ---------------------------------------------------------------------------
__global__ __launch_bounds__(256)
void f32_to_f16_kernel(const float4* __restrict__ in, __half2* __restrict__ out, int n4) {
    for (int i = blockIdx.x * 256 + threadIdx.x; i < n4; i += gridDim.x * 256) {
        float4 v = in[i];
        out[2 * i]     = __floats2half2_rn(v.x, v.y);
        out[2 * i + 1] = __floats2half2_rn(v.z, v.w);
    }
}

// ---------------------------------------------------------------------------
// Block reductions (256 threads)
// ---------------------------------------------------------------------------
__device__ __forceinline__ float block_reduce_sum256(float v) {
    __shared__ float sh[8];
    int lane = threadIdx.x & 31, wid = threadIdx.x >> 5;
    #pragma unroll
    for (int o = 16; o; o >>= 1) v += __shfl_xor_sync(0xffffffffu, v, o);
    if (lane == 0) sh[wid] = v;
    __syncthreads();
    float r = (lane < 8) ? sh[lane] : 0.0f;
    #pragma unroll
    for (int o = 4; o; o >>= 1) r += __shfl_xor_sync(0xffffffffu, r, o);
    r = __shfl_sync(0xffffffffu, r, 0);
    __syncthreads();
    return r;
}
__device__ __forceinline__ float block_reduce_max256(float v) {
    __shared__ float sh[8];
    int lane = threadIdx.x & 31, wid = threadIdx.x >> 5;
    #pragma unroll
    for (int o = 16; o; o >>= 1) v = fmaxf(v, __shfl_xor_sync(0xffffffffu, v, o));
    if (lane == 0) sh[wid] = v;
    __syncthreads();
    float r = (lane < 8) ? sh[lane] : -3.4e38f;
    #pragma unroll
    for (int o = 4; o; o >>= 1) r = fmaxf(r, __shfl_xor_sync(0xffffffffu, r, o));
    r = __shfl_sync(0xffffffffu, r, 0);
    __syncthreads();
    return r;
}

// ---------------------------------------------------------------------------
// scores / softmax / msg / LN kernels (fp32 math)
// ---------------------------------------------------------------------------
__global__ __launch_bounds__(256)
void scores_kernel(const float* __restrict__ aw, const float* __restrict__ ab) {
    int w    = blockIdx.x * 8 + (threadIdx.x >> 5);
    int lane = threadIdx.x & 31;
    int h    = w / (TT * NB);
    int rem  = w % (TT * NB);
    int t    = rem / NB;
    int b    = rem % NB;
    size_t base = ((size_t)(t * NB + b)) * ND + h * NSUB;
    const float* ah = aw + h * 2 * NSUB;
    float sum = g_s[base + lane]      * ah[lane]
              + g_s[base + lane + 32] * ah[lane + 32]
              + g_t[base + lane]      * ah[NSUB + lane]
              + g_t[base + lane + 32] * ah[NSUB + lane + 32];
    #pragma unroll
    for (int o = 16; o; o >>= 1) sum += __shfl_xor_sync(0xffffffffu, sum, o);
    if (lane == 0) g_scores[(h * TT + t) * NB + b] = sum + ab[h];
}

__global__ __launch_bounds__(256)
void softmax_kernel() {
    int ht = blockIdx.x;
    float v = g_scores[(size_t)ht * NB + threadIdx.x];
    float m = block_reduce_max256(v);
    float e = __expf(v - m);
    float s = block_reduce_sum256(e);
    g_wts[(size_t)ht * NB + threadIdx.x] = e / s;
}

__global__ __launch_bounds__(256)
void msg_kernel(const float* __restrict__ mw, const float* __restrict__ mb) {
    __shared__ float prod[64][65];
    __shared__ float mws [64][65];
    __shared__ float wt_s[64];
    __shared__ float mb_s[64];

    const int h  = blockIdx.y;
    const int p0 = blockIdx.x * 64;
    const int tid = threadIdx.x;

    for (int i = tid; i < 64 * 64; i += 256) {
        int u = i >> 6, s = i & 63;
        mws[s][u] = mw[((size_t)h * 64 + u) * 64 + s];
    }
    if (tid < 64) {
        mb_s[tid] = mb[h * 64 + tid];
        int p = p0 + tid, b = p / TT, t = p % TT;
        wt_s[tid] = g_wts[(h * TT + t) * NB + b];
    }
    for (int i = tid; i < 64 * 64; i += 256) {
        int tok = i >> 6, u = i & 63;
        int p = p0 + tok, b = p / TT, t = p % TT;
        size_t idx = ((size_t)(t * NB + b)) * ND + h * NSUB + u;
        prod[tok][u] = g_s[idx] * g_t[idx];
    }
    __syncthreads();

    const int tx = tid & 15, ty = tid >> 4;
    float acc[4][4] = {};
    #pragma unroll 4
    for (int s = 0; s < 64; s++) {
        float a[4], w[4];
        #pragma unroll
        for (int i = 0; i < 4; i++) a[i] = prod[ty * 4 + i][s];
        #pragma unroll
        for (int j = 0; j < 4; j++) w[j] = mws[s][tx * 4 + j];
        #pragma unroll
        for (int i = 0; i < 4; i++)
            #pragma unroll
            for (int j = 0; j < 4; j++)
                acc[i][j] += a[i] * w[j];
    }
    #pragma unroll
    for (int i = 0; i < 4; i++) {
        int tok = ty * 4 + i;
        float wt = wt_s[tok];
        #pragma unroll
        for (int j = 0; j < 4; j++) {
            int u = tx * 4 + j;
            float v = wt * (acc[i][j] + mb_s[u]);
            g_wm_h[((size_t)(p0 + tok)) * ND + h * NSUB + u] =
                __float2half_rn(fmaxf(v, 0.f));
        }
    }
}

// LN1: x[b,t,:] = LN(src[t,b,:] + agg[b,t,:]); writes fp32 + fp16
__global__ __launch_bounds__(256)
void ln1_kernel(const float* __restrict__ src,
                const float* __restrict__ gam, const float* __restrict__ bet) {
    int p = blockIdx.x, b = p / TT, t = p - b * TT;
    const float* srow = src   + ((size_t)(t * NB + b)) * ND;
    const float* arow = g_agg + (size_t)p * ND;
    int i0 = threadIdx.x, i1 = i0 + 256;
    float v0 = srow[i0] + arow[i0];
    float v1 = srow[i1] + arow[i1];
    float mean = block_reduce_sum256(v0 + v1) * (1.0f / ND);
    float d0 = v0 - mean, d1 = v1 - mean;
    float var = block_reduce_sum256(d0 * d0 + d1 * d1) * (1.0f / ND);
    float rstd = rsqrtf(var + 1e-5f);
    float o0 = d0 * rstd * gam[i0] + bet[i0];
    float o1 = d1 * rstd * gam[i1] + bet[i1];
    g_x[(size_t)p * ND + i0] = o0;
    g_x[(size_t)p * ND + i1] = o1;
    g_x_h[(size_t)p * ND + i0] = __float2half_rn(o0);
    g_x_h[(size_t)p * ND + i1] = __float2half_rn(o1);
}

// LN2: out[t,b,:] = LN(x + y); writes fp32 dst (+ fp16 copy unless last layer)
__global__ __launch_bounds__(256)
void ln2_kernel(const float* __restrict__ gam, const float* __restrict__ bet,
                float* __restrict__ out, int write_h) {
    int p = blockIdx.x, b = p / TT, t = p - b * TT;
    const float* xr = g_x + (size_t)p * ND;
    const float* yr = g_y + (size_t)p * ND;
    int i0 = threadIdx.x, i1 = i0 + 256;
    float v0 = xr[i0] + yr[i0];
    float v1 = xr[i1] + yr[i1];
    float mean = block_reduce_sum256(v0 + v1) * (1.0f / ND);
    float d0 = v0 - mean, d1 = v1 - mean;
    float var = block_reduce_sum256(d0 * d0 + d1 * d1) * (1.0f / ND);
    float rstd = rsqrtf(var + 1e-5f);
    float o0 = d0 * rstd * gam[i0] + bet[i0];
    float o1 = d1 * rstd * gam[i1] + bet[i1];
    size_t obase = ((size_t)(t * NB + b)) * ND;
    out[obase + i0] = o0;
    out[obase + i1] = o1;
    if (write_h) {
        g_src_h[obase + i0] = __float2half_rn(o0);
        g_src_h[obase + i1] = __float2half_rn(o1);
    }
}

// ---------------------------------------------------------------------------
extern "C" void kernel_launch(void* const* d_in, const int* in_sizes, int n_in,
                              void* d_out, int out_size) {
    const float* in_src  = (const float*)d_in[0];
    const float* in_srcc = (const float*)d_in[1];
    const float* w_sp = (const float*)d_in[2];
    const float* b_sp = (const float*)d_in[3];
    const float* w_tp = (const float*)d_in[4];
    const float* b_tp = (const float*)d_in[5];
    const float* w_at = (const float*)d_in[6];
    const float* b_at = (const float*)d_in[7];
    const float* w_mg = (const float*)d_in[8];
    const float* b_mg = (const float*)d_in[9];
    const float* w_ag = (const float*)d_in[10];
    const float* b_ag = (const float*)d_in[11];
    const float* w_l1 = (const float*)d_in[12];
    const float* b_l1 = (const float*)d_in[13];
    const float* w_l2 = (const float*)d_in[14];
    const float* b_l2 = (const float*)d_in[15];
    const float* g_n1 = (const float*)d_in[16];
    const float* bb_n1 = (const float*)d_in[17];
    const float* g_n2 = (const float*)d_in[18];
    const float* bb_n2 = (const float*)d_in[19];

    float *p_agg, *p_x, *p_y, *p_src;
    __half *p_wm_h, *p_x_h, *p_h1_h, *p_src_h, *p_srcc_h, *p_src0_h;
    __half *p_wsp, *p_wtp, *p_wag, *p_wl1, *p_wl2;
    float *p_s, *p_t;
    cudaGetSymbolAddress((void**)&p_s,      g_s);
    cudaGetSymbolAddress((void**)&p_t,      g_t);
    cudaGetSymbolAddress((void**)&p_agg,    g_agg);
    cudaGetSymbolAddress((void**)&p_x,      g_x);
    cudaGetSymbolAddress((void**)&p_y,      g_y);
    cudaGetSymbolAddress((void**)&p_src,    g_src);
    cudaGetSymbolAddress((void**)&p_wm_h,   g_wm_h);
    cudaGetSymbolAddress((void**)&p_x_h,    g_x_h);
    cudaGetSymbolAddress((void**)&p_h1_h,   g_h1_h);
    cudaGetSymbolAddress((void**)&p_src_h,  g_src_h);
    cudaGetSymbolAddress((void**)&p_srcc_h, g_srcc_h);
    cudaGetSymbolAddress((void**)&p_src0_h, g_src0_h);
    cudaGetSymbolAddress((void**)&p_wsp,    g_wsp_h);
    cudaGetSymbolAddress((void**)&p_wtp,    g_wtp_h);
    cudaGetSymbolAddress((void**)&p_wag,    g_wag_h);
    cudaGetSymbolAddress((void**)&p_wl1,    g_wl1_h);
    cudaGetSymbolAddress((void**)&p_wl2,    g_wl2_h);

    cudaFuncSetAttribute(tc_gemm<1, 0>, cudaFuncAttributeMaxDynamicSharedMemorySize, DYN_SMEM);
    cudaFuncSetAttribute(tc_gemm<0, 0>, cudaFuncAttributeMaxDynamicSharedMemorySize, DYN_SMEM);
    cudaFuncSetAttribute(tc_gemm<1, 1>, cudaFuncAttributeMaxDynamicSharedMemorySize, DYN_SMEM);

    // one-time fp16 conversions
    f32_to_f16_kernel<<<2048, 256>>>((const float4*)in_srcc, (__half2*)p_srcc_h, NTOK * ND / 4);
    f32_to_f16_kernel<<<2048, 256>>>((const float4*)in_src,  (__half2*)p_src0_h, NTOK * ND / 4);
    f32_to_f16_kernel<<<2048, 256>>>((const float4*)w_sp, (__half2*)p_wsp, NL * ND * ND / 4);
    f32_to_f16_kernel<<<2048, 256>>>((const float4*)w_tp, (__half2*)p_wtp, NL * ND * ND / 4);
    f32_to_f16_kernel<<<2048, 256>>>((const float4*)w_ag, (__half2*)p_wag, NL * ND * ND / 4);
    f32_to_f16_kernel<<<2048, 256>>>((const float4*)w_l1, (__half2*)p_wl1, NL * NDFF * ND / 4);
    f32_to_f16_kernel<<<2048, 256>>>((const float4*)w_l2, (__half2*)p_wl2, NL * ND * NDFF / 4);

    for (int l = 0; l < NL; l++) {
        const __half* srcA   = (l == 0) ? p_src0_h : p_src_h;
        const float*  srcRes = (l == 0) ? in_src   : p_src;

        // s = relu(srcc @ sw^T + sb)  [fp32 out]
        tc_gemm<1, 0><<<dim3(ND / BN, NTOK / BM), 256, DYN_SMEM>>>(
            p_srcc_h, p_wsp + (size_t)l * ND * ND, b_sp + l * ND, p_s, nullptr, ND, ND);
        // t = relu(src @ tw^T + tb)  [fp32 out]
        tc_gemm<1, 0><<<dim3(ND / BN, NTOK / BM), 256, DYN_SMEM>>>(
            srcA, p_wtp + (size_t)l * ND * ND, b_tp + l * ND, p_t, nullptr, ND, ND);
        // scores + softmax over batch
        scores_kernel<<<NH * TT * NB / 8, 256>>>(w_at + (size_t)l * NH * 2 * NSUB,
                                                 b_at + l * NH);
        softmax_kernel<<<NH * TT, NB>>>();
        // weighted message -> relu(wm) [B,T,D] fp16
        msg_kernel<<<dim3(NTOK / 64, NH), 256>>>(w_mg + (size_t)l * NH * NSUB * NSUB,
                                                 b_mg + l * NH * NSUB);
        // agg = wm @ gw^T + gb  [fp32 out]
        tc_gemm<0, 0><<<dim3(ND / BN, NTOK / BM), 256, DYN_SMEM>>>(
            p_wm_h, p_wag + (size_t)l * ND * ND, b_ag + l * ND, p_agg, nullptr, ND, ND);
        // x = LN(src^T + agg)  [fp32 + fp16]
        ln1_kernel<<<NTOK, 256>>>(srcRes, g_n1 + l * ND, bb_n1 + l * ND);
        // h1 = relu(x @ w1^T + b1)  [fp16 out only]
        tc_gemm<1, 1><<<dim3(NDFF / BN, NTOK / BM), 256, DYN_SMEM>>>(
            p_x_h, p_wl1 + (size_t)l * NDFF * ND, b_l1 + l * NDFF, nullptr, p_h1_h, ND, NDFF);
        // y = h1 @ w2^T + b2  [fp32 out]
        tc_gemm<0, 0><<<dim3(ND / BN, NTOK / BM), 256, DYN_SMEM>>>(
            p_h1_h, p_wl2 + (size_t)l * ND * NDFF, b_l2 + l * ND, p_y, nullptr, NDFF, ND);
        // out = LN(x + y) -> [T,B,D]
        float* dst = (l == NL - 1) ? (float*)d_out : p_src;
        ln2_kernel<<<NTOK, 256>>>(g_n2 + l * ND, bb_n2 + l * ND, dst, (l == NL - 1) ? 0 : 1);
    }
}

// round 4
// speedup vs baseline: 5.1809x; 1.0587x over previous
#include <cuda_runtime.h>
#include <cuda_fp16.h>
#include <cstdint>
#include <cstddef>

// Problem dims
#define NL   6
#define TT   128
#define NB   256
#define ND   512
#define NH   8
#define NDFF 2048
#define NSUB 64
#define NTOK (TT * NB)   // 32768 tokens

// mma.sync GEMM tile config (fp16 in, fp32 accum)
#define BM 128
#define BN 128
#define BKH 64                         // 64 halves = 128B row
#define NSTAGE 4
#define A_BYTES (BM * BKH * 2)         // 16384
#define STAGE_BYTES (2 * A_BYTES)      // 32768
#define DYN_SMEM (NSTAGE * STAGE_BYTES)  // 131072

// ---------------------------------------------------------------------------
// Scratch (__device__ globals; no allocation allowed)
// ---------------------------------------------------------------------------
__device__ __align__(16) float  g_s   [(size_t)NTOK * ND];
__device__ __align__(16) float  g_t   [(size_t)NTOK * ND];
__device__ __align__(16) float  g_scores[NH * TT * NB];
__device__ __align__(16) float  g_wts   [NH * TT * NB];
__device__ __align__(16) __half g_prod_h[(size_t)NTOK * ND];
__device__ __align__(16) __half g_wm_h[(size_t)NTOK * ND];
__device__ __align__(16) float  g_agg [(size_t)NTOK * ND];   // holds src^T + agg
__device__ __align__(16) float  g_x   [(size_t)NTOK * ND];
__device__ __align__(16) __half g_x_h [(size_t)NTOK * ND];
__device__ __align__(16) __half g_h1_h[(size_t)NTOK * NDFF];
__device__ __align__(16) float  g_y   [(size_t)NTOK * ND];   // holds x + y
__device__ __align__(16) float  g_src [(size_t)NTOK * ND];
__device__ __align__(16) __half g_src_h[(size_t)NTOK * ND];
__device__ __align__(16) __half g_srcc_h[(size_t)NTOK * ND];
__device__ __align__(16) __half g_src0_h[(size_t)NTOK * ND];
// fp16 weights
__device__ __align__(16) __half g_wsp_h[(size_t)NL * ND * ND];
__device__ __align__(16) __half g_wtp_h[(size_t)NL * ND * ND];
__device__ __align__(16) __half g_wag_h[(size_t)NL * ND * ND];
__device__ __align__(16) __half g_wl1_h[(size_t)NL * NDFF * ND];
__device__ __align__(16) __half g_wl2_h[(size_t)NL * ND * NDFF];

// ---------------------------------------------------------------------------
// PTX helpers (baseline sm_80+ instructions only)
// ---------------------------------------------------------------------------
__device__ __forceinline__ uint32_t smem_u32(const void* p) {
    uint32_t a;
    asm("{ .reg .u64 t; cvta.to.shared.u64 t, %1; cvt.u32.u64 %0, t; }"
        : "=r"(a) : "l"(p));
    return a;
}
__device__ __forceinline__ void cp_async16(uint32_t dst, const void* src) {
    asm volatile("cp.async.cg.shared.global [%0], [%1], 16;" :: "r"(dst), "l"(src));
}
#define CP_COMMIT() asm volatile("cp.async.commit_group;" ::: "memory")
#define CP_WAIT2()  asm volatile("cp.async.wait_group 2;" ::: "memory")

__device__ __forceinline__ void ldsm_x4(uint32_t* r, uint32_t addr) {
    asm volatile("ldmatrix.sync.aligned.m8n8.x4.shared.b16 {%0,%1,%2,%3}, [%4];"
                 : "=r"(r[0]), "=r"(r[1]), "=r"(r[2]), "=r"(r[3]) : "r"(addr));
}
__device__ __forceinline__ void mma16816(float* d, const uint32_t* a,
                                         uint32_t b0, uint32_t b1) {
    asm volatile(
        "mma.sync.aligned.m16n8k16.row.col.f32.f16.f16.f32 "
        "{%0,%1,%2,%3}, {%4,%5,%6,%7}, {%8,%9}, {%0,%1,%2,%3};"
        : "+f"(d[0]), "+f"(d[1]), "+f"(d[2]), "+f"(d[3])
        : "r"(a[0]), "r"(a[1]), "r"(a[2]), "r"(a[3]), "r"(b0), "r"(b1));
}

// ---------------------------------------------------------------------------
// cooperative stage loader: A tile [128 x 64h] + B tile [128 x 64h], swizzled
// ---------------------------------------------------------------------------
__device__ __forceinline__ void load_stage(const __half* __restrict__ Ag,
                                           const __half* __restrict__ Wg,
                                           int K, uint32_t abase, uint32_t bbase,
                                           int tid) {
    #pragma unroll
    for (int it = 0; it < 4; it++) {
        int q = tid + it * 256;        // 0..1023 16B chunks per operand
        int r = q >> 3;                // row 0..127
        int c = q & 7;                 // logical 16B chunk in row
        uint32_t off = (uint32_t)(r * 128 + ((c ^ (r & 7)) << 4));
        cp_async16(abase + off, Ag + (size_t)r * K + c * 8);
        cp_async16(bbase + off, Wg + (size_t)r * K + c * 8);
    }
    CP_COMMIT();
}

// fragment loader: one ks step (k16 slice) for this warp
__device__ __forceinline__ void load_frags(uint32_t aB, uint32_t bB, int ks,
                                           int arow, int brow, int axor, int bxor,
                                           int csel,
                                           uint32_t af[4][4], uint32_t bf[2][4]) {
    #pragma unroll
    for (int mt = 0; mt < 4; mt++) {
        uint32_t addr = aB + (uint32_t)((arow + mt * 16) * 128)
                      + (uint32_t)((((ks << 1) + csel) ^ axor) << 4);
        ldsm_x4(af[mt], addr);
    }
    #pragma unroll
    for (int np = 0; np < 2; np++) {
        uint32_t addr = bB + (uint32_t)((brow + np * 16) * 128)
                      + (uint32_t)((((ks << 1) + csel) ^ bxor) << 4);
        ldsm_x4(bf[np], addr);
    }
}

// ---------------------------------------------------------------------------
// fp16 tensor-core GEMM: C[M,N] = A[M,K]@W[N,K]^T + bias (+residual), opt relu.
// ADDMODE: 0 none, 1 res same layout as C, 2 res transposed [(m%TT)*NB+(m/TT)]
// grid (N/128, M/128), 256 threads (8 warps, 2x4, warp tile 64x32).
// ---------------------------------------------------------------------------
template <int RELU, int OUTH, int ADDMODE>
__global__ __launch_bounds__(256)
void tc_gemm(const __half* __restrict__ A, const __half* __restrict__ W,
             const float* __restrict__ bias, float* __restrict__ Cf,
             __half* __restrict__ Ch, const float* __restrict__ Res,
             int K, int N) {
    __shared__ float s_bias[BN];
    extern __shared__ __align__(1024) char dynsmem[];
    const uint32_t dynbase = smem_u32(dynsmem);

    const int tid = threadIdx.x;
    const int wid = tid >> 5, lid = tid & 31;
    const int wm_ = wid >> 2, wn_ = wid & 3;   // 2 x 4 warp grid
    const int m0 = blockIdx.y * BM, n0 = blockIdx.x * BN;

    if (tid < BN) s_bias[tid] = bias[n0 + tid];

    const __half* Abase = A + (size_t)m0 * K;
    const __half* Wbase = W + (size_t)n0 * K;
    const int NCH = K / BKH;

    // per-lane ldmatrix geometry
    const int sub = lid >> 3, wi = lid & 7;
    const int csel = sub >> 1;                       // 0/1 -> k halves 0/8
    const int arow = wm_ * 64 + (sub & 1) * 8 + wi;  // + mt*16
    const int brow = wn_ * 32 + (sub & 1) * 8 + wi;  // + np*16
    const int axor = arow & 7, bxor = brow & 7;      // invariant under +16

    // prologue: stages 0..2
    #pragma unroll
    for (int c = 0; c < NSTAGE - 1; c++)
        load_stage(Abase + c * BKH, Wbase + c * BKH, K,
                   dynbase + c * STAGE_BYTES,
                   dynbase + c * STAGE_BYTES + A_BYTES, tid);

    float acc[4][4][4] = {};
    uint32_t afr[2][4][4], bfr[2][2][4];

    for (int i = 0; i < NCH; i++) {
        CP_WAIT2();              // stage i resident (<=2 pending)
        __syncthreads();         // all warps done reading the slot being refilled
        int j = i + NSTAGE - 1;
        if (j < NCH) {
            int sj = j & (NSTAGE - 1);
            load_stage(Abase + j * BKH, Wbase + j * BKH, K,
                       dynbase + sj * STAGE_BYTES,
                       dynbase + sj * STAGE_BYTES + A_BYTES, tid);
        } else {
            CP_COMMIT();         // keep group accounting uniform
        }

        const uint32_t aB = dynbase + (i & (NSTAGE - 1)) * STAGE_BYTES;
        const uint32_t bB = aB + A_BYTES;

        load_frags(aB, bB, 0, arow, brow, axor, bxor, csel, afr[0], bfr[0]);
        #pragma unroll
        for (int ks = 0; ks < 4; ks++) {
            int cur = ks & 1;
            if (ks < 3)
                load_frags(aB, bB, ks + 1, arow, brow, axor, bxor, csel,
                           afr[cur ^ 1], bfr[cur ^ 1]);
            #pragma unroll
            for (int mt = 0; mt < 4; mt++)
                #pragma unroll
                for (int nt = 0; nt < 4; nt++)
                    mma16816(acc[mt][nt], afr[cur][mt],
                             bfr[cur][nt >> 1][nt & 1],
                             bfr[cur][nt >> 1][(nt & 1) + 2]);
        }
    }

    // epilogue: direct stores (+ optional residual)
    #pragma unroll
    for (int mt = 0; mt < 4; mt++) {
        int row = m0 + wm_ * 64 + mt * 16 + (lid >> 2);
        size_t rb0 = 0, rb1 = 0;
        if (ADDMODE == 1) {
            rb0 = (size_t)row * N;
            rb1 = (size_t)(row + 8) * N;
        } else if (ADDMODE == 2) {
            int b0_ = row >> 7, t0_ = row & 127;          // TT = 128
            int b1_ = (row + 8) >> 7, t1_ = (row + 8) & 127;
            rb0 = ((size_t)(t0_ * NB + b0_)) * ND;
            rb1 = ((size_t)(t1_ * NB + b1_)) * ND;
        }
        #pragma unroll
        for (int nt = 0; nt < 4; nt++) {
            int coll = wn_ * 32 + nt * 8 + (lid & 3) * 2;
            int col = n0 + coll;
            float bx = s_bias[coll], by = s_bias[coll + 1];
            float v0 = acc[mt][nt][0] + bx, v1 = acc[mt][nt][1] + by;
            float v2 = acc[mt][nt][2] + bx, v3 = acc[mt][nt][3] + by;
            if (ADDMODE != 0) {
                float2 r0 = *(const float2*)(Res + rb0 + col);
                float2 r1 = *(const float2*)(Res + rb1 + col);
                v0 += r0.x; v1 += r0.y; v2 += r1.x; v3 += r1.y;
            }
            if (RELU) {
                v0 = fmaxf(v0, 0.f); v1 = fmaxf(v1, 0.f);
                v2 = fmaxf(v2, 0.f); v3 = fmaxf(v3, 0.f);
            }
            if (OUTH) {
                *(__half2*)(Ch + (size_t)row * N + col)       = __floats2half2_rn(v0, v1);
                *(__half2*)(Ch + (size_t)(row + 8) * N + col) = __floats2half2_rn(v2, v3);
            } else {
                *(float2*)(Cf + (size_t)row * N + col)       = make_float2(v0, v1);
                *(float2*)(Cf + (size_t)(row + 8) * N + col) = make_float2(v2, v3);
            }
        }
    }
}

// ---------------------------------------------------------------------------
// f32 -> f16 conversion (float4 -> half2x2)
// ---------------------------------------------------------------------------
__global__ __launch_bounds__(256)
void f32_to_f16_kernel(const float4* __restrict__ in, __half2* __restrict__ out, int n4) {
    for (int i = blockIdx.x * 256 + threadIdx.x; i < n4; i += gridDim.x * 256) {
        float4 v = in[i];
        out[2 * i]     = __floats2half2_rn(v.x, v.y);
        out[2 * i + 1] = __floats2half2_rn(v.z, v.w);
    }
}

// ---------------------------------------------------------------------------
// Block reductions (256 threads)
// ---------------------------------------------------------------------------
__device__ __forceinline__ float block_reduce_sum256(float v) {
    __shared__ float sh[8];
    int lane = threadIdx.x & 31, wid = threadIdx.x >> 5;
    #pragma unroll
    for (int o = 16; o; o >>= 1) v += __shfl_xor_sync(0xffffffffu, v, o);
    if (lane == 0) sh[wid] = v;
    __syncthreads();
    float r = (lane < 8) ? sh[lane] : 0.0f;
    #pragma unroll
    for (int o = 4; o; o >>= 1) r += __shfl_xor_sync(0xffffffffu, r, o);
    r = __shfl_sync(0xffffffffu, r, 0);
    __syncthreads();
    return r;
}
__device__ __forceinline__ float block_reduce_max256(float v) {
    __shared__ float sh[8];
    int lane = threadIdx.x & 31, wid = threadIdx.x >> 5;
    #pragma unroll
    for (int o = 16; o; o >>= 1) v = fmaxf(v, __shfl_xor_sync(0xffffffffu, v, o));
    if (lane == 0) sh[wid] = v;
    __syncthreads();
    float r = (lane < 8) ? sh[lane] : -3.4e38f;
    #pragma unroll
    for (int o = 4; o; o >>= 1) r = fmaxf(r, __shfl_xor_sync(0xffffffffu, r, o));
    r = __shfl_sync(0xffffffffu, r, 0);
    __syncthreads();
    return r;
}

// ---------------------------------------------------------------------------
// fused scores + (s*t) product: one warp per token.
// scores[h][t][b] = dot(s, aw[h][:64]) + dot(t, aw[h][64:]) + ab[h]
// prod_h[tok][:] = fp16(s * t)
// ---------------------------------------------------------------------------
__global__ __launch_bounds__(256)
void fuse_st_kernel(const float* __restrict__ aw, const float* __restrict__ ab) {
    __shared__ float aw_s[NH * 2 * NSUB];   // 1024 floats
    __shared__ float ab_s[NH];

    const int tid = threadIdx.x;
    if (tid < NH * 2 * NSUB) { /* 1024 > 256: strided */ }
    for (int i = tid; i < NH * 2 * NSUB; i += 256) aw_s[i] = aw[i];
    if (tid < NH) ab_s[tid] = ab[tid];
    __syncthreads();

    const int w = blockIdx.x * 8 + (tid >> 5);      // token index (t*NB+b)
    const int l = tid & 31;
    const int t = w / NB, b = w % NB;
    const size_t base = (size_t)w * ND;
    const int hi = l >> 4;                          // 0 or 1

    float part[4];
    #pragma unroll
    for (int k = 0; k < 4; k++) {
        int idx = k * 128 + l * 4;
        int h = idx >> 6;                           // = 2k + hi
        int u = idx & 63;
        float4 sv = *(const float4*)(g_s + base + idx);
        float4 tv = *(const float4*)(g_t + base + idx);
        // product -> fp16
        __half2 p0 = __floats2half2_rn(sv.x * tv.x, sv.y * tv.y);
        __half2 p1 = __floats2half2_rn(sv.z * tv.z, sv.w * tv.w);
        *(__half2*)(g_prod_h + base + idx)     = p0;
        *(__half2*)(g_prod_h + base + idx + 2) = p1;
        // score partial
        const float* as = aw_s + h * 128 + u;       // s part
        const float* at = as + 64;                  // t part
        part[k] = sv.x * as[0] + sv.y * as[1] + sv.z * as[2] + sv.w * as[3]
                + tv.x * at[0] + tv.y * at[1] + tv.z * at[2] + tv.w * at[3];
    }
    // reduce within each 16-lane half (heads differ between halves)
    #pragma unroll
    for (int o = 1; o < 16; o <<= 1) {
        #pragma unroll
        for (int k = 0; k < 4; k++)
            part[k] += __shfl_xor_sync(0xffffffffu, part[k], o);
    }
    if ((l & 15) == 0) {
        #pragma unroll
        for (int k = 0; k < 4; k++) {
            int h = 2 * k + hi;
            g_scores[(h * TT + t) * NB + b] = part[k] + ab_s[h];
        }
    }
}

// softmax over b (axis=1 of [H,B,T])
__global__ __launch_bounds__(256)
void softmax_kernel() {
    int ht = blockIdx.x;
    float v = g_scores[(size_t)ht * NB + threadIdx.x];
    float m = block_reduce_max256(v);
    float e = __expf(v - m);
    float s = block_reduce_sum256(e);
    g_wts[(size_t)ht * NB + threadIdx.x] = e / s;
}

// per-head message mini-GEMM, reads prod_h
__global__ __launch_bounds__(256)
void msg_kernel(const float* __restrict__ mw, const float* __restrict__ mb) {
    __shared__ float prod[64][65];
    __shared__ float mws [64][65];
    __shared__ float wt_s[64];
    __shared__ float mb_s[64];

    const int h  = blockIdx.y;
    const int p0 = blockIdx.x * 64;
    const int tid = threadIdx.x;

    for (int i = tid; i < 64 * 64; i += 256) {
        int u = i >> 6, s = i & 63;
        mws[s][u] = mw[((size_t)h * 64 + u) * 64 + s];
    }
    if (tid < 64) {
        mb_s[tid] = mb[h * 64 + tid];
        int p = p0 + tid, b = p / TT, t = p % TT;
        wt_s[tid] = g_wts[(h * TT + t) * NB + b];
    }
    for (int i = tid; i < 64 * 32; i += 256) {      // half2 granularity
        int tok = i >> 5, u2 = i & 31;
        int p = p0 + tok, b = p / TT, t = p % TT;
        size_t idx = ((size_t)(t * NB + b)) * ND + h * NSUB + u2 * 2;
        __half2 pv = *(const __half2*)(g_prod_h + idx);
        float2 pf = __half22float2(pv);
        prod[tok][u2 * 2]     = pf.x;
        prod[tok][u2 * 2 + 1] = pf.y;
    }
    __syncthreads();

    const int tx = tid & 15, ty = tid >> 4;
    float acc[4][4] = {};
    #pragma unroll 4
    for (int s = 0; s < 64; s++) {
        float a[4], w[4];
        #pragma unroll
        for (int i = 0; i < 4; i++) a[i] = prod[ty * 4 + i][s];
        #pragma unroll
        for (int j = 0; j < 4; j++) w[j] = mws[s][tx * 4 + j];
        #pragma unroll
        for (int i = 0; i < 4; i++)
            #pragma unroll
            for (int j = 0; j < 4; j++)
                acc[i][j] += a[i] * w[j];
    }
    #pragma unroll
    for (int i = 0; i < 4; i++) {
        int tok = ty * 4 + i;
        float wt = wt_s[tok];
        #pragma unroll
        for (int j = 0; j < 4; j++) {
            int u = tx * 4 + j;
            float v = wt * (acc[i][j] + mb_s[u]);
            g_wm_h[((size_t)(p0 + tok)) * ND + h * NSUB + u] =
                __float2half_rn(fmaxf(v, 0.f));
        }
    }
}

// LN1: input g_agg (already src^T + agg); writes x fp32 + fp16. float2 lanes.
__global__ __launch_bounds__(256)
void ln1_kernel(const float* __restrict__ gam, const float* __restrict__ bet) {
    int p = blockIdx.x;
    const float2* a = (const float2*)(g_agg + (size_t)p * ND);
    int i = threadIdx.x;
    float2 v = a[i];
    float mean = block_reduce_sum256(v.x + v.y) * (1.0f / ND);
    float d0 = v.x - mean, d1 = v.y - mean;
    float var = block_reduce_sum256(d0 * d0 + d1 * d1) * (1.0f / ND);
    float rstd = rsqrtf(var + 1e-5f);
    float2 gg = *(const float2*)(gam + 2 * i);
    float2 bb = *(const float2*)(bet + 2 * i);
    float o0 = d0 * rstd * gg.x + bb.x;
    float o1 = d1 * rstd * gg.y + bb.y;
    *(float2*)(g_x + (size_t)p * ND + 2 * i) = make_float2(o0, o1);
    *(__half2*)(g_x_h + (size_t)p * ND + 2 * i) = __floats2half2_rn(o0, o1);
}

// LN2: input g_y (already x + y); writes out [T,B,D] (+ fp16 copy if not last)
__global__ __launch_bounds__(256)
void ln2_kernel(const float* __restrict__ gam, const float* __restrict__ bet,
                float* __restrict__ out, int write_h) {
    int p = blockIdx.x, b = p / TT, t = p - b * TT;
    const float2* a = (const float2*)(g_y + (size_t)p * ND);
    int i = threadIdx.x;
    float2 v = a[i];
    float mean = block_reduce_sum256(v.x + v.y) * (1.0f / ND);
    float d0 = v.x - mean, d1 = v.y - mean;
    float var = block_reduce_sum256(d0 * d0 + d1 * d1) * (1.0f / ND);
    float rstd = rsqrtf(var + 1e-5f);
    float2 gg = *(const float2*)(gam + 2 * i);
    float2 bb = *(const float2*)(bet + 2 * i);
    float o0 = d0 * rstd * gg.x + bb.x;
    float o1 = d1 * rstd * gg.y + bb.y;
    size_t obase = ((size_t)(t * NB + b)) * ND + 2 * i;
    *(float2*)(out + obase) = make_float2(o0, o1);
    if (write_h)
        *(__half2*)(g_src_h + obase) = __floats2half2_rn(o0, o1);
}

// ---------------------------------------------------------------------------
extern "C" void kernel_launch(void* const* d_in, const int* in_sizes, int n_in,
                              void* d_out, int out_size) {
    const float* in_src  = (const float*)d_in[0];
    const float* in_srcc = (const float*)d_in[1];
    const float* w_sp = (const float*)d_in[2];
    const float* b_sp = (const float*)d_in[3];
    const float* w_tp = (const float*)d_in[4];
    const float* b_tp = (const float*)d_in[5];
    const float* w_at = (const float*)d_in[6];
    const float* b_at = (const float*)d_in[7];
    const float* w_mg = (const float*)d_in[8];
    const float* b_mg = (const float*)d_in[9];
    const float* w_ag = (const float*)d_in[10];
    const float* b_ag = (const float*)d_in[11];
    const float* w_l1 = (const float*)d_in[12];
    const float* b_l1 = (const float*)d_in[13];
    const float* w_l2 = (const float*)d_in[14];
    const float* b_l2 = (const float*)d_in[15];
    const float* g_n1 = (const float*)d_in[16];
    const float* bb_n1 = (const float*)d_in[17];
    const float* g_n2 = (const float*)d_in[18];
    const float* bb_n2 = (const float*)d_in[19];

    float *p_agg, *p_x, *p_y, *p_src, *p_s, *p_t;
    __half *p_wm_h, *p_x_h, *p_h1_h, *p_src_h, *p_srcc_h, *p_src0_h;
    __half *p_wsp, *p_wtp, *p_wag, *p_wl1, *p_wl2;
    cudaGetSymbolAddress((void**)&p_s,      g_s);
    cudaGetSymbolAddress((void**)&p_t,      g_t);
    cudaGetSymbolAddress((void**)&p_agg,    g_agg);
    cudaGetSymbolAddress((void**)&p_x,      g_x);
    cudaGetSymbolAddress((void**)&p_y,      g_y);
    cudaGetSymbolAddress((void**)&p_src,    g_src);
    cudaGetSymbolAddress((void**)&p_wm_h,   g_wm_h);
    cudaGetSymbolAddress((void**)&p_x_h,    g_x_h);
    cudaGetSymbolAddress((void**)&p_h1_h,   g_h1_h);
    cudaGetSymbolAddress((void**)&p_src_h,  g_src_h);
    cudaGetSymbolAddress((void**)&p_srcc_h, g_srcc_h);
    cudaGetSymbolAddress((void**)&p_src0_h, g_src0_h);
    cudaGetSymbolAddress((void**)&p_wsp,    g_wsp_h);
    cudaGetSymbolAddress((void**)&p_wtp,    g_wtp_h);
    cudaGetSymbolAddress((void**)&p_wag,    g_wag_h);
    cudaGetSymbolAddress((void**)&p_wl1,    g_wl1_h);
    cudaGetSymbolAddress((void**)&p_wl2,    g_wl2_h);

    cudaFuncSetAttribute(tc_gemm<1, 0, 0>, cudaFuncAttributeMaxDynamicSharedMemorySize, DYN_SMEM);
    cudaFuncSetAttribute(tc_gemm<0, 0, 2>, cudaFuncAttributeMaxDynamicSharedMemorySize, DYN_SMEM);
    cudaFuncSetAttribute(tc_gemm<1, 1, 0>, cudaFuncAttributeMaxDynamicSharedMemorySize, DYN_SMEM);
    cudaFuncSetAttribute(tc_gemm<0, 0, 1>, cudaFuncAttributeMaxDynamicSharedMemorySize, DYN_SMEM);

    // one-time fp16 conversions
    f32_to_f16_kernel<<<2048, 256>>>((const float4*)in_srcc, (__half2*)p_srcc_h, NTOK * ND / 4);
    f32_to_f16_kernel<<<2048, 256>>>((const float4*)in_src,  (__half2*)p_src0_h, NTOK * ND / 4);
    f32_to_f16_kernel<<<2048, 256>>>((const float4*)w_sp, (__half2*)p_wsp, NL * ND * ND / 4);
    f32_to_f16_kernel<<<2048, 256>>>((const float4*)w_tp, (__half2*)p_wtp, NL * ND * ND / 4);
    f32_to_f16_kernel<<<2048, 256>>>((const float4*)w_ag, (__half2*)p_wag, NL * ND * ND / 4);
    f32_to_f16_kernel<<<2048, 256>>>((const float4*)w_l1, (__half2*)p_wl1, NL * NDFF * ND / 4);
    f32_to_f16_kernel<<<2048, 256>>>((const float4*)w_l2, (__half2*)p_wl2, NL * ND * NDFF / 4);

    for (int l = 0; l < NL; l++) {
        const __half* srcA   = (l == 0) ? p_src0_h : p_src_h;
        const float*  srcRes = (l == 0) ? in_src   : p_src;

        // s = relu(srcc @ sw^T + sb)  [fp32 out]
        tc_gemm<1, 0, 0><<<dim3(ND / BN, NTOK / BM), 256, DYN_SMEM>>>(
            p_srcc_h, p_wsp + (size_t)l * ND * ND, b_sp + l * ND, p_s, nullptr, nullptr, ND, ND);
        // t = relu(src @ tw^T + tb)  [fp32 out]
        tc_gemm<1, 0, 0><<<dim3(ND / BN, NTOK / BM), 256, DYN_SMEM>>>(
            srcA, p_wtp + (size_t)l * ND * ND, b_tp + l * ND, p_t, nullptr, nullptr, ND, ND);
        // fused scores + product
        fuse_st_kernel<<<NTOK / 8, 256>>>(w_at + (size_t)l * NH * 2 * NSUB, b_at + l * NH);
        softmax_kernel<<<NH * TT, NB>>>();
        // weighted message -> relu(wm) [B,T,D] fp16
        msg_kernel<<<dim3(NTOK / 64, NH), 256>>>(w_mg + (size_t)l * NH * NSUB * NSUB,
                                                 b_mg + l * NH * NSUB);
        // agg = wm @ gw^T + gb + src^T  [fp32 out, residual fused]
        tc_gemm<0, 0, 2><<<dim3(ND / BN, NTOK / BM), 256, DYN_SMEM>>>(
            p_wm_h, p_wag + (size_t)l * ND * ND, b_ag + l * ND, p_agg, nullptr, srcRes, ND, ND);
        // x = LN(agg')  [fp32 + fp16]
        ln1_kernel<<<NTOK, 256>>>(g_n1 + l * ND, bb_n1 + l * ND);
        // h1 = relu(x @ w1^T + b1)  [fp16 out only]
        tc_gemm<1, 1, 0><<<dim3(NDFF / BN, NTOK / BM), 256, DYN_SMEM>>>(
            p_x_h, p_wl1 + (size_t)l * NDFF * ND, b_l1 + l * NDFF, nullptr, p_h1_h, nullptr, ND, NDFF);
        // y = h1 @ w2^T + b2 + x  [fp32 out, residual fused]
        tc_gemm<0, 0, 1><<<dim3(ND / BN, NTOK / BM), 256, DYN_SMEM>>>(
            p_h1_h, p_wl2 + (size_t)l * ND * NDFF, b_l2 + l * ND, p_y, nullptr, p_x, NDFF, ND);
        // out = LN(y') -> [T,B,D]
        float* dst = (l == NL - 1) ? (float*)d_out : p_src;
        ln2_kernel<<<NTOK, 256>>>(g_n2 + l * ND, bb_n2 + l * ND, dst, (l == NL - 1) ? 0 : 1);
    }
}

// round 5
// speedup vs baseline: 6.0139x; 1.1608x over previous
#include <cuda_runtime.h>
#include <cuda_fp16.h>
#include <cstdint>
#include <cstddef>

// Problem dims
#define NL   6
#define TT   128
#define NB   256
#define ND   512
#define NH   8
#define NDFF 2048
#define NSUB 64
#define NTOK (TT * NB)   // 32768 tokens

// mma.sync GEMM tile config (fp16 in, fp32 accum)
// CTA tile 128x128x64, 4 warps (2x2), warp tile 64x64, 3-stage cp.async
#define BM 128
#define BN 128
#define BKH 64                         // 64 halves = 128B row
#define NSTAGE 3
#define A_BYTES (BM * BKH * 2)         // 16384
#define STAGE_BYTES (2 * A_BYTES)      // 32768
#define DYN_SMEM (NSTAGE * STAGE_BYTES)  // 98304

// ---------------------------------------------------------------------------
// Scratch (__device__ globals; no allocation allowed)
// ---------------------------------------------------------------------------
__device__ __align__(16) __half g_s_h [(size_t)NTOK * ND];
__device__ __align__(16) __half g_t_h [(size_t)NTOK * ND];
__device__ __align__(16) float  g_scores[NH * TT * NB];
__device__ __align__(16) float  g_wts   [NH * TT * NB];
__device__ __align__(16) __half g_prod_h[(size_t)NTOK * ND];
__device__ __align__(16) __half g_wm_h[(size_t)NTOK * ND];
__device__ __align__(16) float  g_agg [(size_t)NTOK * ND];   // holds src^T + agg
__device__ __align__(16) float  g_x   [(size_t)NTOK * ND];
__device__ __align__(16) __half g_x_h [(size_t)NTOK * ND];
__device__ __align__(16) __half g_h1_h[(size_t)NTOK * NDFF];
__device__ __align__(16) float  g_y   [(size_t)NTOK * ND];   // holds x + y
__device__ __align__(16) float  g_src [(size_t)NTOK * ND];
__device__ __align__(16) __half g_src_h[(size_t)NTOK * ND];
__device__ __align__(16) __half g_srcc_h[(size_t)NTOK * ND];
__device__ __align__(16) __half g_src0_h[(size_t)NTOK * ND];
// fp16 weights
__device__ __align__(16) __half g_wsp_h[(size_t)NL * ND * ND];
__device__ __align__(16) __half g_wtp_h[(size_t)NL * ND * ND];
__device__ __align__(16) __half g_wag_h[(size_t)NL * ND * ND];
__device__ __align__(16) __half g_wl1_h[(size_t)NL * NDFF * ND];
__device__ __align__(16) __half g_wl2_h[(size_t)NL * ND * NDFF];

// ---------------------------------------------------------------------------
// PTX helpers (baseline sm_80+ instructions only)
// ---------------------------------------------------------------------------
__device__ __forceinline__ uint32_t smem_u32(const void* p) {
    uint32_t a;
    asm("{ .reg .u64 t; cvta.to.shared.u64 t, %1; cvt.u32.u64 %0, t; }"
        : "=r"(a) : "l"(p));
    return a;
}
__device__ __forceinline__ void cp_async16(uint32_t dst, const void* src) {
    asm volatile("cp.async.cg.shared.global [%0], [%1], 16;" :: "r"(dst), "l"(src));
}
#define CP_COMMIT() asm volatile("cp.async.commit_group;" ::: "memory")
#define CP_WAIT1()  asm volatile("cp.async.wait_group 1;" ::: "memory")

__device__ __forceinline__ void ldsm_x4(uint32_t* r, uint32_t addr) {
    asm volatile("ldmatrix.sync.aligned.m8n8.x4.shared.b16 {%0,%1,%2,%3}, [%4];"
                 : "=r"(r[0]), "=r"(r[1]), "=r"(r[2]), "=r"(r[3]) : "r"(addr));
}
__device__ __forceinline__ void mma16816(float* d, const uint32_t* a,
                                         uint32_t b0, uint32_t b1) {
    asm volatile(
        "mma.sync.aligned.m16n8k16.row.col.f32.f16.f16.f32 "
        "{%0,%1,%2,%3}, {%4,%5,%6,%7}, {%8,%9}, {%0,%1,%2,%3};"
        : "+f"(d[0]), "+f"(d[1]), "+f"(d[2]), "+f"(d[3])
        : "r"(a[0]), "r"(a[1]), "r"(a[2]), "r"(a[3]), "r"(b0), "r"(b1));
}

// ---------------------------------------------------------------------------
// cooperative stage loader (128 threads): A + B tile [128 x 64h], swizzled
// ---------------------------------------------------------------------------
__device__ __forceinline__ void load_stage(const __half* __restrict__ Ag,
                                           const __half* __restrict__ Wg,
                                           int K, uint32_t abase, uint32_t bbase,
                                           int tid) {
    #pragma unroll
    for (int it = 0; it < 8; it++) {
        int q = tid + it * 128;        // 0..1023 16B chunks per operand
        int r = q >> 3;                // row 0..127
        int c = q & 7;                 // logical 16B chunk in row
        uint32_t off = (uint32_t)(r * 128 + ((c ^ (r & 7)) << 4));
        cp_async16(abase + off, Ag + (size_t)r * K + c * 8);
        cp_async16(bbase + off, Wg + (size_t)r * K + c * 8);
    }
    CP_COMMIT();
}

// fragment loader: one k16 slice for this warp (64x64 warp tile)
__device__ __forceinline__ void load_frags(uint32_t aB, uint32_t bB, int ks,
                                           int arow, int brow, int axor, int bxor,
                                           int csel,
                                           uint32_t af[4][4], uint32_t bf[4][4]) {
    #pragma unroll
    for (int mt = 0; mt < 4; mt++) {
        uint32_t addr = aB + (uint32_t)((arow + mt * 16) * 128)
                      + (uint32_t)((((ks << 1) + csel) ^ axor) << 4);
        ldsm_x4(af[mt], addr);
    }
    #pragma unroll
    for (int np = 0; np < 4; np++) {
        uint32_t addr = bB + (uint32_t)((brow + np * 16) * 128)
                      + (uint32_t)((((ks << 1) + csel) ^ bxor) << 4);
        ldsm_x4(bf[np], addr);
    }
}

// ---------------------------------------------------------------------------
// fp16 tensor-core GEMM: C[M,N] = A[M,K]@W[N,K]^T + bias (+residual), opt relu.
// ADDMODE: 0 none, 1 res same layout as C, 2 res transposed [(m%TT)*NB+(m/TT)]
// grid (N/128, M/128), 128 threads (4 warps, 2x2, warp tile 64x64).
// ---------------------------------------------------------------------------
template <int RELU, int OUTH, int ADDMODE>
__global__ __launch_bounds__(128)
void tc_gemm(const __half* __restrict__ A, const __half* __restrict__ W,
             const float* __restrict__ bias, float* __restrict__ Cf,
             __half* __restrict__ Ch, const float* __restrict__ Res,
             int K, int N) {
    __shared__ float s_bias[BN];
    extern __shared__ __align__(1024) char dynsmem[];
    const uint32_t dynbase = smem_u32(dynsmem);

    const int tid = threadIdx.x;
    const int wid = tid >> 5, lid = tid & 31;
    const int wm_ = wid >> 1, wn_ = wid & 1;   // 2 x 2 warp grid
    const int m0 = blockIdx.y * BM, n0 = blockIdx.x * BN;

    s_bias[tid] = bias[n0 + tid];

    const __half* Abase = A + (size_t)m0 * K;
    const __half* Wbase = W + (size_t)n0 * K;
    const int NCH = K / BKH;

    // per-lane ldmatrix geometry
    const int sub = lid >> 3, wi = lid & 7;
    const int csel = sub >> 1;                       // 0/1 -> k halves 0/8
    const int arow = wm_ * 64 + (sub & 1) * 8 + wi;  // + mt*16
    const int brow = wn_ * 64 + (sub & 1) * 8 + wi;  // + np*16
    const int axor = arow & 7, bxor = brow & 7;      // invariant under +16

    // prologue: stages 0..1
    #pragma unroll
    for (int c = 0; c < NSTAGE - 1; c++)
        load_stage(Abase + c * BKH, Wbase + c * BKH, K,
                   dynbase + c * STAGE_BYTES,
                   dynbase + c * STAGE_BYTES + A_BYTES, tid);

    float acc[4][8][4] = {};
    uint32_t afr[2][4][4], bfr[2][4][4];

    int stage = 0;
    for (int i = 0; i < NCH; i++) {
        CP_WAIT1();              // stage for chunk i resident (<=1 pending)
        __syncthreads();         // all warps done reading the slot being refilled
        int j = i + NSTAGE - 1;
        int sj = stage + NSTAGE - 1; if (sj >= NSTAGE) sj -= NSTAGE;
        if (j < NCH) {
            load_stage(Abase + j * BKH, Wbase + j * BKH, K,
                       dynbase + sj * STAGE_BYTES,
                       dynbase + sj * STAGE_BYTES + A_BYTES, tid);
        } else {
            CP_COMMIT();         // keep group accounting uniform
        }

        const uint32_t aB = dynbase + stage * STAGE_BYTES;
        const uint32_t bB = aB + A_BYTES;

        load_frags(aB, bB, 0, arow, brow, axor, bxor, csel, afr[0], bfr[0]);
        #pragma unroll
        for (int ks = 0; ks < 4; ks++) {
            int cur = ks & 1;
            if (ks < 3)
                load_frags(aB, bB, ks + 1, arow, brow, axor, bxor, csel,
                           afr[cur ^ 1], bfr[cur ^ 1]);
            #pragma unroll
            for (int mt = 0; mt < 4; mt++)
                #pragma unroll
                for (int nt = 0; nt < 8; nt++)
                    mma16816(acc[mt][nt], afr[cur][mt],
                             bfr[cur][nt >> 1][nt & 1],
                             bfr[cur][nt >> 1][(nt & 1) + 2]);
        }
        if (++stage == NSTAGE) stage = 0;
    }

    // epilogue: direct stores (+ optional residual)
    #pragma unroll
    for (int mt = 0; mt < 4; mt++) {
        int row = m0 + wm_ * 64 + mt * 16 + (lid >> 2);
        size_t rb0 = 0, rb1 = 0;
        if (ADDMODE == 1) {
            rb0 = (size_t)row * N;
            rb1 = (size_t)(row + 8) * N;
        } else if (ADDMODE == 2) {
            int b0_ = row >> 7, t0_ = row & 127;          // TT = 128
            int b1_ = (row + 8) >> 7, t1_ = (row + 8) & 127;
            rb0 = ((size_t)(t0_ * NB + b0_)) * ND;
            rb1 = ((size_t)(t1_ * NB + b1_)) * ND;
        }
        #pragma unroll
        for (int nt = 0; nt < 8; nt++) {
            int coll = wn_ * 64 + nt * 8 + (lid & 3) * 2;
            int col = n0 + coll;
            float bx = s_bias[coll], by = s_bias[coll + 1];
            float v0 = acc[mt][nt][0] + bx, v1 = acc[mt][nt][1] + by;
            float v2 = acc[mt][nt][2] + bx, v3 = acc[mt][nt][3] + by;
            if (ADDMODE != 0) {
                float2 r0 = *(const float2*)(Res + rb0 + col);
                float2 r1 = *(const float2*)(Res + rb1 + col);
                v0 += r0.x; v1 += r0.y; v2 += r1.x; v3 += r1.y;
            }
            if (RELU) {
                v0 = fmaxf(v0, 0.f); v1 = fmaxf(v1, 0.f);
                v2 = fmaxf(v2, 0.f); v3 = fmaxf(v3, 0.f);
            }
            if (OUTH) {
                *(__half2*)(Ch + (size_t)row * N + col)       = __floats2half2_rn(v0, v1);
                *(__half2*)(Ch + (size_t)(row + 8) * N + col) = __floats2half2_rn(v2, v3);
            } else {
                *(float2*)(Cf + (size_t)row * N + col)       = make_float2(v0, v1);
                *(float2*)(Cf + (size_t)(row + 8) * N + col) = make_float2(v2, v3);
            }
        }
    }
}

// ---------------------------------------------------------------------------
// f32 -> f16 conversion (float4 -> half2x2)
// ---------------------------------------------------------------------------
__global__ __launch_bounds__(256)
void f32_to_f16_kernel(const float4* __restrict__ in, __half2* __restrict__ out, int n4) {
    for (int i = blockIdx.x * 256 + threadIdx.x; i < n4; i += gridDim.x * 256) {
        float4 v = in[i];
        out[2 * i]     = __floats2half2_rn(v.x, v.y);
        out[2 * i + 1] = __floats2half2_rn(v.z, v.w);
    }
}

// ---------------------------------------------------------------------------
// Block reductions (256 threads)
// ---------------------------------------------------------------------------
__device__ __forceinline__ float block_reduce_sum256(float v) {
    __shared__ float sh[8];
    int lane = threadIdx.x & 31, wid = threadIdx.x >> 5;
    #pragma unroll
    for (int o = 16; o; o >>= 1) v += __shfl_xor_sync(0xffffffffu, v, o);
    if (lane == 0) sh[wid] = v;
    __syncthreads();
    float r = (lane < 8) ? sh[lane] : 0.0f;
    #pragma unroll
    for (int o = 4; o; o >>= 1) r += __shfl_xor_sync(0xffffffffu, r, o);
    r = __shfl_sync(0xffffffffu, r, 0);
    __syncthreads();
    return r;
}
__device__ __forceinline__ float block_reduce_max256(float v) {
    __shared__ float sh[8];
    int lane = threadIdx.x & 31, wid = threadIdx.x >> 5;
    #pragma unroll
    for (int o = 16; o; o >>= 1) v = fmaxf(v, __shfl_xor_sync(0xffffffffu, v, o));
    if (lane == 0) sh[wid] = v;
    __syncthreads();
    float r = (lane < 8) ? sh[lane] : -3.4e38f;
    #pragma unroll
    for (int o = 4; o; o >>= 1) r = fmaxf(r, __shfl_xor_sync(0xffffffffu, r, o));
    r = __shfl_sync(0xffffffffu, r, 0);
    __syncthreads();
    return r;
}

// ---------------------------------------------------------------------------
// fused scores + (s*t) product: one warp per token. s,t are fp16 now.
// scores[h][t][b] = dot(s, aw[h][:64]) + dot(t, aw[h][64:]) + ab[h]
// prod_h[tok][:] = s_h * t_h (fp16 multiply)
// ---------------------------------------------------------------------------
__global__ __launch_bounds__(256)
void fuse_st_kernel(const float* __restrict__ aw, const float* __restrict__ ab) {
    __shared__ float aw_s[NH * 2 * NSUB];   // 1024 floats
    __shared__ float ab_s[NH];

    const int tid = threadIdx.x;
    for (int i = tid; i < NH * 2 * NSUB; i += 256) aw_s[i] = aw[i];
    if (tid < NH) ab_s[tid] = ab[tid];
    __syncthreads();

    const int w = blockIdx.x * 8 + (tid >> 5);      // token index (t*NB+b)
    const int l = tid & 31;
    const int t = w / NB, b = w % NB;
    const size_t base = (size_t)w * ND;
    const int hi = l >> 4;                          // 0 or 1

    float part[4];
    #pragma unroll
    for (int k = 0; k < 4; k++) {
        int idx = k * 128 + l * 4;                  // 4 halves = 8 bytes
        int h = idx >> 6;                           // = 2k + hi
        int u = idx & 63;
        uint2 sraw = *(const uint2*)(g_s_h + base + idx);
        uint2 traw = *(const uint2*)(g_t_h + base + idx);
        __half2 s0 = *(__half2*)&sraw.x, s1 = *(__half2*)&sraw.y;
        __half2 t0 = *(__half2*)&traw.x, t1 = *(__half2*)&traw.y;
        // product in fp16
        __half2 p0 = __hmul2(s0, t0), p1 = __hmul2(s1, t1);
        uint2 praw; praw.x = *(uint32_t*)&p0; praw.y = *(uint32_t*)&p1;
        *(uint2*)(g_prod_h + base + idx) = praw;
        // score partial in fp32
        float2 s0f = __half22float2(s0), s1f = __half22float2(s1);
        float2 t0f = __half22float2(t0), t1f = __half22float2(t1);
        const float* as = aw_s + h * 128 + u;       // s part
        const float* at = as + 64;                  // t part
        part[k] = s0f.x * as[0] + s0f.y * as[1] + s1f.x * as[2] + s1f.y * as[3]
                + t0f.x * at[0] + t0f.y * at[1] + t1f.x * at[2] + t1f.y * at[3];
    }
    // reduce within each 16-lane half (heads differ between halves)
    #pragma unroll
    for (int o = 1; o < 16; o <<= 1) {
        #pragma unroll
        for (int k = 0; k < 4; k++)
            part[k] += __shfl_xor_sync(0xffffffffu, part[k], o);
    }
    if ((l & 15) == 0) {
        #pragma unroll
        for (int k = 0; k < 4; k++) {
            int h = 2 * k + hi;
            g_scores[(h * TT + t) * NB + b] = part[k] + ab_s[h];
        }
    }
}

// softmax over b (axis=1 of [H,B,T])
__global__ __launch_bounds__(256)
void softmax_kernel() {
    int ht = blockIdx.x;
    float v = g_scores[(size_t)ht * NB + threadIdx.x];
    float m = block_reduce_max256(v);
    float e = __expf(v - m);
    float s = block_reduce_sum256(e);
    g_wts[(size_t)ht * NB + threadIdx.x] = e / s;
}

// per-head message mini-GEMM, reads prod_h
__global__ __launch_bounds__(256)
void msg_kernel(const float* __restrict__ mw, const float* __restrict__ mb) {
    __shared__ float prod[64][65];
    __shared__ float mws [64][65];
    __shared__ float wt_s[64];
    __shared__ float mb_s[64];

    const int h  = blockIdx.y;
    const int p0 = blockIdx.x * 64;
    const int tid = threadIdx.x;

    for (int i = tid; i < 64 * 64; i += 256) {
        int u = i >> 6, s = i & 63;
        mws[s][u] = mw[((size_t)h * 64 + u) * 64 + s];
    }
    if (tid < 64) {
        mb_s[tid] = mb[h * 64 + tid];
        int p = p0 + tid, b = p / TT, t = p % TT;
        wt_s[tid] = g_wts[(h * TT + t) * NB + b];
    }
    for (int i = tid; i < 64 * 32; i += 256) {      // half2 granularity
        int tok = i >> 5, u2 = i & 31;
        int p = p0 + tok, b = p / TT, t = p % TT;
        size_t idx = ((size_t)(t * NB + b)) * ND + h * NSUB + u2 * 2;
        __half2 pv = *(const __half2*)(g_prod_h + idx);
        float2 pf = __half22float2(pv);
        prod[tok][u2 * 2]     = pf.x;
        prod[tok][u2 * 2 + 1] = pf.y;
    }
    __syncthreads();

    const int tx = tid & 15, ty = tid >> 4;
    float acc[4][4] = {};
    #pragma unroll 4
    for (int s = 0; s < 64; s++) {
        float a[4], w[4];
        #pragma unroll
        for (int i = 0; i < 4; i++) a[i] = prod[ty * 4 + i][s];
        #pragma unroll
        for (int j = 0; j < 4; j++) w[j] = mws[s][tx * 4 + j];
        #pragma unroll
        for (int i = 0; i < 4; i++)
            #pragma unroll
            for (int j = 0; j < 4; j++)
                acc[i][j] += a[i] * w[j];
    }
    #pragma unroll
    for (int i = 0; i < 4; i++) {
        int tok = ty * 4 + i;
        float wt = wt_s[tok];
        #pragma unroll
        for (int j = 0; j < 4; j++) {
            int u = tx * 4 + j;
            float v = wt * (acc[i][j] + mb_s[u]);
            g_wm_h[((size_t)(p0 + tok)) * ND + h * NSUB + u] =
                __float2half_rn(fmaxf(v, 0.f));
        }
    }
}

// LN1: input g_agg (already src^T + agg); writes x fp32 + fp16. float2 lanes.
__global__ __launch_bounds__(256)
void ln1_kernel(const float* __restrict__ gam, const float* __restrict__ bet) {
    int p = blockIdx.x;
    const float2* a = (const float2*)(g_agg + (size_t)p * ND);
    int i = threadIdx.x;
    float2 v = a[i];
    float mean = block_reduce_sum256(v.x + v.y) * (1.0f / ND);
    float d0 = v.x - mean, d1 = v.y - mean;
    float var = block_reduce_sum256(d0 * d0 + d1 * d1) * (1.0f / ND);
    float rstd = rsqrtf(var + 1e-5f);
    float2 gg = *(const float2*)(gam + 2 * i);
    float2 bb = *(const float2*)(bet + 2 * i);
    float o0 = d0 * rstd * gg.x + bb.x;
    float o1 = d1 * rstd * gg.y + bb.y;
    *(float2*)(g_x + (size_t)p * ND + 2 * i) = make_float2(o0, o1);
    *(__half2*)(g_x_h + (size_t)p * ND + 2 * i) = __floats2half2_rn(o0, o1);
}

// LN2: input g_y (already x + y); writes out [T,B,D] (+ fp16 copy if not last)
__global__ __launch_bounds__(256)
void ln2_kernel(const float* __restrict__ gam, const float* __restrict__ bet,
                float* __restrict__ out, int write_h) {
    int p = blockIdx.x, b = p / TT, t = p - b * TT;
    const float2* a = (const float2*)(g_y + (size_t)p * ND);
    int i = threadIdx.x;
    float2 v = a[i];
    float mean = block_reduce_sum256(v.x + v.y) * (1.0f / ND);
    float d0 = v.x - mean, d1 = v.y - mean;
    float var = block_reduce_sum256(d0 * d0 + d1 * d1) * (1.0f / ND);
    float rstd = rsqrtf(var + 1e-5f);
    float2 gg = *(const float2*)(gam + 2 * i);
    float2 bb = *(const float2*)(bet + 2 * i);
    float o0 = d0 * rstd * gg.x + bb.x;
    float o1 = d1 * rstd * gg.y + bb.y;
    size_t obase = ((size_t)(t * NB + b)) * ND + 2 * i;
    *(float2*)(out + obase) = make_float2(o0, o1);
    if (write_h)
        *(__half2*)(g_src_h + obase) = __floats2half2_rn(o0, o1);
}

// ---------------------------------------------------------------------------
extern "C" void kernel_launch(void* const* d_in, const int* in_sizes, int n_in,
                              void* d_out, int out_size) {
    const float* in_src  = (const float*)d_in[0];
    const float* in_srcc = (const float*)d_in[1];
    const float* w_sp = (const float*)d_in[2];
    const float* b_sp = (const float*)d_in[3];
    const float* w_tp = (const float*)d_in[4];
    const float* b_tp = (const float*)d_in[5];
    const float* w_at = (const float*)d_in[6];
    const float* b_at = (const float*)d_in[7];
    const float* w_mg = (const float*)d_in[8];
    const float* b_mg = (const float*)d_in[9];
    const float* w_ag = (const float*)d_in[10];
    const float* b_ag = (const float*)d_in[11];
    const float* w_l1 = (const float*)d_in[12];
    const float* b_l1 = (const float*)d_in[13];
    const float* w_l2 = (const float*)d_in[14];
    const float* b_l2 = (const float*)d_in[15];
    const float* g_n1 = (const float*)d_in[16];
    const float* bb_n1 = (const float*)d_in[17];
    const float* g_n2 = (const float*)d_in[18];
    const float* bb_n2 = (const float*)d_in[19];

    float *p_agg, *p_x, *p_y, *p_src;
    __half *p_s_h, *p_t_h, *p_wm_h, *p_x_h, *p_h1_h, *p_src_h, *p_srcc_h, *p_src0_h;
    __half *p_wsp, *p_wtp, *p_wag, *p_wl1, *p_wl2;
    cudaGetSymbolAddress((void**)&p_s_h,    g_s_h);
    cudaGetSymbolAddress((void**)&p_t_h,    g_t_h);
    cudaGetSymbolAddress((void**)&p_agg,    g_agg);
    cudaGetSymbolAddress((void**)&p_x,      g_x);
    cudaGetSymbolAddress((void**)&p_y,      g_y);
    cudaGetSymbolAddress((void**)&p_src,    g_src);
    cudaGetSymbolAddress((void**)&p_wm_h,   g_wm_h);
    cudaGetSymbolAddress((void**)&p_x_h,    g_x_h);
    cudaGetSymbolAddress((void**)&p_h1_h,   g_h1_h);
    cudaGetSymbolAddress((void**)&p_src_h,  g_src_h);
    cudaGetSymbolAddress((void**)&p_srcc_h, g_srcc_h);
    cudaGetSymbolAddress((void**)&p_src0_h, g_src0_h);
    cudaGetSymbolAddress((void**)&p_wsp,    g_wsp_h);
    cudaGetSymbolAddress((void**)&p_wtp,    g_wtp_h);
    cudaGetSymbolAddress((void**)&p_wag,    g_wag_h);
    cudaGetSymbolAddress((void**)&p_wl1,    g_wl1_h);
    cudaGetSymbolAddress((void**)&p_wl2,    g_wl2_h);

    cudaFuncSetAttribute(tc_gemm<1, 1, 0>, cudaFuncAttributeMaxDynamicSharedMemorySize, DYN_SMEM);
    cudaFuncSetAttribute(tc_gemm<0, 0, 2>, cudaFuncAttributeMaxDynamicSharedMemorySize, DYN_SMEM);
    cudaFuncSetAttribute(tc_gemm<0, 0, 1>, cudaFuncAttributeMaxDynamicSharedMemorySize, DYN_SMEM);

    // one-time fp16 conversions
    f32_to_f16_kernel<<<2048, 256>>>((const float4*)in_srcc, (__half2*)p_srcc_h, NTOK * ND / 4);
    f32_to_f16_kernel<<<2048, 256>>>((const float4*)in_src,  (__half2*)p_src0_h, NTOK * ND / 4);
    f32_to_f16_kernel<<<2048, 256>>>((const float4*)w_sp, (__half2*)p_wsp, NL * ND * ND / 4);
    f32_to_f16_kernel<<<2048, 256>>>((const float4*)w_tp, (__half2*)p_wtp, NL * ND * ND / 4);
    f32_to_f16_kernel<<<2048, 256>>>((const float4*)w_ag, (__half2*)p_wag, NL * ND * ND / 4);
    f32_to_f16_kernel<<<2048, 256>>>((const float4*)w_l1, (__half2*)p_wl1, NL * NDFF * ND / 4);
    f32_to_f16_kernel<<<2048, 256>>>((const float4*)w_l2, (__half2*)p_wl2, NL * ND * NDFF / 4);

    for (int l = 0; l < NL; l++) {
        const __half* srcA   = (l == 0) ? p_src0_h : p_src_h;
        const float*  srcRes = (l == 0) ? in_src   : p_src;

        // s = relu(srcc @ sw^T + sb)  [fp16 out]
        tc_gemm<1, 1, 0><<<dim3(ND / BN, NTOK / BM), 128, DYN_SMEM>>>(
            p_srcc_h, p_wsp + (size_t)l * ND * ND, b_sp + l * ND, nullptr, p_s_h, nullptr, ND, ND);
        // t = relu(src @ tw^T + tb)  [fp16 out]
        tc_gemm<1, 1, 0><<<dim3(ND / BN, NTOK / BM), 128, DYN_SMEM>>>(
            srcA, p_wtp + (size_t)l * ND * ND, b_tp + l * ND, nullptr, p_t_h, nullptr, ND, ND);
        // fused scores + product
        fuse_st_kernel<<<NTOK / 8, 256>>>(w_at + (size_t)l * NH * 2 * NSUB, b_at + l * NH);
        softmax_kernel<<<NH * TT, NB>>>();
        // weighted message -> relu(wm) [B,T,D] fp16
        msg_kernel<<<dim3(NTOK / 64, NH), 256>>>(w_mg + (size_t)l * NH * NSUB * NSUB,
                                                 b_mg + l * NH * NSUB);
        // agg = wm @ gw^T + gb + src^T  [fp32 out, residual fused]
        tc_gemm<0, 0, 2><<<dim3(ND / BN, NTOK / BM), 128, DYN_SMEM>>>(
            p_wm_h, p_wag + (size_t)l * ND * ND, b_ag + l * ND, p_agg, nullptr, srcRes, ND, ND);
        // x = LN(agg')  [fp32 + fp16]
        ln1_kernel<<<NTOK, 256>>>(g_n1 + l * ND, bb_n1 + l * ND);
        // h1 = relu(x @ w1^T + b1)  [fp16 out only]
        tc_gemm<1, 1, 0><<<dim3(NDFF / BN, NTOK / BM), 128, DYN_SMEM>>>(
            p_x_h, p_wl1 + (size_t)l * NDFF * ND, b_l1 + l * NDFF, nullptr, p_h1_h, nullptr, ND, NDFF);
        // y = h1 @ w2^T + b2 + x  [fp32 out, residual fused]
        tc_gemm<0, 0, 1><<<dim3(ND / BN, NTOK / BM), 128, DYN_SMEM>>>(
            p_h1_h, p_wl2 + (size_t)l * ND * NDFF, b_l2 + l * ND, p_y, nullptr, p_x, NDFF, ND);
        // out = LN(y') -> [T,B,D]
        float* dst = (l == NL - 1) ? (float*)d_out : p_src;
        ln2_kernel<<<NTOK, 256>>>(g_n2 + l * ND, bb_n2 + l * ND, dst, (l == NL - 1) ? 0 : 1);
    }
}

// round 6
// speedup vs baseline: 6.4934x; 1.0797x over previous
#include <cuda_runtime.h>
#include <cuda_fp16.h>
#include <cstdint>
#include <cstddef>

// Problem dims
#define NL   6
#define TT   128
#define NB   256
#define ND   512
#define NH   8
#define NDFF 2048
#define NSUB 64
#define NTOK (TT * NB)   // 32768 tokens

// mma.sync GEMM tile config (fp16 in, fp32 accum)
// CTA tile 128x128x64, 4 warps (2x2), warp tile 64x64, 3-stage cp.async
#define BM 128
#define BN 128
#define BKH 64                         // 64 halves = 128B row
#define NSTAGE 3
#define A_BYTES (BM * BKH * 2)         // 16384
#define STAGE_BYTES (2 * A_BYTES)      // 32768
#define DYN_SMEM (NSTAGE * STAGE_BYTES)  // 98304

// ---------------------------------------------------------------------------
// Scratch (__device__ globals; no allocation allowed)
// ---------------------------------------------------------------------------
__device__ __align__(16) __half g_s_h [(size_t)NTOK * ND];
__device__ __align__(16) __half g_t_h [(size_t)NTOK * ND];
__device__ __align__(16) float  g_scores[NH * TT * NB];
__device__ __align__(16) float  g_wts   [NH * TT * NB];
__device__ __align__(16) __half g_wm_h[(size_t)NTOK * ND];
__device__ __align__(16) float  g_agg [(size_t)NTOK * ND];   // holds src^T + agg
__device__ __align__(16) __half g_x_h [(size_t)NTOK * ND];
__device__ __align__(16) __half g_h1_h[(size_t)NTOK * NDFF];
__device__ __align__(16) float  g_y   [(size_t)NTOK * ND];   // holds x + y
__device__ __align__(16) float  g_src [(size_t)NTOK * ND];
__device__ __align__(16) __half g_src_h[(size_t)NTOK * ND];
__device__ __align__(16) __half g_srcc_h[(size_t)NTOK * ND];
__device__ __align__(16) __half g_src0_h[(size_t)NTOK * ND];
// fp16 weights
__device__ __align__(16) __half g_wsp_h[(size_t)NL * ND * ND];
__device__ __align__(16) __half g_wtp_h[(size_t)NL * ND * ND];
__device__ __align__(16) __half g_wag_h[(size_t)NL * ND * ND];
__device__ __align__(16) __half g_wl1_h[(size_t)NL * NDFF * ND];
__device__ __align__(16) __half g_wl2_h[(size_t)NL * ND * NDFF];

// ---------------------------------------------------------------------------
// PTX helpers (baseline sm_80+ instructions only)
// ---------------------------------------------------------------------------
__device__ __forceinline__ uint32_t smem_u32(const void* p) {
    uint32_t a;
    asm("{ .reg .u64 t; cvta.to.shared.u64 t, %1; cvt.u32.u64 %0, t; }"
        : "=r"(a) : "l"(p));
    return a;
}
__device__ __forceinline__ void cp_async16(uint32_t dst, const void* src) {
    asm volatile("cp.async.cg.shared.global [%0], [%1], 16;" :: "r"(dst), "l"(src));
}
#define CP_COMMIT() asm volatile("cp.async.commit_group;" ::: "memory")
#define CP_WAIT1()  asm volatile("cp.async.wait_group 1;" ::: "memory")

__device__ __forceinline__ void ldsm_x4(uint32_t* r, uint32_t addr) {
    asm volatile("ldmatrix.sync.aligned.m8n8.x4.shared.b16 {%0,%1,%2,%3}, [%4];"
                 : "=r"(r[0]), "=r"(r[1]), "=r"(r[2]), "=r"(r[3]) : "r"(addr));
}
__device__ __forceinline__ void mma16816(float* d, const uint32_t* a,
                                         uint32_t b0, uint32_t b1) {
    asm volatile(
        "mma.sync.aligned.m16n8k16.row.col.f32.f16.f16.f32 "
        "{%0,%1,%2,%3}, {%4,%5,%6,%7}, {%8,%9}, {%0,%1,%2,%3};"
        : "+f"(d[0]), "+f"(d[1]), "+f"(d[2]), "+f"(d[3])
        : "r"(a[0]), "r"(a[1]), "r"(a[2]), "r"(a[3]), "r"(b0), "r"(b1));
}

// ---------------------------------------------------------------------------
// cooperative stage loader (128 threads): A + B tile [128 x 64h], swizzled
// ---------------------------------------------------------------------------
__device__ __forceinline__ void load_stage(const __half* __restrict__ Ag,
                                           const __half* __restrict__ Wg,
                                           int K, uint32_t abase, uint32_t bbase,
                                           int tid) {
    #pragma unroll
    for (int it = 0; it < 8; it++) {
        int q = tid + it * 128;        // 0..1023 16B chunks per operand
        int r = q >> 3;                // row 0..127
        int c = q & 7;                 // logical 16B chunk in row
        uint32_t off = (uint32_t)(r * 128 + ((c ^ (r & 7)) << 4));
        cp_async16(abase + off, Ag + (size_t)r * K + c * 8);
        cp_async16(bbase + off, Wg + (size_t)r * K + c * 8);
    }
    CP_COMMIT();
}

// fragment loader: one k16 slice for this warp (64x64 warp tile)
__device__ __forceinline__ void load_frags(uint32_t aB, uint32_t bB, int ks,
                                           int arow, int brow, int axor, int bxor,
                                           int csel,
                                           uint32_t af[4][4], uint32_t bf[4][4]) {
    #pragma unroll
    for (int mt = 0; mt < 4; mt++) {
        uint32_t addr = aB + (uint32_t)((arow + mt * 16) * 128)
                      + (uint32_t)((((ks << 1) + csel) ^ axor) << 4);
        ldsm_x4(af[mt], addr);
    }
    #pragma unroll
    for (int np = 0; np < 4; np++) {
        uint32_t addr = bB + (uint32_t)((brow + np * 16) * 128)
                      + (uint32_t)((((ks << 1) + csel) ^ bxor) << 4);
        ldsm_x4(bf[np], addr);
    }
}

// ---------------------------------------------------------------------------
// fp16 tensor-core GEMM: C[M,N] = A[M,K]@W[N,K]^T + bias (+residual), opt relu.
// ADDMODE: 0 none
//          2 fp32 residual, transposed rows [(m%TT)*NB+(m/TT)]
//          3 fp16 residual, same layout as C
// grid (N/128, M/128), 128 threads (4 warps, 2x2, warp tile 64x64).
// ---------------------------------------------------------------------------
template <int RELU, int OUTH, int ADDMODE>
__global__ __launch_bounds__(128)
void tc_gemm(const __half* __restrict__ A, const __half* __restrict__ W,
             const float* __restrict__ bias, float* __restrict__ Cf,
             __half* __restrict__ Ch, const void* __restrict__ Res,
             int K, int N) {
    __shared__ float s_bias[BN];
    extern __shared__ __align__(1024) char dynsmem[];
    const uint32_t dynbase = smem_u32(dynsmem);

    const int tid = threadIdx.x;
    const int wid = tid >> 5, lid = tid & 31;
    const int wm_ = wid >> 1, wn_ = wid & 1;   // 2 x 2 warp grid
    const int m0 = blockIdx.y * BM, n0 = blockIdx.x * BN;

    s_bias[tid] = bias[n0 + tid];

    const __half* Abase = A + (size_t)m0 * K;
    const __half* Wbase = W + (size_t)n0 * K;
    const int NCH = K / BKH;

    // per-lane ldmatrix geometry
    const int sub = lid >> 3, wi = lid & 7;
    const int csel = sub >> 1;                       // 0/1 -> k halves 0/8
    const int arow = wm_ * 64 + (sub & 1) * 8 + wi;  // + mt*16
    const int brow = wn_ * 64 + (sub & 1) * 8 + wi;  // + np*16
    const int axor = arow & 7, bxor = brow & 7;      // invariant under +16

    // prologue: stages 0..1
    #pragma unroll
    for (int c = 0; c < NSTAGE - 1; c++)
        load_stage(Abase + c * BKH, Wbase + c * BKH, K,
                   dynbase + c * STAGE_BYTES,
                   dynbase + c * STAGE_BYTES + A_BYTES, tid);

    float acc[4][8][4] = {};
    uint32_t afr[2][4][4], bfr[2][4][4];

    int stage = 0;
    for (int i = 0; i < NCH; i++) {
        CP_WAIT1();              // stage for chunk i resident (<=1 pending)
        __syncthreads();         // all warps done reading the slot being refilled
        int j = i + NSTAGE - 1;
        int sj = stage + NSTAGE - 1; if (sj >= NSTAGE) sj -= NSTAGE;
        if (j < NCH) {
            load_stage(Abase + j * BKH, Wbase + j * BKH, K,
                       dynbase + sj * STAGE_BYTES,
                       dynbase + sj * STAGE_BYTES + A_BYTES, tid);
        } else {
            CP_COMMIT();         // keep group accounting uniform
        }

        const uint32_t aB = dynbase + stage * STAGE_BYTES;
        const uint32_t bB = aB + A_BYTES;

        load_frags(aB, bB, 0, arow, brow, axor, bxor, csel, afr[0], bfr[0]);
        #pragma unroll
        for (int ks = 0; ks < 4; ks++) {
            int cur = ks & 1;
            if (ks < 3)
                load_frags(aB, bB, ks + 1, arow, brow, axor, bxor, csel,
                           afr[cur ^ 1], bfr[cur ^ 1]);
            #pragma unroll
            for (int mt = 0; mt < 4; mt++)
                #pragma unroll
                for (int nt = 0; nt < 8; nt++)
                    mma16816(acc[mt][nt], afr[cur][mt],
                             bfr[cur][nt >> 1][nt & 1],
                             bfr[cur][nt >> 1][(nt & 1) + 2]);
        }
        if (++stage == NSTAGE) stage = 0;
    }

    // epilogue: direct stores (+ optional residual)
    #pragma unroll
    for (int mt = 0; mt < 4; mt++) {
        int row = m0 + wm_ * 64 + mt * 16 + (lid >> 2);
        size_t rb0 = 0, rb1 = 0;
        if (ADDMODE == 3) {
            rb0 = (size_t)row * N;
            rb1 = (size_t)(row + 8) * N;
        } else if (ADDMODE == 2) {
            int b0_ = row >> 7, t0_ = row & 127;          // TT = 128
            int b1_ = (row + 8) >> 7, t1_ = (row + 8) & 127;
            rb0 = ((size_t)(t0_ * NB + b0_)) * ND;
            rb1 = ((size_t)(t1_ * NB + b1_)) * ND;
        }
        #pragma unroll
        for (int nt = 0; nt < 8; nt++) {
            int coll = wn_ * 64 + nt * 8 + (lid & 3) * 2;
            int col = n0 + coll;
            float bx = s_bias[coll], by = s_bias[coll + 1];
            float v0 = acc[mt][nt][0] + bx, v1 = acc[mt][nt][1] + by;
            float v2 = acc[mt][nt][2] + bx, v3 = acc[mt][nt][3] + by;
            if (ADDMODE == 2) {
                const float* Rf = (const float*)Res;
                float2 r0 = *(const float2*)(Rf + rb0 + col);
                float2 r1 = *(const float2*)(Rf + rb1 + col);
                v0 += r0.x; v1 += r0.y; v2 += r1.x; v3 += r1.y;
            } else if (ADDMODE == 3) {
                const __half* Rh = (const __half*)Res;
                float2 r0 = __half22float2(*(const __half2*)(Rh + rb0 + col));
                float2 r1 = __half22float2(*(const __half2*)(Rh + rb1 + col));
                v0 += r0.x; v1 += r0.y; v2 += r1.x; v3 += r1.y;
            }
            if (RELU) {
                v0 = fmaxf(v0, 0.f); v1 = fmaxf(v1, 0.f);
                v2 = fmaxf(v2, 0.f); v3 = fmaxf(v3, 0.f);
            }
            if (OUTH) {
                *(__half2*)(Ch + (size_t)row * N + col)       = __floats2half2_rn(v0, v1);
                *(__half2*)(Ch + (size_t)(row + 8) * N + col) = __floats2half2_rn(v2, v3);
            } else {
                *(float2*)(Cf + (size_t)row * N + col)       = make_float2(v0, v1);
                *(float2*)(Cf + (size_t)(row + 8) * N + col) = make_float2(v2, v3);
            }
        }
    }
}

// ---------------------------------------------------------------------------
// f32 -> f16 conversion (float4 -> half2x2)
// ---------------------------------------------------------------------------
__global__ __launch_bounds__(256)
void f32_to_f16_kernel(const float4* __restrict__ in, __half2* __restrict__ out, int n4) {
    for (int i = blockIdx.x * 256 + threadIdx.x; i < n4; i += gridDim.x * 256) {
        float4 v = in[i];
        out[2 * i]     = __floats2half2_rn(v.x, v.y);
        out[2 * i + 1] = __floats2half2_rn(v.z, v.w);
    }
}

// ---------------------------------------------------------------------------
// Block reductions (256 threads) — used by softmax only
// ---------------------------------------------------------------------------
__device__ __forceinline__ float block_reduce_sum256(float v) {
    __shared__ float sh[8];
    int lane = threadIdx.x & 31, wid = threadIdx.x >> 5;
    #pragma unroll
    for (int o = 16; o; o >>= 1) v += __shfl_xor_sync(0xffffffffu, v, o);
    if (lane == 0) sh[wid] = v;
    __syncthreads();
    float r = (lane < 8) ? sh[lane] : 0.0f;
    #pragma unroll
    for (int o = 4; o; o >>= 1) r += __shfl_xor_sync(0xffffffffu, r, o);
    r = __shfl_sync(0xffffffffu, r, 0);
    __syncthreads();
    return r;
}
__device__ __forceinline__ float block_reduce_max256(float v) {
    __shared__ float sh[8];
    int lane = threadIdx.x & 31, wid = threadIdx.x >> 5;
    #pragma unroll
    for (int o = 16; o; o >>= 1) v = fmaxf(v, __shfl_xor_sync(0xffffffffu, v, o));
    if (lane == 0) sh[wid] = v;
    __syncthreads();
    float r = (lane < 8) ? sh[lane] : -3.4e38f;
    #pragma unroll
    for (int o = 4; o; o >>= 1) r = fmaxf(r, __shfl_xor_sync(0xffffffffu, r, o));
    r = __shfl_sync(0xffffffffu, r, 0);
    __syncthreads();
    return r;
}

// ---------------------------------------------------------------------------
// scores: one warp per token. s,t fp16.
// scores[h][t][b] = dot(s, aw[h][:64]) + dot(t, aw[h][64:]) + ab[h]
// ---------------------------------------------------------------------------
__global__ __launch_bounds__(256)
void fuse_st_kernel(const float* __restrict__ aw, const float* __restrict__ ab) {
    __shared__ float aw_s[NH * 2 * NSUB];   // 1024 floats
    __shared__ float ab_s[NH];

    const int tid = threadIdx.x;
    for (int i = tid; i < NH * 2 * NSUB; i += 256) aw_s[i] = aw[i];
    if (tid < NH) ab_s[tid] = ab[tid];
    __syncthreads();

    const int w = blockIdx.x * 8 + (tid >> 5);      // token index (t*NB+b)
    const int l = tid & 31;
    const int t = w / NB, b = w % NB;
    const size_t base = (size_t)w * ND;
    const int hi = l >> 4;                          // 0 or 1

    float part[4];
    #pragma unroll
    for (int k = 0; k < 4; k++) {
        int idx = k * 128 + l * 4;                  // 4 halves = 8 bytes
        int h = idx >> 6;                           // = 2k + hi
        int u = idx & 63;
        uint2 sraw = *(const uint2*)(g_s_h + base + idx);
        uint2 traw = *(const uint2*)(g_t_h + base + idx);
        __half2 s0 = *(__half2*)&sraw.x, s1 = *(__half2*)&sraw.y;
        __half2 t0 = *(__half2*)&traw.x, t1 = *(__half2*)&traw.y;
        float2 s0f = __half22float2(s0), s1f = __half22float2(s1);
        float2 t0f = __half22float2(t0), t1f = __half22float2(t1);
        const float* as = aw_s + h * 128 + u;       // s part
        const float* at = as + 64;                  // t part
        part[k] = s0f.x * as[0] + s0f.y * as[1] + s1f.x * as[2] + s1f.y * as[3]
                + t0f.x * at[0] + t0f.y * at[1] + t1f.x * at[2] + t1f.y * at[3];
    }
    // reduce within each 16-lane half (heads differ between halves)
    #pragma unroll
    for (int o = 1; o < 16; o <<= 1) {
        #pragma unroll
        for (int k = 0; k < 4; k++)
            part[k] += __shfl_xor_sync(0xffffffffu, part[k], o);
    }
    if ((l & 15) == 0) {
        #pragma unroll
        for (int k = 0; k < 4; k++) {
            int h = 2 * k + hi;
            g_scores[(h * TT + t) * NB + b] = part[k] + ab_s[h];
        }
    }
}

// softmax over b (axis=1 of [H,B,T])
__global__ __launch_bounds__(256)
void softmax_kernel() {
    int ht = blockIdx.x;
    float v = g_scores[(size_t)ht * NB + threadIdx.x];
    float m = block_reduce_max256(v);
    float e = __expf(v - m);
    float s = block_reduce_sum256(e);
    g_wts[(size_t)ht * NB + threadIdx.x] = e / s;
}

// per-head message mini-GEMM, reads s_h/t_h directly (product on load, fp32)
__global__ __launch_bounds__(256)
void msg_kernel(const float* __restrict__ mw, const float* __restrict__ mb) {
    __shared__ float prod[64][65];
    __shared__ float mws [64][65];
    __shared__ float wt_s[64];
    __shared__ float mb_s[64];

    const int h  = blockIdx.y;
    const int p0 = blockIdx.x * 64;
    const int tid = threadIdx.x;

    for (int i = tid; i < 64 * 64; i += 256) {
        int u = i >> 6, s = i & 63;
        mws[s][u] = mw[((size_t)h * 64 + u) * 64 + s];
    }
    if (tid < 64) {
        mb_s[tid] = mb[h * 64 + tid];
        int p = p0 + tid, b = p / TT, t = p % TT;
        wt_s[tid] = g_wts[(h * TT + t) * NB + b];
    }
    for (int i = tid; i < 64 * 16; i += 256) {      // uint2 = 4 halves
        int tok = i >> 4, u4 = i & 15;
        int p = p0 + tok, b = p / TT, t = p % TT;
        size_t idx = ((size_t)(t * NB + b)) * ND + h * NSUB + u4 * 4;
        uint2 sraw = *(const uint2*)(g_s_h + idx);
        uint2 traw = *(const uint2*)(g_t_h + idx);
        float2 s0 = __half22float2(*(__half2*)&sraw.x);
        float2 s1 = __half22float2(*(__half2*)&sraw.y);
        float2 t0 = __half22float2(*(__half2*)&traw.x);
        float2 t1 = __half22float2(*(__half2*)&traw.y);
        prod[tok][u4 * 4]     = s0.x * t0.x;
        prod[tok][u4 * 4 + 1] = s0.y * t0.y;
        prod[tok][u4 * 4 + 2] = s1.x * t1.x;
        prod[tok][u4 * 4 + 3] = s1.y * t1.y;
    }
    __syncthreads();

    const int tx = tid & 15, ty = tid >> 4;
    float acc[4][4] = {};
    #pragma unroll 4
    for (int s = 0; s < 64; s++) {
        float a[4], w[4];
        #pragma unroll
        for (int i = 0; i < 4; i++) a[i] = prod[ty * 4 + i][s];
        #pragma unroll
        for (int j = 0; j < 4; j++) w[j] = mws[s][tx * 4 + j];
        #pragma unroll
        for (int i = 0; i < 4; i++)
            #pragma unroll
            for (int j = 0; j < 4; j++)
                acc[i][j] += a[i] * w[j];
    }
    #pragma unroll
    for (int i = 0; i < 4; i++) {
        int tok = ty * 4 + i;
        float wt = wt_s[tok];
        #pragma unroll
        for (int j = 0; j < 4; j++) {
            int u = tx * 4 + j;
            float v = wt * (acc[i][j] + mb_s[u]);
            g_wm_h[((size_t)(p0 + tok)) * ND + h * NSUB + u] =
                __float2half_rn(fmaxf(v, 0.f));
        }
    }
}

// ---------------------------------------------------------------------------
// Warp-per-token LayerNorms (no block barriers). 8 warps/block.
// ---------------------------------------------------------------------------
// LN1: input g_agg (already src^T + agg) rows (b*TT+t); writes g_x_h fp16 only.
__global__ __launch_bounds__(256)
void ln1_kernel(const float* __restrict__ gam, const float* __restrict__ bet) {
    const int tok = blockIdx.x * 8 + (threadIdx.x >> 5);
    const int l = threadIdx.x & 31;
    const float4* a = (const float4*)(g_agg + (size_t)tok * ND);
    float4 v[4];
    float s = 0.f;
    #pragma unroll
    for (int k = 0; k < 4; k++) {
        v[k] = a[l + 32 * k];
        s += (v[k].x + v[k].y) + (v[k].z + v[k].w);
    }
    #pragma unroll
    for (int o = 16; o; o >>= 1) s += __shfl_xor_sync(0xffffffffu, s, o);
    const float mean = s * (1.0f / ND);
    float q = 0.f;
    #pragma unroll
    for (int k = 0; k < 4; k++) {
        v[k].x -= mean; v[k].y -= mean; v[k].z -= mean; v[k].w -= mean;
        q += (v[k].x * v[k].x + v[k].y * v[k].y) + (v[k].z * v[k].z + v[k].w * v[k].w);
    }
    #pragma unroll
    for (int o = 16; o; o >>= 1) q += __shfl_xor_sync(0xffffffffu, q, o);
    const float rstd = rsqrtf(q * (1.0f / ND) + 1e-5f);
    uint2* xr = (uint2*)(g_x_h + (size_t)tok * ND);
    #pragma unroll
    for (int k = 0; k < 4; k++) {
        int idx = l + 32 * k;
        float4 gg = *(const float4*)(gam + idx * 4);
        float4 bb = *(const float4*)(bet + idx * 4);
        __half2 h0 = __floats2half2_rn(v[k].x * rstd * gg.x + bb.x,
                                       v[k].y * rstd * gg.y + bb.y);
        __half2 h1 = __floats2half2_rn(v[k].z * rstd * gg.z + bb.z,
                                       v[k].w * rstd * gg.w + bb.w);
        uint2 u; u.x = *(uint32_t*)&h0; u.y = *(uint32_t*)&h1;
        xr[idx] = u;
    }
}

// LN2: input g_y (already x + y) rows (b*TT+t); writes out [T,B,D] fp32
// (+ fp16 copy g_src_h unless last layer)
__global__ __launch_bounds__(256)
void ln2_kernel(const float* __restrict__ gam, const float* __restrict__ bet,
                float* __restrict__ out, int write_h) {
    const int p = blockIdx.x * 8 + (threadIdx.x >> 5);
    const int l = threadIdx.x & 31;
    const int b = p >> 7, t = p & 127;          // p = b*TT + t, TT=128
    const float4* a = (const float4*)(g_y + (size_t)p * ND);
    float4 v[4];
    float s = 0.f;
    #pragma unroll
    for (int k = 0; k < 4; k++) {
        v[k] = a[l + 32 * k];
        s += (v[k].x + v[k].y) + (v[k].z + v[k].w);
    }
    #pragma unroll
    for (int o = 16; o; o >>= 1) s += __shfl_xor_sync(0xffffffffu, s, o);
    const float mean = s * (1.0f / ND);
    float q = 0.f;
    #pragma unroll
    for (int k = 0; k < 4; k++) {
        v[k].x -= mean; v[k].y -= mean; v[k].z -= mean; v[k].w -= mean;
        q += (v[k].x * v[k].x + v[k].y * v[k].y) + (v[k].z * v[k].z + v[k].w * v[k].w);
    }
    #pragma unroll
    for (int o = 16; o; o >>= 1) q += __shfl_xor_sync(0xffffffffu, q, o);
    const float rstd = rsqrtf(q * (1.0f / ND) + 1e-5f);
    const size_t obase = ((size_t)(t * NB + b)) * ND;
    float4* orow = (float4*)(out + obase);
    uint2*  hrow = (uint2*)(g_src_h + obase);
    #pragma unroll
    for (int k = 0; k < 4; k++) {
        int idx = l + 32 * k;
        float4 gg = *(const float4*)(gam + idx * 4);
        float4 bb = *(const float4*)(bet + idx * 4);
        float4 o4;
        o4.x = v[k].x * rstd * gg.x + bb.x;
        o4.y = v[k].y * rstd * gg.y + bb.y;
        o4.z = v[k].z * rstd * gg.z + bb.z;
        o4.w = v[k].w * rstd * gg.w + bb.w;
        orow[idx] = o4;
        if (write_h) {
            __half2 h0 = __floats2half2_rn(o4.x, o4.y);
            __half2 h1 = __floats2half2_rn(o4.z, o4.w);
            uint2 u; u.x = *(uint32_t*)&h0; u.y = *(uint32_t*)&h1;
            hrow[idx] = u;
        }
    }
}

// ---------------------------------------------------------------------------
extern "C" void kernel_launch(void* const* d_in, const int* in_sizes, int n_in,
                              void* d_out, int out_size) {
    const float* in_src  = (const float*)d_in[0];
    const float* in_srcc = (const float*)d_in[1];
    const float* w_sp = (const float*)d_in[2];
    const float* b_sp = (const float*)d_in[3];
    const float* w_tp = (const float*)d_in[4];
    const float* b_tp = (const float*)d_in[5];
    const float* w_at = (const float*)d_in[6];
    const float* b_at = (const float*)d_in[7];
    const float* w_mg = (const float*)d_in[8];
    const float* b_mg = (const float*)d_in[9];
    const float* w_ag = (const float*)d_in[10];
    const float* b_ag = (const float*)d_in[11];
    const float* w_l1 = (const float*)d_in[12];
    const float* b_l1 = (const float*)d_in[13];
    const float* w_l2 = (const float*)d_in[14];
    const float* b_l2 = (const float*)d_in[15];
    const float* g_n1 = (const float*)d_in[16];
    const float* bb_n1 = (const float*)d_in[17];
    const float* g_n2 = (const float*)d_in[18];
    const float* bb_n2 = (const float*)d_in[19];

    float *p_agg, *p_y, *p_src;
    __half *p_s_h, *p_t_h, *p_wm_h, *p_x_h, *p_h1_h, *p_src_h, *p_srcc_h, *p_src0_h;
    __half *p_wsp, *p_wtp, *p_wag, *p_wl1, *p_wl2;
    cudaGetSymbolAddress((void**)&p_s_h,    g_s_h);
    cudaGetSymbolAddress((void**)&p_t_h,    g_t_h);
    cudaGetSymbolAddress((void**)&p_agg,    g_agg);
    cudaGetSymbolAddress((void**)&p_y,      g_y);
    cudaGetSymbolAddress((void**)&p_src,    g_src);
    cudaGetSymbolAddress((void**)&p_wm_h,   g_wm_h);
    cudaGetSymbolAddress((void**)&p_x_h,    g_x_h);
    cudaGetSymbolAddress((void**)&p_h1_h,   g_h1_h);
    cudaGetSymbolAddress((void**)&p_src_h,  g_src_h);
    cudaGetSymbolAddress((void**)&p_srcc_h, g_srcc_h);
    cudaGetSymbolAddress((void**)&p_src0_h, g_src0_h);
    cudaGetSymbolAddress((void**)&p_wsp,    g_wsp_h);
    cudaGetSymbolAddress((void**)&p_wtp,    g_wtp_h);
    cudaGetSymbolAddress((void**)&p_wag,    g_wag_h);
    cudaGetSymbolAddress((void**)&p_wl1,    g_wl1_h);
    cudaGetSymbolAddress((void**)&p_wl2,    g_wl2_h);

    cudaFuncSetAttribute(tc_gemm<1, 1, 0>, cudaFuncAttributeMaxDynamicSharedMemorySize, DYN_SMEM);
    cudaFuncSetAttribute(tc_gemm<0, 0, 2>, cudaFuncAttributeMaxDynamicSharedMemorySize, DYN_SMEM);
    cudaFuncSetAttribute(tc_gemm<0, 0, 3>, cudaFuncAttributeMaxDynamicSharedMemorySize, DYN_SMEM);

    // one-time fp16 conversions
    f32_to_f16_kernel<<<2048, 256>>>((const float4*)in_srcc, (__half2*)p_srcc_h, NTOK * ND / 4);
    f32_to_f16_kernel<<<2048, 256>>>((const float4*)in_src,  (__half2*)p_src0_h, NTOK * ND / 4);
    f32_to_f16_kernel<<<2048, 256>>>((const float4*)w_sp, (__half2*)p_wsp, NL * ND * ND / 4);
    f32_to_f16_kernel<<<2048, 256>>>((const float4*)w_tp, (__half2*)p_wtp, NL * ND * ND / 4);
    f32_to_f16_kernel<<<2048, 256>>>((const float4*)w_ag, (__half2*)p_wag, NL * ND * ND / 4);
    f32_to_f16_kernel<<<2048, 256>>>((const float4*)w_l1, (__half2*)p_wl1, NL * NDFF * ND / 4);
    f32_to_f16_kernel<<<2048, 256>>>((const float4*)w_l2, (__half2*)p_wl2, NL * ND * NDFF / 4);

    for (int l = 0; l < NL; l++) {
        const __half* srcA   = (l == 0) ? p_src0_h : p_src_h;
        const float*  srcRes = (l == 0) ? in_src   : p_src;

        // s = relu(srcc @ sw^T + sb)  [fp16 out]
        tc_gemm<1, 1, 0><<<dim3(ND / BN, NTOK / BM), 128, DYN_SMEM>>>(
            p_srcc_h, p_wsp + (size_t)l * ND * ND, b_sp + l * ND, nullptr, p_s_h, nullptr, ND, ND);
        // t = relu(src @ tw^T + tb)  [fp16 out]
        tc_gemm<1, 1, 0><<<dim3(ND / BN, NTOK / BM), 128, DYN_SMEM>>>(
            srcA, p_wtp + (size_t)l * ND * ND, b_tp + l * ND, nullptr, p_t_h, nullptr, ND, ND);
        // scores + softmax over batch
        fuse_st_kernel<<<NTOK / 8, 256>>>(w_at + (size_t)l * NH * 2 * NSUB, b_at + l * NH);
        softmax_kernel<<<NH * TT, NB>>>();
        // weighted message -> relu(wm) [B,T,D] fp16
        msg_kernel<<<dim3(NTOK / 64, NH), 256>>>(w_mg + (size_t)l * NH * NSUB * NSUB,
                                                 b_mg + l * NH * NSUB);
        // agg = wm @ gw^T + gb + src^T  [fp32 out, fp32 residual fused]
        tc_gemm<0, 0, 2><<<dim3(ND / BN, NTOK / BM), 128, DYN_SMEM>>>(
            p_wm_h, p_wag + (size_t)l * ND * ND, b_ag + l * ND, p_agg, nullptr, srcRes, ND, ND);
        // x = LN(agg')  [fp16 only]
        ln1_kernel<<<NTOK / 8, 256>>>(g_n1 + l * ND, bb_n1 + l * ND);
        // h1 = relu(x @ w1^T + b1)  [fp16 out]
        tc_gemm<1, 1, 0><<<dim3(NDFF / BN, NTOK / BM), 128, DYN_SMEM>>>(
            p_x_h, p_wl1 + (size_t)l * NDFF * ND, b_l1 + l * NDFF, nullptr, p_h1_h, nullptr, ND, NDFF);
        // y = h1 @ w2^T + b2 + x(fp16)  [fp32 out, fp16 residual fused]
        tc_gemm<0, 0, 3><<<dim3(ND / BN, NTOK / BM), 128, DYN_SMEM>>>(
            p_h1_h, p_wl2 + (size_t)l * ND * NDFF, b_l2 + l * ND, p_y, nullptr, p_x_h, NDFF, ND);
        // out = LN(y') -> [T,B,D]
        float* dst = (l == NL - 1) ? (float*)d_out : p_src;
        ln2_kernel<<<NTOK / 8, 256>>>(g_n2 + l * ND, bb_n2 + l * ND, dst, (l == NL - 1) ? 0 : 1);
    }
}

// round 7
// speedup vs baseline: 6.6424x; 1.0229x over previous
#include <cuda_runtime.h>
#include <cuda_fp16.h>
#include <cstdint>
#include <cstddef>

// Problem dims
#define NL   6
#define TT   128
#define NB   256
#define ND   512
#define NH   8
#define NDFF 2048
#define NSUB 64
#define NTOK (TT * NB)   // 32768 tokens

// mma.sync GEMM tile config (fp16 in, fp32 accum)
// CTA tile 128x128x64, 4 warps (2x2), warp tile 64x64, 3-stage cp.async
#define BM 128
#define BN 128
#define BKH 64                         // 64 halves = 128B row
#define NSTAGE 3
#define A_BYTES (BM * BKH * 2)         // 16384
#define STAGE_BYTES (2 * A_BYTES)      // 32768
#define DYN_SMEM (NSTAGE * STAGE_BYTES)  // 98304

// ---------------------------------------------------------------------------
// Scratch (__device__ globals; no allocation allowed)
// ---------------------------------------------------------------------------
__device__ __align__(16) __half g_s_h [(size_t)NTOK * ND];
__device__ __align__(16) __half g_t_h [(size_t)NTOK * ND];
__device__ __align__(16) float  g_scores[NH * TT * NB];
__device__ __align__(16) float  g_wts   [NH * TT * NB];
__device__ __align__(16) __half g_wm_h[(size_t)NTOK * ND];
__device__ __align__(16) float  g_agg [(size_t)NTOK * ND];   // holds src^T + agg
__device__ __align__(16) __half g_x_h [(size_t)NTOK * ND];
__device__ __align__(16) __half g_h1_h[(size_t)NTOK * NDFF];
__device__ __align__(16) float  g_y   [(size_t)NTOK * ND];   // holds x + y
__device__ __align__(16) __half g_src_h[(size_t)NTOK * ND];
__device__ __align__(16) __half g_srcc_h[(size_t)NTOK * ND];
__device__ __align__(16) __half g_src0_h[(size_t)NTOK * ND];
// fp16 weights
__device__ __align__(16) __half g_wsp_h[(size_t)NL * ND * ND];
__device__ __align__(16) __half g_wtp_h[(size_t)NL * ND * ND];
__device__ __align__(16) __half g_wag_h[(size_t)NL * ND * ND];
__device__ __align__(16) __half g_wl1_h[(size_t)NL * NDFF * ND];
__device__ __align__(16) __half g_wl2_h[(size_t)NL * ND * NDFF];

// ---------------------------------------------------------------------------
// PTX helpers (baseline sm_80+ instructions only)
// ---------------------------------------------------------------------------
__device__ __forceinline__ uint32_t smem_u32(const void* p) {
    uint32_t a;
    asm("{ .reg .u64 t; cvta.to.shared.u64 t, %1; cvt.u32.u64 %0, t; }"
        : "=r"(a) : "l"(p));
    return a;
}
__device__ __forceinline__ void cp_async16(uint32_t dst, const void* src) {
    asm volatile("cp.async.cg.shared.global [%0], [%1], 16;" :: "r"(dst), "l"(src));
}
#define CP_COMMIT() asm volatile("cp.async.commit_group;" ::: "memory")
#define CP_WAIT1()  asm volatile("cp.async.wait_group 1;" ::: "memory")

__device__ __forceinline__ void ldsm_x4(uint32_t* r, uint32_t addr) {
    asm volatile("ldmatrix.sync.aligned.m8n8.x4.shared.b16 {%0,%1,%2,%3}, [%4];"
                 : "=r"(r[0]), "=r"(r[1]), "=r"(r[2]), "=r"(r[3]) : "r"(addr));
}
__device__ __forceinline__ void mma16816(float* d, const uint32_t* a,
                                         uint32_t b0, uint32_t b1) {
    asm volatile(
        "mma.sync.aligned.m16n8k16.row.col.f32.f16.f16.f32 "
        "{%0,%1,%2,%3}, {%4,%5,%6,%7}, {%8,%9}, {%0,%1,%2,%3};"
        : "+f"(d[0]), "+f"(d[1]), "+f"(d[2]), "+f"(d[3])
        : "r"(a[0]), "r"(a[1]), "r"(a[2]), "r"(a[3]), "r"(b0), "r"(b1));
}

// ---------------------------------------------------------------------------
// cooperative stage loader (128 threads): A + B tile [128 x 64h], swizzled
// ---------------------------------------------------------------------------
__device__ __forceinline__ void load_stage(const __half* __restrict__ Ag,
                                           const __half* __restrict__ Wg,
                                           int K, uint32_t abase, uint32_t bbase,
                                           int tid) {
    #pragma unroll
    for (int it = 0; it < 8; it++) {
        int q = tid + it * 128;        // 0..1023 16B chunks per operand
        int r = q >> 3;                // row 0..127
        int c = q & 7;                 // logical 16B chunk in row
        uint32_t off = (uint32_t)(r * 128 + ((c ^ (r & 7)) << 4));
        cp_async16(abase + off, Ag + (size_t)r * K + c * 8);
        cp_async16(bbase + off, Wg + (size_t)r * K + c * 8);
    }
    CP_COMMIT();
}

// fragment loader: one k16 slice for this warp (64x64 warp tile)
__device__ __forceinline__ void load_frags(uint32_t aB, uint32_t bB, int ks,
                                           int arow, int brow, int axor, int bxor,
                                           int csel,
                                           uint32_t af[4][4], uint32_t bf[4][4]) {
    #pragma unroll
    for (int mt = 0; mt < 4; mt++) {
        uint32_t addr = aB + (uint32_t)((arow + mt * 16) * 128)
                      + (uint32_t)((((ks << 1) + csel) ^ axor) << 4);
        ldsm_x4(af[mt], addr);
    }
    #pragma unroll
    for (int np = 0; np < 4; np++) {
        uint32_t addr = bB + (uint32_t)((brow + np * 16) * 128)
                      + (uint32_t)((((ks << 1) + csel) ^ bxor) << 4);
        ldsm_x4(bf[np], addr);
    }
}

// ---------------------------------------------------------------------------
// fp16 tensor-core GEMM: C[M,N] = A[M,K]@W[N,K]^T + bias (+residual), opt relu.
// ADDMODE: 0 none
//          2 fp32 residual, transposed rows [(m%TT)*NB+(m/TT)]
//          3 fp16 residual, same layout as C
//          4 fp16 residual, transposed rows
// SCORE:   0 none; 1 store s-part scores; 2 atomicAdd t-part scores.
//          (requires N=512, rows are tokens t*NB+b; aw = attn weights [H,128])
// grid (N/128, M/128), 128 threads (4 warps, 2x2, warp tile 64x64).
// ---------------------------------------------------------------------------
template <int RELU, int OUTH, int ADDMODE, int SCORE>
__global__ __launch_bounds__(128)
void tc_gemm(const __half* __restrict__ A, const __half* __restrict__ W,
             const float* __restrict__ bias, float* __restrict__ Cf,
             __half* __restrict__ Ch, const void* __restrict__ Res,
             const float* __restrict__ aw, int K, int N) {
    __shared__ float s_bias[BN];
    extern __shared__ __align__(1024) char dynsmem[];
    const uint32_t dynbase = smem_u32(dynsmem);

    const int tid = threadIdx.x;
    const int wid = tid >> 5, lid = tid & 31;
    const int wm_ = wid >> 1, wn_ = wid & 1;   // 2 x 2 warp grid
    const int m0 = blockIdx.y * BM, n0 = blockIdx.x * BN;

    s_bias[tid] = bias[n0 + tid];

    const __half* Abase = A + (size_t)m0 * K;
    const __half* Wbase = W + (size_t)n0 * K;
    const int NCH = K / BKH;

    // per-lane ldmatrix geometry
    const int sub = lid >> 3, wi = lid & 7;
    const int csel = sub >> 1;                       // 0/1 -> k halves 0/8
    const int arow = wm_ * 64 + (sub & 1) * 8 + wi;  // + mt*16
    const int brow = wn_ * 64 + (sub & 1) * 8 + wi;  // + np*16
    const int axor = arow & 7, bxor = brow & 7;      // invariant under +16

    // prologue: stages 0..1
    #pragma unroll
    for (int c = 0; c < NSTAGE - 1; c++)
        load_stage(Abase + c * BKH, Wbase + c * BKH, K,
                   dynbase + c * STAGE_BYTES,
                   dynbase + c * STAGE_BYTES + A_BYTES, tid);

    float acc[4][8][4] = {};
    uint32_t afr[2][4][4], bfr[2][4][4];

    int stage = 0;
    for (int i = 0; i < NCH; i++) {
        CP_WAIT1();              // stage for chunk i resident (<=1 pending)
        __syncthreads();         // all warps done reading the slot being refilled
        int j = i + NSTAGE - 1;
        int sj = stage + NSTAGE - 1; if (sj >= NSTAGE) sj -= NSTAGE;
        if (j < NCH) {
            load_stage(Abase + j * BKH, Wbase + j * BKH, K,
                       dynbase + sj * STAGE_BYTES,
                       dynbase + sj * STAGE_BYTES + A_BYTES, tid);
        } else {
            CP_COMMIT();         // keep group accounting uniform
        }

        const uint32_t aB = dynbase + stage * STAGE_BYTES;
        const uint32_t bB = aB + A_BYTES;

        load_frags(aB, bB, 0, arow, brow, axor, bxor, csel, afr[0], bfr[0]);
        #pragma unroll
        for (int ks = 0; ks < 4; ks++) {
            int cur = ks & 1;
            if (ks < 3)
                load_frags(aB, bB, ks + 1, arow, brow, axor, bxor, csel,
                           afr[cur ^ 1], bfr[cur ^ 1]);
            #pragma unroll
            for (int mt = 0; mt < 4; mt++)
                #pragma unroll
                for (int nt = 0; nt < 8; nt++)
                    mma16816(acc[mt][nt], afr[cur][mt],
                             bfr[cur][nt >> 1][nt & 1],
                             bfr[cur][nt >> 1][(nt & 1) + 2]);
        }
        if (++stage == NSTAGE) stage = 0;
    }

    // score weights: u = nt*8 + (lid&3)*2 (n0-invariant), head = n0/64 + wn_
    float waw[16];
    const int shead = (n0 >> 6) + wn_;
    if (SCORE) {
        const int off = (SCORE == 2) ? 64 : 0;
        #pragma unroll
        for (int nt = 0; nt < 8; nt++) {
            int u = nt * 8 + (lid & 3) * 2;
            waw[nt * 2]     = __ldg(aw + shead * 128 + off + u);
            waw[nt * 2 + 1] = __ldg(aw + shead * 128 + off + u + 1);
        }
    }

    // epilogue: direct stores (+ optional residual, + optional score partials)
    #pragma unroll
    for (int mt = 0; mt < 4; mt++) {
        int row = m0 + wm_ * 64 + mt * 16 + (lid >> 2);
        size_t rb0 = 0, rb1 = 0;
        if (ADDMODE == 3) {
            rb0 = (size_t)row * N;
            rb1 = (size_t)(row + 8) * N;
        } else if (ADDMODE == 2 || ADDMODE == 4) {
            int b0_ = row >> 7, t0_ = row & 127;          // TT = 128
            int b1_ = (row + 8) >> 7, t1_ = (row + 8) & 127;
            rb0 = ((size_t)(t0_ * NB + b0_)) * ND;
            rb1 = ((size_t)(t1_ * NB + b1_)) * ND;
        }
        float sc0 = 0.f, sc1 = 0.f;
        #pragma unroll
        for (int nt = 0; nt < 8; nt++) {
            int coll = wn_ * 64 + nt * 8 + (lid & 3) * 2;
            int col = n0 + coll;
            float bx = s_bias[coll], by = s_bias[coll + 1];
            float v0 = acc[mt][nt][0] + bx, v1 = acc[mt][nt][1] + by;
            float v2 = acc[mt][nt][2] + bx, v3 = acc[mt][nt][3] + by;
            if (ADDMODE == 2) {
                const float* Rf = (const float*)Res;
                float2 r0 = *(const float2*)(Rf + rb0 + col);
                float2 r1 = *(const float2*)(Rf + rb1 + col);
                v0 += r0.x; v1 += r0.y; v2 += r1.x; v3 += r1.y;
            } else if (ADDMODE == 3 || ADDMODE == 4) {
                const __half* Rh = (const __half*)Res;
                float2 r0 = __half22float2(*(const __half2*)(Rh + rb0 + col));
                float2 r1 = __half22float2(*(const __half2*)(Rh + rb1 + col));
                v0 += r0.x; v1 += r0.y; v2 += r1.x; v3 += r1.y;
            }
            if (RELU) {
                v0 = fmaxf(v0, 0.f); v1 = fmaxf(v1, 0.f);
                v2 = fmaxf(v2, 0.f); v3 = fmaxf(v3, 0.f);
            }
            if (SCORE) {
                sc0 += v0 * waw[nt * 2] + v1 * waw[nt * 2 + 1];
                sc1 += v2 * waw[nt * 2] + v3 * waw[nt * 2 + 1];
            }
            if (OUTH) {
                *(__half2*)(Ch + (size_t)row * N + col)       = __floats2half2_rn(v0, v1);
                *(__half2*)(Ch + (size_t)(row + 8) * N + col) = __floats2half2_rn(v2, v3);
            } else {
                *(float2*)(Cf + (size_t)row * N + col)       = make_float2(v0, v1);
                *(float2*)(Cf + (size_t)(row + 8) * N + col) = make_float2(v2, v3);
            }
        }
        if (SCORE) {
            // quad reduction: lanes lid^1, lid^2 share the same rows
            sc0 += __shfl_xor_sync(0xffffffffu, sc0, 1);
            sc0 += __shfl_xor_sync(0xffffffffu, sc0, 2);
            sc1 += __shfl_xor_sync(0xffffffffu, sc1, 1);
            sc1 += __shfl_xor_sync(0xffffffffu, sc1, 2);
            if ((lid & 3) == 0) {
                int tok0 = row, tok1 = row + 8;        // tok = t*NB + b
                int t0_ = tok0 >> 8, b0_ = tok0 & 255; // NB = 256
                int t1_ = tok1 >> 8, b1_ = tok1 & 255;
                float* sp0 = g_scores + (shead * TT + t0_) * NB + b0_;
                float* sp1 = g_scores + (shead * TT + t1_) * NB + b1_;
                if (SCORE == 1) { *sp0 = sc0; *sp1 = sc1; }
                else           { atomicAdd(sp0, sc0); atomicAdd(sp1, sc1); }
            }
        }
    }
}

// ---------------------------------------------------------------------------
// f32 -> f16 conversion (float4 -> half2x2)
// ---------------------------------------------------------------------------
__global__ __launch_bounds__(256)
void f32_to_f16_kernel(const float4* __restrict__ in, __half2* __restrict__ out, int n4) {
    for (int i = blockIdx.x * 256 + threadIdx.x; i < n4; i += gridDim.x * 256) {
        float4 v = in[i];
        out[2 * i]     = __floats2half2_rn(v.x, v.y);
        out[2 * i + 1] = __floats2half2_rn(v.z, v.w);
    }
}

// ---------------------------------------------------------------------------
// Block reductions (256 threads) — used by softmax only
// ---------------------------------------------------------------------------
__device__ __forceinline__ float block_reduce_sum256(float v) {
    __shared__ float sh[8];
    int lane = threadIdx.x & 31, wid = threadIdx.x >> 5;
    #pragma unroll
    for (int o = 16; o; o >>= 1) v += __shfl_xor_sync(0xffffffffu, v, o);
    if (lane == 0) sh[wid] = v;
    __syncthreads();
    float r = (lane < 8) ? sh[lane] : 0.0f;
    #pragma unroll
    for (int o = 4; o; o >>= 1) r += __shfl_xor_sync(0xffffffffu, r, o);
    r = __shfl_sync(0xffffffffu, r, 0);
    __syncthreads();
    return r;
}
__device__ __forceinline__ float block_reduce_max256(float v) {
    __shared__ float sh[8];
    int lane = threadIdx.x & 31, wid = threadIdx.x >> 5;
    #pragma unroll
    for (int o = 16; o; o >>= 1) v = fmaxf(v, __shfl_xor_sync(0xffffffffu, v, o));
    if (lane == 0) sh[wid] = v;
    __syncthreads();
    float r = (lane < 8) ? sh[lane] : -3.4e38f;
    #pragma unroll
    for (int o = 4; o; o >>= 1) r = fmaxf(r, __shfl_xor_sync(0xffffffffu, r, o));
    r = __shfl_sync(0xffffffffu, r, 0);
    __syncthreads();
    return r;
}

// softmax over b (axis=1 of [H,B,T]); note attn bias ab[h] is constant along b
// and cancels in softmax, so it is never added.
__global__ __launch_bounds__(256)
void softmax_kernel() {
    int ht = blockIdx.x;
    float v = g_scores[(size_t)ht * NB + threadIdx.x];
    float m = block_reduce_max256(v);
    float e = __expf(v - m);
    float s = block_reduce_sum256(e);
    g_wts[(size_t)ht * NB + threadIdx.x] = e / s;
}

// per-head message mini-GEMM, reads s_h/t_h directly (product on load, fp32)
__global__ __launch_bounds__(256)
void msg_kernel(const float* __restrict__ mw, const float* __restrict__ mb) {
    __shared__ float prod[64][65];
    __shared__ float mws [64][65];
    __shared__ float wt_s[64];
    __shared__ float mb_s[64];

    const int h  = blockIdx.y;
    const int p0 = blockIdx.x * 64;
    const int tid = threadIdx.x;

    for (int i = tid; i < 64 * 64; i += 256) {
        int u = i >> 6, s = i & 63;
        mws[s][u] = mw[((size_t)h * 64 + u) * 64 + s];
    }
    if (tid < 64) {
        mb_s[tid] = mb[h * 64 + tid];
        int p = p0 + tid, b = p / TT, t = p % TT;
        wt_s[tid] = g_wts[(h * TT + t) * NB + b];
    }
    for (int i = tid; i < 64 * 16; i += 256) {      // uint2 = 4 halves
        int tok = i >> 4, u4 = i & 15;
        int p = p0 + tok, b = p / TT, t = p % TT;
        size_t idx = ((size_t)(t * NB + b)) * ND + h * NSUB + u4 * 4;
        uint2 sraw = *(const uint2*)(g_s_h + idx);
        uint2 traw = *(const uint2*)(g_t_h + idx);
        float2 s0 = __half22float2(*(__half2*)&sraw.x);
        float2 s1 = __half22float2(*(__half2*)&sraw.y);
        float2 t0 = __half22float2(*(__half2*)&traw.x);
        float2 t1 = __half22float2(*(__half2*)&traw.y);
        prod[tok][u4 * 4]     = s0.x * t0.x;
        prod[tok][u4 * 4 + 1] = s0.y * t0.y;
        prod[tok][u4 * 4 + 2] = s1.x * t1.x;
        prod[tok][u4 * 4 + 3] = s1.y * t1.y;
    }
    __syncthreads();

    const int tx = tid & 15, ty = tid >> 4;
    float acc[4][4] = {};
    #pragma unroll 4
    for (int s = 0; s < 64; s++) {
        float a[4], w[4];
        #pragma unroll
        for (int i = 0; i < 4; i++) a[i] = prod[ty * 4 + i][s];
        #pragma unroll
        for (int j = 0; j < 4; j++) w[j] = mws[s][tx * 4 + j];
        #pragma unroll
        for (int i = 0; i < 4; i++)
            #pragma unroll
            for (int j = 0; j < 4; j++)
                acc[i][j] += a[i] * w[j];
    }
    #pragma unroll
    for (int i = 0; i < 4; i++) {
        int tok = ty * 4 + i;
        float wt = wt_s[tok];
        #pragma unroll
        for (int j = 0; j < 4; j++) {
            int u = tx * 4 + j;
            float v = wt * (acc[i][j] + mb_s[u]);
            g_wm_h[((size_t)(p0 + tok)) * ND + h * NSUB + u] =
                __float2half_rn(fmaxf(v, 0.f));
        }
    }
}

// ---------------------------------------------------------------------------
// Warp-per-token LayerNorms (no block barriers). 8 warps/block.
// ---------------------------------------------------------------------------
// LN1: input g_agg (already src^T + agg) rows (b*TT+t); writes g_x_h fp16 only.
__global__ __launch_bounds__(256)
void ln1_kernel(const float* __restrict__ gam, const float* __restrict__ bet) {
    const int tok = blockIdx.x * 8 + (threadIdx.x >> 5);
    const int l = threadIdx.x & 31;
    const float4* a = (const float4*)(g_agg + (size_t)tok * ND);
    float4 v[4];
    float s = 0.f;
    #pragma unroll
    for (int k = 0; k < 4; k++) {
        v[k] = a[l + 32 * k];
        s += (v[k].x + v[k].y) + (v[k].z + v[k].w);
    }
    #pragma unroll
    for (int o = 16; o; o >>= 1) s += __shfl_xor_sync(0xffffffffu, s, o);
    const float mean = s * (1.0f / ND);
    float q = 0.f;
    #pragma unroll
    for (int k = 0; k < 4; k++) {
        v[k].x -= mean; v[k].y -= mean; v[k].z -= mean; v[k].w -= mean;
        q += (v[k].x * v[k].x + v[k].y * v[k].y) + (v[k].z * v[k].z + v[k].w * v[k].w);
    }
    #pragma unroll
    for (int o = 16; o; o >>= 1) q += __shfl_xor_sync(0xffffffffu, q, o);
    const float rstd = rsqrtf(q * (1.0f / ND) + 1e-5f);
    uint2* xr = (uint2*)(g_x_h + (size_t)tok * ND);
    #pragma unroll
    for (int k = 0; k < 4; k++) {
        int idx = l + 32 * k;
        float4 gg = *(const float4*)(gam + idx * 4);
        float4 bb = *(const float4*)(bet + idx * 4);
        __half2 h0 = __floats2half2_rn(v[k].x * rstd * gg.x + bb.x,
                                       v[k].y * rstd * gg.y + bb.y);
        __half2 h1 = __floats2half2_rn(v[k].z * rstd * gg.z + bb.z,
                                       v[k].w * rstd * gg.w + bb.w);
        uint2 u; u.x = *(uint32_t*)&h0; u.y = *(uint32_t*)&h1;
        xr[idx] = u;
    }
}

// LN2: input g_y (already x + y) rows (b*TT+t); writes [T,B,D]:
// mode 0 (last layer): fp32 out only.  mode 1: fp16 g_src_h only.
__global__ __launch_bounds__(256)
void ln2_kernel(const float* __restrict__ gam, const float* __restrict__ bet,
                float* __restrict__ out, int mode) {
    const int p = blockIdx.x * 8 + (threadIdx.x >> 5);
    const int l = threadIdx.x & 31;
    const int b = p >> 7, t = p & 127;          // p = b*TT + t, TT=128
    const float4* a = (const float4*)(g_y + (size_t)p * ND);
    float4 v[4];
    float s = 0.f;
    #pragma unroll
    for (int k = 0; k < 4; k++) {
        v[k] = a[l + 32 * k];
        s += (v[k].x + v[k].y) + (v[k].z + v[k].w);
    }
    #pragma unroll
    for (int o = 16; o; o >>= 1) s += __shfl_xor_sync(0xffffffffu, s, o);
    const float mean = s * (1.0f / ND);
    float q = 0.f;
    #pragma unroll
    for (int k = 0; k < 4; k++) {
        v[k].x -= mean; v[k].y -= mean; v[k].z -= mean; v[k].w -= mean;
        q += (v[k].x * v[k].x + v[k].y * v[k].y) + (v[k].z * v[k].z + v[k].w * v[k].w);
    }
    #pragma unroll
    for (int o = 16; o; o >>= 1) q += __shfl_xor_sync(0xffffffffu, q, o);
    const float rstd = rsqrtf(q * (1.0f / ND) + 1e-5f);
    const size_t obase = ((size_t)(t * NB + b)) * ND;
    float4* orow = (float4*)(out + obase);
    uint2*  hrow = (uint2*)(g_src_h + obase);
    #pragma unroll
    for (int k = 0; k < 4; k++) {
        int idx = l + 32 * k;
        float4 gg = *(const float4*)(gam + idx * 4);
        float4 bb = *(const float4*)(bet + idx * 4);
        float4 o4;
        o4.x = v[k].x * rstd * gg.x + bb.x;
        o4.y = v[k].y * rstd * gg.y + bb.y;
        o4.z = v[k].z * rstd * gg.z + bb.z;
        o4.w = v[k].w * rstd * gg.w + bb.w;
        if (mode == 0) {
            orow[idx] = o4;
        } else {
            __half2 h0 = __floats2half2_rn(o4.x, o4.y);
            __half2 h1 = __floats2half2_rn(o4.z, o4.w);
            uint2 u; u.x = *(uint32_t*)&h0; u.y = *(uint32_t*)&h1;
            hrow[idx] = u;
        }
    }
}

// ---------------------------------------------------------------------------
extern "C" void kernel_launch(void* const* d_in, const int* in_sizes, int n_in,
                              void* d_out, int out_size) {
    const float* in_src  = (const float*)d_in[0];
    const float* in_srcc = (const float*)d_in[1];
    const float* w_sp = (const float*)d_in[2];
    const float* b_sp = (const float*)d_in[3];
    const float* w_tp = (const float*)d_in[4];
    const float* b_tp = (const float*)d_in[5];
    const float* w_at = (const float*)d_in[6];
    const float* b_mg = (const float*)d_in[9];
    const float* w_mg = (const float*)d_in[8];
    const float* w_ag = (const float*)d_in[10];
    const float* b_ag = (const float*)d_in[11];
    const float* w_l1 = (const float*)d_in[12];
    const float* b_l1 = (const float*)d_in[13];
    const float* w_l2 = (const float*)d_in[14];
    const float* b_l2 = (const float*)d_in[15];
    const float* g_n1 = (const float*)d_in[16];
    const float* bb_n1 = (const float*)d_in[17];
    const float* g_n2 = (const float*)d_in[18];
    const float* bb_n2 = (const float*)d_in[19];

    float *p_agg, *p_y;
    __half *p_s_h, *p_t_h, *p_wm_h, *p_x_h, *p_h1_h, *p_src_h, *p_srcc_h, *p_src0_h;
    __half *p_wsp, *p_wtp, *p_wag, *p_wl1, *p_wl2;
    cudaGetSymbolAddress((void**)&p_s_h,    g_s_h);
    cudaGetSymbolAddress((void**)&p_t_h,    g_t_h);
    cudaGetSymbolAddress((void**)&p_agg,    g_agg);
    cudaGetSymbolAddress((void**)&p_y,      g_y);
    cudaGetSymbolAddress((void**)&p_wm_h,   g_wm_h);
    cudaGetSymbolAddress((void**)&p_x_h,    g_x_h);
    cudaGetSymbolAddress((void**)&p_h1_h,   g_h1_h);
    cudaGetSymbolAddress((void**)&p_src_h,  g_src_h);
    cudaGetSymbolAddress((void**)&p_srcc_h, g_srcc_h);
    cudaGetSymbolAddress((void**)&p_src0_h, g_src0_h);
    cudaGetSymbolAddress((void**)&p_wsp,    g_wsp_h);
    cudaGetSymbolAddress((void**)&p_wtp,    g_wtp_h);
    cudaGetSymbolAddress((void**)&p_wag,    g_wag_h);
    cudaGetSymbolAddress((void**)&p_wl1,    g_wl1_h);
    cudaGetSymbolAddress((void**)&p_wl2,    g_wl2_h);

    cudaFuncSetAttribute(tc_gemm<1, 1, 0, 1>, cudaFuncAttributeMaxDynamicSharedMemorySize, DYN_SMEM);
    cudaFuncSetAttribute(tc_gemm<1, 1, 0, 2>, cudaFuncAttributeMaxDynamicSharedMemorySize, DYN_SMEM);
    cudaFuncSetAttribute(tc_gemm<0, 0, 2, 0>, cudaFuncAttributeMaxDynamicSharedMemorySize, DYN_SMEM);
    cudaFuncSetAttribute(tc_gemm<0, 0, 4, 0>, cudaFuncAttributeMaxDynamicSharedMemorySize, DYN_SMEM);
    cudaFuncSetAttribute(tc_gemm<1, 1, 0, 0>, cudaFuncAttributeMaxDynamicSharedMemorySize, DYN_SMEM);
    cudaFuncSetAttribute(tc_gemm<0, 0, 3, 0>, cudaFuncAttributeMaxDynamicSharedMemorySize, DYN_SMEM);

    // one-time fp16 conversions
    f32_to_f16_kernel<<<2048, 256>>>((const float4*)in_srcc, (__half2*)p_srcc_h, NTOK * ND / 4);
    f32_to_f16_kernel<<<2048, 256>>>((const float4*)in_src,  (__half2*)p_src0_h, NTOK * ND / 4);
    f32_to_f16_kernel<<<2048, 256>>>((const float4*)w_sp, (__half2*)p_wsp, NL * ND * ND / 4);
    f32_to_f16_kernel<<<2048, 256>>>((const float4*)w_tp, (__half2*)p_wtp, NL * ND * ND / 4);
    f32_to_f16_kernel<<<2048, 256>>>((const float4*)w_ag, (__half2*)p_wag, NL * ND * ND / 4);
    f32_to_f16_kernel<<<2048, 256>>>((const float4*)w_l1, (__half2*)p_wl1, NL * NDFF * ND / 4);
    f32_to_f16_kernel<<<2048, 256>>>((const float4*)w_l2, (__half2*)p_wl2, NL * ND * NDFF / 4);

    const dim3 gemm_dd(ND / BN, NTOK / BM);
    for (int l = 0; l < NL; l++) {
        const __half* srcA = (l == 0) ? p_src0_h : p_src_h;
        const float*  awl  = w_at + (size_t)l * NH * 2 * NSUB;

        // s = relu(srcc @ sw^T + sb) [fp16 out] + STORE s-part scores
        tc_gemm<1, 1, 0, 1><<<gemm_dd, 128, DYN_SMEM>>>(
            p_srcc_h, p_wsp + (size_t)l * ND * ND, b_sp + l * ND,
            nullptr, p_s_h, nullptr, awl, ND, ND);
        // t = relu(src @ tw^T + tb) [fp16 out] + ATOMIC-ADD t-part scores
        tc_gemm<1, 1, 0, 2><<<gemm_dd, 128, DYN_SMEM>>>(
            srcA, p_wtp + (size_t)l * ND * ND, b_tp + l * ND,
            nullptr, p_t_h, nullptr, awl, ND, ND);
        // softmax over batch
        softmax_kernel<<<NH * TT, NB>>>();
        // weighted message -> relu(wm) [B,T,D] fp16
        msg_kernel<<<dim3(NTOK / 64, NH), 256>>>(w_mg + (size_t)l * NH * NSUB * NSUB,
                                                 b_mg + l * NH * NSUB);
        // agg = wm @ gw^T + gb + src^T  [fp32 out, residual fused]
        if (l == 0)
            tc_gemm<0, 0, 2, 0><<<gemm_dd, 128, DYN_SMEM>>>(
                p_wm_h, p_wag + (size_t)l * ND * ND, b_ag + l * ND,
                p_agg, nullptr, in_src, nullptr, ND, ND);
        else
            tc_gemm<0, 0, 4, 0><<<gemm_dd, 128, DYN_SMEM>>>(
                p_wm_h, p_wag + (size_t)l * ND * ND, b_ag + l * ND,
                p_agg, nullptr, p_src_h, nullptr, ND, ND);
        // x = LN(agg')  [fp16 only]
        ln1_kernel<<<NTOK / 8, 256>>>(g_n1 + l * ND, bb_n1 + l * ND);
        // h1 = relu(x @ w1^T + b1)  [fp16 out]
        tc_gemm<1, 1, 0, 0><<<dim3(NDFF / BN, NTOK / BM), 128, DYN_SMEM>>>(
            p_x_h, p_wl1 + (size_t)l * NDFF * ND, b_l1 + l * NDFF,
            nullptr, p_h1_h, nullptr, nullptr, ND, NDFF);
        // y = h1 @ w2^T + b2 + x(fp16)  [fp32 out, fp16 residual fused]
        tc_gemm<0, 0, 3, 0><<<gemm_dd, 128, DYN_SMEM>>>(
            p_h1_h, p_wl2 + (size_t)l * ND * NDFF, b_l2 + l * ND,
            p_y, nullptr, p_x_h, nullptr, NDFF, ND);
        // out = LN(y') -> [T,B,D]: last layer fp32 d_out, else fp16 g_src_h
        ln2_kernel<<<NTOK / 8, 256>>>(g_n2 + l * ND, bb_n2 + l * ND,
                                      (float*)d_out, (l == NL - 1) ? 0 : 1);
    }
}

// round 8
// speedup vs baseline: 6.6927x; 1.0076x over previous
#include <cuda_runtime.h>
#include <cuda_fp16.h>
#include <cstdint>
#include <cstddef>

// Problem dims
#define NL   6
#define TT   128
#define NB   256
#define ND   512
#define NH   8
#define NDFF 2048
#define NSUB 64
#define NTOK (TT * NB)   // 32768 tokens

// mma.sync GEMM tile config (fp16 in, fp32 accum)
// CTA tile 128x128x64, 4 warps (2x2), warp tile 64x64, 3-stage cp.async
#define BM 128
#define BN 128
#define BKH 64                         // 64 halves = 128B row
#define NSTAGE 3
#define A_BYTES (BM * BKH * 2)         // 16384
#define STAGE_BYTES (2 * A_BYTES)      // 32768
#define DYN_SMEM (NSTAGE * STAGE_BYTES)  // 98304

// ---------------------------------------------------------------------------
// Scratch (__device__ globals; no allocation allowed)
// ---------------------------------------------------------------------------
__device__ __align__(16) __half g_s_h [(size_t)NL * NTOK * ND];  // all layers
__device__ __align__(16) __half g_t_h [(size_t)NTOK * ND];
__device__ __align__(16) float  g_scores[(size_t)NL * NH * TT * NB];
__device__ __align__(16) float  g_wts   [NH * TT * NB];
__device__ __align__(16) __half g_wm_h[(size_t)NTOK * ND];
__device__ __align__(16) float  g_agg [(size_t)NTOK * ND];   // holds src^T + agg
__device__ __align__(16) __half g_x_h [(size_t)NTOK * ND];
__device__ __align__(16) __half g_h1_h[(size_t)NTOK * NDFF];
__device__ __align__(16) float  g_y   [(size_t)NTOK * ND];   // holds x + y
__device__ __align__(16) __half g_src_h[(size_t)NTOK * ND];
__device__ __align__(16) __half g_srcc_h[(size_t)NTOK * ND];
__device__ __align__(16) __half g_src0_h[(size_t)NTOK * ND];
// fp16 weights
__device__ __align__(16) __half g_wsp_h[(size_t)NL * ND * ND];
__device__ __align__(16) __half g_wtp_h[(size_t)NL * ND * ND];
__device__ __align__(16) __half g_wag_h[(size_t)NL * ND * ND];
__device__ __align__(16) __half g_wl1_h[(size_t)NL * NDFF * ND];
__device__ __align__(16) __half g_wl2_h[(size_t)NL * ND * NDFF];

// ---------------------------------------------------------------------------
// PTX helpers (baseline sm_80+ instructions only)
// ---------------------------------------------------------------------------
__device__ __forceinline__ uint32_t smem_u32(const void* p) {
    uint32_t a;
    asm("{ .reg .u64 t; cvta.to.shared.u64 t, %1; cvt.u32.u64 %0, t; }"
        : "=r"(a) : "l"(p));
    return a;
}
__device__ __forceinline__ void cp_async16(uint32_t dst, const void* src) {
    asm volatile("cp.async.cg.shared.global [%0], [%1], 16;" :: "r"(dst), "l"(src));
}
#define CP_COMMIT() asm volatile("cp.async.commit_group;" ::: "memory")
#define CP_WAIT1()  asm volatile("cp.async.wait_group 1;" ::: "memory")

__device__ __forceinline__ void ldsm_x4(uint32_t* r, uint32_t addr) {
    asm volatile("ldmatrix.sync.aligned.m8n8.x4.shared.b16 {%0,%1,%2,%3}, [%4];"
                 : "=r"(r[0]), "=r"(r[1]), "=r"(r[2]), "=r"(r[3]) : "r"(addr));
}
__device__ __forceinline__ void mma16816(float* d, const uint32_t* a,
                                         uint32_t b0, uint32_t b1) {
    asm volatile(
        "mma.sync.aligned.m16n8k16.row.col.f32.f16.f16.f32 "
        "{%0,%1,%2,%3}, {%4,%5,%6,%7}, {%8,%9}, {%0,%1,%2,%3};"
        : "+f"(d[0]), "+f"(d[1]), "+f"(d[2]), "+f"(d[3])
        : "r"(a[0]), "r"(a[1]), "r"(a[2]), "r"(a[3]), "r"(b0), "r"(b1));
}

// ---------------------------------------------------------------------------
// cooperative stage loader (128 threads): A + B tile [128 x 64h], swizzled
// ---------------------------------------------------------------------------
__device__ __forceinline__ void load_stage(const __half* __restrict__ Ag,
                                           const __half* __restrict__ Wg,
                                           int K, uint32_t abase, uint32_t bbase,
                                           int tid) {
    #pragma unroll
    for (int it = 0; it < 8; it++) {
        int q = tid + it * 128;        // 0..1023 16B chunks per operand
        int r = q >> 3;                // row 0..127
        int c = q & 7;                 // logical 16B chunk in row
        uint32_t off = (uint32_t)(r * 128 + ((c ^ (r & 7)) << 4));
        cp_async16(abase + off, Ag + (size_t)r * K + c * 8);
        cp_async16(bbase + off, Wg + (size_t)r * K + c * 8);
    }
    CP_COMMIT();
}

// fragment loader: one k16 slice for this warp (64x64 warp tile)
__device__ __forceinline__ void load_frags(uint32_t aB, uint32_t bB, int ks,
                                           int arow, int brow, int axor, int bxor,
                                           int csel,
                                           uint32_t af[4][4], uint32_t bf[4][4]) {
    #pragma unroll
    for (int mt = 0; mt < 4; mt++) {
        uint32_t addr = aB + (uint32_t)((arow + mt * 16) * 128)
                      + (uint32_t)((((ks << 1) + csel) ^ axor) << 4);
        ldsm_x4(af[mt], addr);
    }
    #pragma unroll
    for (int np = 0; np < 4; np++) {
        uint32_t addr = bB + (uint32_t)((brow + np * 16) * 128)
                      + (uint32_t)((((ks << 1) + csel) ^ bxor) << 4);
        ldsm_x4(bf[np], addr);
    }
}

// ---------------------------------------------------------------------------
// fp16 tensor-core GEMM: C[M,N] = A[M,K]@W[N,K]^T + bias (+residual), opt relu.
// ADDMODE: 0 none
//          2 fp32 residual, transposed rows [(m%TT)*NB+(m/TT)]
//          3 fp16 residual, same layout as C
//          4 fp16 residual, transposed rows
// SCORE:   0 none; 1 store s-part scores (BATCHED over layers via blockIdx.z);
//          2 atomicAdd t-part scores.
//          (requires N=512, rows are tokens t*NB+b; aw = attn weights [H,128])
// grid (N/128, M/128[, NL when SCORE==1]), 128 threads (4 warps, 2x2).
// ---------------------------------------------------------------------------
template <int RELU, int OUTH, int ADDMODE, int SCORE>
__global__ __launch_bounds__(128)
void tc_gemm(const __half* __restrict__ A, const __half* __restrict__ W,
             const float* __restrict__ bias, float* __restrict__ Cf,
             __half* __restrict__ Ch, const void* __restrict__ Res,
             const float* __restrict__ aw, float* __restrict__ sbuf,
             int K, int N) {
    __shared__ float s_bias[BN];
    extern __shared__ __align__(1024) char dynsmem[];
    const uint32_t dynbase = smem_u32(dynsmem);

    // batched-over-layers offsets (s-pass only; all strides compile-time)
    if (SCORE == 1) {
        const int zl = blockIdx.z;
        W    += (size_t)zl * ND * ND;
        bias += zl * ND;
        Ch   += (size_t)zl * NTOK * ND;
        aw   += zl * NH * 2 * NSUB;
        sbuf += (size_t)zl * NH * TT * NB;
    }

    const int tid = threadIdx.x;
    const int wid = tid >> 5, lid = tid & 31;
    const int wm_ = wid >> 1, wn_ = wid & 1;   // 2 x 2 warp grid
    const int m0 = blockIdx.y * BM, n0 = blockIdx.x * BN;

    s_bias[tid] = bias[n0 + tid];

    const __half* Abase = A + (size_t)m0 * K;
    const __half* Wbase = W + (size_t)n0 * K;
    const int NCH = K / BKH;

    // per-lane ldmatrix geometry
    const int sub = lid >> 3, wi = lid & 7;
    const int csel = sub >> 1;                       // 0/1 -> k halves 0/8
    const int arow = wm_ * 64 + (sub & 1) * 8 + wi;  // + mt*16
    const int brow = wn_ * 64 + (sub & 1) * 8 + wi;  // + np*16
    const int axor = arow & 7, bxor = brow & 7;      // invariant under +16

    // prologue: stages 0..1
    #pragma unroll
    for (int c = 0; c < NSTAGE - 1; c++)
        load_stage(Abase + c * BKH, Wbase + c * BKH, K,
                   dynbase + c * STAGE_BYTES,
                   dynbase + c * STAGE_BYTES + A_BYTES, tid);

    float acc[4][8][4] = {};
    uint32_t afr[2][4][4], bfr[2][4][4];

    int stage = 0;
    for (int i = 0; i < NCH; i++) {
        CP_WAIT1();              // stage for chunk i resident (<=1 pending)
        __syncthreads();         // all warps done reading the slot being refilled
        int j = i + NSTAGE - 1;
        int sj = stage + NSTAGE - 1; if (sj >= NSTAGE) sj -= NSTAGE;
        if (j < NCH) {
            load_stage(Abase + j * BKH, Wbase + j * BKH, K,
                       dynbase + sj * STAGE_BYTES,
                       dynbase + sj * STAGE_BYTES + A_BYTES, tid);
        } else {
            CP_COMMIT();         // keep group accounting uniform
        }

        const uint32_t aB = dynbase + stage * STAGE_BYTES;
        const uint32_t bB = aB + A_BYTES;

        load_frags(aB, bB, 0, arow, brow, axor, bxor, csel, afr[0], bfr[0]);
        #pragma unroll
        for (int ks = 0; ks < 4; ks++) {
            int cur = ks & 1;
            if (ks < 3)
                load_frags(aB, bB, ks + 1, arow, brow, axor, bxor, csel,
                           afr[cur ^ 1], bfr[cur ^ 1]);
            #pragma unroll
            for (int mt = 0; mt < 4; mt++)
                #pragma unroll
                for (int nt = 0; nt < 8; nt++)
                    mma16816(acc[mt][nt], afr[cur][mt],
                             bfr[cur][nt >> 1][nt & 1],
                             bfr[cur][nt >> 1][(nt & 1) + 2]);
        }
        if (++stage == NSTAGE) stage = 0;
    }

    // score weights: u = nt*8 + (lid&3)*2 (n0-invariant), head = n0/64 + wn_
    float waw[16];
    const int shead = (n0 >> 6) + wn_;
    if (SCORE) {
        const int off = (SCORE == 2) ? 64 : 0;
        #pragma unroll
        for (int nt = 0; nt < 8; nt++) {
            int u = nt * 8 + (lid & 3) * 2;
            waw[nt * 2]     = __ldg(aw + shead * 128 + off + u);
            waw[nt * 2 + 1] = __ldg(aw + shead * 128 + off + u + 1);
        }
    }

    // epilogue: direct stores (+ optional residual, + optional score partials)
    #pragma unroll
    for (int mt = 0; mt < 4; mt++) {
        int row = m0 + wm_ * 64 + mt * 16 + (lid >> 2);
        size_t rb0 = 0, rb1 = 0;
        if (ADDMODE == 3) {
            rb0 = (size_t)row * N;
            rb1 = (size_t)(row + 8) * N;
        } else if (ADDMODE == 2 || ADDMODE == 4) {
            int b0_ = row >> 7, t0_ = row & 127;          // TT = 128
            int b1_ = (row + 8) >> 7, t1_ = (row + 8) & 127;
            rb0 = ((size_t)(t0_ * NB + b0_)) * ND;
            rb1 = ((size_t)(t1_ * NB + b1_)) * ND;
        }
        float sc0 = 0.f, sc1 = 0.f;
        #pragma unroll
        for (int nt = 0; nt < 8; nt++) {
            int coll = wn_ * 64 + nt * 8 + (lid & 3) * 2;
            int col = n0 + coll;
            float bx = s_bias[coll], by = s_bias[coll + 1];
            float v0 = acc[mt][nt][0] + bx, v1 = acc[mt][nt][1] + by;
            float v2 = acc[mt][nt][2] + bx, v3 = acc[mt][nt][3] + by;
            if (ADDMODE == 2) {
                const float* Rf = (const float*)Res;
                float2 r0 = *(const float2*)(Rf + rb0 + col);
                float2 r1 = *(const float2*)(Rf + rb1 + col);
                v0 += r0.x; v1 += r0.y; v2 += r1.x; v3 += r1.y;
            } else if (ADDMODE == 3 || ADDMODE == 4) {
                const __half* Rh = (const __half*)Res;
                float2 r0 = __half22float2(*(const __half2*)(Rh + rb0 + col));
                float2 r1 = __half22float2(*(const __half2*)(Rh + rb1 + col));
                v0 += r0.x; v1 += r0.y; v2 += r1.x; v3 += r1.y;
            }
            if (RELU) {
                v0 = fmaxf(v0, 0.f); v1 = fmaxf(v1, 0.f);
                v2 = fmaxf(v2, 0.f); v3 = fmaxf(v3, 0.f);
            }
            if (SCORE) {
                sc0 += v0 * waw[nt * 2] + v1 * waw[nt * 2 + 1];
                sc1 += v2 * waw[nt * 2] + v3 * waw[nt * 2 + 1];
            }
            if (OUTH) {
                *(__half2*)(Ch + (size_t)row * N + col)       = __floats2half2_rn(v0, v1);
                *(__half2*)(Ch + (size_t)(row + 8) * N + col) = __floats2half2_rn(v2, v3);
            } else {
                *(float2*)(Cf + (size_t)row * N + col)       = make_float2(v0, v1);
                *(float2*)(Cf + (size_t)(row + 8) * N + col) = make_float2(v2, v3);
            }
        }
        if (SCORE) {
            // quad reduction: lanes lid^1, lid^2 share the same rows
            sc0 += __shfl_xor_sync(0xffffffffu, sc0, 1);
            sc0 += __shfl_xor_sync(0xffffffffu, sc0, 2);
            sc1 += __shfl_xor_sync(0xffffffffu, sc1, 1);
            sc1 += __shfl_xor_sync(0xffffffffu, sc1, 2);
            if ((lid & 3) == 0) {
                int tok0 = row, tok1 = row + 8;        // tok = t*NB + b
                int t0_ = tok0 >> 8, b0_ = tok0 & 255; // NB = 256
                int t1_ = tok1 >> 8, b1_ = tok1 & 255;
                float* sp0 = sbuf + (shead * TT + t0_) * NB + b0_;
                float* sp1 = sbuf + (shead * TT + t1_) * NB + b1_;
                if (SCORE == 1) { *sp0 = sc0; *sp1 = sc1; }
                else           { atomicAdd(sp0, sc0); atomicAdd(sp1, sc1); }
            }
        }
    }
}

// ---------------------------------------------------------------------------
// f32 -> f16 conversion (float4 -> half2x2)
// ---------------------------------------------------------------------------
__global__ __launch_bounds__(256)
void f32_to_f16_kernel(const float4* __restrict__ in, __half2* __restrict__ out, int n4) {
    for (int i = blockIdx.x * 256 + threadIdx.x; i < n4; i += gridDim.x * 256) {
        float4 v = in[i];
        out[2 * i]     = __floats2half2_rn(v.x, v.y);
        out[2 * i + 1] = __floats2half2_rn(v.z, v.w);
    }
}

// ---------------------------------------------------------------------------
// Block reductions (256 threads) — used by softmax only
// ---------------------------------------------------------------------------
__device__ __forceinline__ float block_reduce_sum256(float v) {
    __shared__ float sh[8];
    int lane = threadIdx.x & 31, wid = threadIdx.x >> 5;
    #pragma unroll
    for (int o = 16; o; o >>= 1) v += __shfl_xor_sync(0xffffffffu, v, o);
    if (lane == 0) sh[wid] = v;
    __syncthreads();
    float r = (lane < 8) ? sh[lane] : 0.0f;
    #pragma unroll
    for (int o = 4; o; o >>= 1) r += __shfl_xor_sync(0xffffffffu, r, o);
    r = __shfl_sync(0xffffffffu, r, 0);
    __syncthreads();
    return r;
}
__device__ __forceinline__ float block_reduce_max256(float v) {
    __shared__ float sh[8];
    int lane = threadIdx.x & 31, wid = threadIdx.x >> 5;
    #pragma unroll
    for (int o = 16; o; o >>= 1) v = fmaxf(v, __shfl_xor_sync(0xffffffffu, v, o));
    if (lane == 0) sh[wid] = v;
    __syncthreads();
    float r = (lane < 8) ? sh[lane] : -3.4e38f;
    #pragma unroll
    for (int o = 4; o; o >>= 1) r = fmaxf(r, __shfl_xor_sync(0xffffffffu, r, o));
    r = __shfl_sync(0xffffffffu, r, 0);
    __syncthreads();
    return r;
}

// softmax over b (axis=1 of [H,B,T]); attn bias ab[h] cancels in softmax.
__global__ __launch_bounds__(256)
void softmax_kernel(const float* __restrict__ sbuf) {
    int ht = blockIdx.x;
    float v = sbuf[(size_t)ht * NB + threadIdx.x];
    float m = block_reduce_max256(v);
    float e = __expf(v - m);
    float s = block_reduce_sum256(e);
    g_wts[(size_t)ht * NB + threadIdx.x] = e / s;
}

// per-head message mini-GEMM, reads s_h (layer slice) / t_h
__global__ __launch_bounds__(256)
void msg_kernel(const float* __restrict__ mw, const float* __restrict__ mb,
                const __half* __restrict__ s_h) {
    __shared__ float prod[64][65];
    __shared__ float mws [64][65];
    __shared__ float wt_s[64];
    __shared__ float mb_s[64];

    const int h  = blockIdx.y;
    const int p0 = blockIdx.x * 64;
    const int tid = threadIdx.x;

    for (int i = tid; i < 64 * 64; i += 256) {
        int u = i >> 6, s = i & 63;
        mws[s][u] = mw[((size_t)h * 64 + u) * 64 + s];
    }
    if (tid < 64) {
        mb_s[tid] = mb[h * 64 + tid];
        int p = p0 + tid, b = p / TT, t = p % TT;
        wt_s[tid] = g_wts[(h * TT + t) * NB + b];
    }
    for (int i = tid; i < 64 * 16; i += 256) {      // uint2 = 4 halves
        int tok = i >> 4, u4 = i & 15;
        int p = p0 + tok, b = p / TT, t = p % TT;
        size_t idx = ((size_t)(t * NB + b)) * ND + h * NSUB + u4 * 4;
        uint2 sraw = *(const uint2*)(s_h + idx);
        uint2 traw = *(const uint2*)(g_t_h + idx);
        float2 s0 = __half22float2(*(__half2*)&sraw.x);
        float2 s1 = __half22float2(*(__half2*)&sraw.y);
        float2 t0 = __half22float2(*(__half2*)&traw.x);
        float2 t1 = __half22float2(*(__half2*)&traw.y);
        prod[tok][u4 * 4]     = s0.x * t0.x;
        prod[tok][u4 * 4 + 1] = s0.y * t0.y;
        prod[tok][u4 * 4 + 2] = s1.x * t1.x;
        prod[tok][u4 * 4 + 3] = s1.y * t1.y;
    }
    __syncthreads();

    const int tx = tid & 15, ty = tid >> 4;
    float acc[4][4] = {};
    #pragma unroll 4
    for (int s = 0; s < 64; s++) {
        float a[4], w[4];
        #pragma unroll
        for (int i = 0; i < 4; i++) a[i] = prod[ty * 4 + i][s];
        #pragma unroll
        for (int j = 0; j < 4; j++) w[j] = mws[s][tx * 4 + j];
        #pragma unroll
        for (int i = 0; i < 4; i++)
            #pragma unroll
            for (int j = 0; j < 4; j++)
                acc[i][j] += a[i] * w[j];
    }
    #pragma unroll
    for (int i = 0; i < 4; i++) {
        int tok = ty * 4 + i;
        float wt = wt_s[tok];
        #pragma unroll
        for (int j = 0; j < 4; j++) {
            int u = tx * 4 + j;
            float v = wt * (acc[i][j] + mb_s[u]);
            g_wm_h[((size_t)(p0 + tok)) * ND + h * NSUB + u] =
                __float2half_rn(fmaxf(v, 0.f));
        }
    }
}

// ---------------------------------------------------------------------------
// Warp-per-token LayerNorms (no block barriers). 8 warps/block.
// ---------------------------------------------------------------------------
// LN1: input g_agg (already src^T + agg) rows (b*TT+t); writes g_x_h fp16 only.
__global__ __launch_bounds__(256)
void ln1_kernel(const float* __restrict__ gam, const float* __restrict__ bet) {
    const int tok = blockIdx.x * 8 + (threadIdx.x >> 5);
    const int l = threadIdx.x & 31;
    const float4* a = (const float4*)(g_agg + (size_t)tok * ND);
    float4 v[4];
    float s = 0.f;
    #pragma unroll
    for (int k = 0; k < 4; k++) {
        v[k] = a[l + 32 * k];
        s += (v[k].x + v[k].y) + (v[k].z + v[k].w);
    }
    #pragma unroll
    for (int o = 16; o; o >>= 1) s += __shfl_xor_sync(0xffffffffu, s, o);
    const float mean = s * (1.0f / ND);
    float q = 0.f;
    #pragma unroll
    for (int k = 0; k < 4; k++) {
        v[k].x -= mean; v[k].y -= mean; v[k].z -= mean; v[k].w -= mean;
        q += (v[k].x * v[k].x + v[k].y * v[k].y) + (v[k].z * v[k].z + v[k].w * v[k].w);
    }
    #pragma unroll
    for (int o = 16; o; o >>= 1) q += __shfl_xor_sync(0xffffffffu, q, o);
    const float rstd = rsqrtf(q * (1.0f / ND) + 1e-5f);
    uint2* xr = (uint2*)(g_x_h + (size_t)tok * ND);
    #pragma unroll
    for (int k = 0; k < 4; k++) {
        int idx = l + 32 * k;
        float4 gg = *(const float4*)(gam + idx * 4);
        float4 bb = *(const float4*)(bet + idx * 4);
        __half2 h0 = __floats2half2_rn(v[k].x * rstd * gg.x + bb.x,
                                       v[k].y * rstd * gg.y + bb.y);
        __half2 h1 = __floats2half2_rn(v[k].z * rstd * gg.z + bb.z,
                                       v[k].w * rstd * gg.w + bb.w);
        uint2 u; u.x = *(uint32_t*)&h0; u.y = *(uint32_t*)&h1;
        xr[idx] = u;
    }
}

// LN2: input g_y (already x + y) rows (b*TT+t); writes [T,B,D]:
// mode 0 (last layer): fp32 out only.  mode 1: fp16 g_src_h only.
__global__ __launch_bounds__(256)
void ln2_kernel(const float* __restrict__ gam, const float* __restrict__ bet,
                float* __restrict__ out, int mode) {
    const int p = blockIdx.x * 8 + (threadIdx.x >> 5);
    const int l = threadIdx.x & 31;
    const int b = p >> 7, t = p & 127;          // p = b*TT + t, TT=128
    const float4* a = (const float4*)(g_y + (size_t)p * ND);
    float4 v[4];
    float s = 0.f;
    #pragma unroll
    for (int k = 0; k < 4; k++) {
        v[k] = a[l + 32 * k];
        s += (v[k].x + v[k].y) + (v[k].z + v[k].w);
    }
    #pragma unroll
    for (int o = 16; o; o >>= 1) s += __shfl_xor_sync(0xffffffffu, s, o);
    const float mean = s * (1.0f / ND);
    float q = 0.f;
    #pragma unroll
    for (int k = 0; k < 4; k++) {
        v[k].x -= mean; v[k].y -= mean; v[k].z -= mean; v[k].w -= mean;
        q += (v[k].x * v[k].x + v[k].y * v[k].y) + (v[k].z * v[k].z + v[k].w * v[k].w);
    }
    #pragma unroll
    for (int o = 16; o; o >>= 1) q += __shfl_xor_sync(0xffffffffu, q, o);
    const float rstd = rsqrtf(q * (1.0f / ND) + 1e-5f);
    const size_t obase = ((size_t)(t * NB + b)) * ND;
    float4* orow = (float4*)(out + obase);
    uint2*  hrow = (uint2*)(g_src_h + obase);
    #pragma unroll
    for (int k = 0; k < 4; k++) {
        int idx = l + 32 * k;
        float4 gg = *(const float4*)(gam + idx * 4);
        float4 bb = *(const float4*)(bet + idx * 4);
        float4 o4;
        o4.x = v[k].x * rstd * gg.x + bb.x;
        o4.y = v[k].y * rstd * gg.y + bb.y;
        o4.z = v[k].z * rstd * gg.z + bb.z;
        o4.w = v[k].w * rstd * gg.w + bb.w;
        if (mode == 0) {
            orow[idx] = o4;
        } else {
            __half2 h0 = __floats2half2_rn(o4.x, o4.y);
            __half2 h1 = __floats2half2_rn(o4.z, o4.w);
            uint2 u; u.x = *(uint32_t*)&h0; u.y = *(uint32_t*)&h1;
            hrow[idx] = u;
        }
    }
}

// ---------------------------------------------------------------------------
extern "C" void kernel_launch(void* const* d_in, const int* in_sizes, int n_in,
                              void* d_out, int out_size) {
    const float* in_src  = (const float*)d_in[0];
    const float* in_srcc = (const float*)d_in[1];
    const float* w_sp = (const float*)d_in[2];
    const float* b_sp = (const float*)d_in[3];
    const float* w_tp = (const float*)d_in[4];
    const float* b_tp = (const float*)d_in[5];
    const float* w_at = (const float*)d_in[6];
    const float* w_mg = (const float*)d_in[8];
    const float* b_mg = (const float*)d_in[9];
    const float* w_ag = (const float*)d_in[10];
    const float* b_ag = (const float*)d_in[11];
    const float* w_l1 = (const float*)d_in[12];
    const float* b_l1 = (const float*)d_in[13];
    const float* w_l2 = (const float*)d_in[14];
    const float* b_l2 = (const float*)d_in[15];
    const float* g_n1 = (const float*)d_in[16];
    const float* bb_n1 = (const float*)d_in[17];
    const float* g_n2 = (const float*)d_in[18];
    const float* bb_n2 = (const float*)d_in[19];

    float *p_agg, *p_y, *p_scores;
    __half *p_s_h, *p_t_h, *p_wm_h, *p_x_h, *p_h1_h, *p_src_h, *p_srcc_h, *p_src0_h;
    __half *p_wsp, *p_wtp, *p_wag, *p_wl1, *p_wl2;
    cudaGetSymbolAddress((void**)&p_s_h,    g_s_h);
    cudaGetSymbolAddress((void**)&p_t_h,    g_t_h);
    cudaGetSymbolAddress((void**)&p_scores, g_scores);
    cudaGetSymbolAddress((void**)&p_agg,    g_agg);
    cudaGetSymbolAddress((void**)&p_y,      g_y);
    cudaGetSymbolAddress((void**)&p_wm_h,   g_wm_h);
    cudaGetSymbolAddress((void**)&p_x_h,    g_x_h);
    cudaGetSymbolAddress((void**)&p_h1_h,   g_h1_h);
    cudaGetSymbolAddress((void**)&p_src_h,  g_src_h);
    cudaGetSymbolAddress((void**)&p_srcc_h, g_srcc_h);
    cudaGetSymbolAddress((void**)&p_src0_h, g_src0_h);
    cudaGetSymbolAddress((void**)&p_wsp,    g_wsp_h);
    cudaGetSymbolAddress((void**)&p_wtp,    g_wtp_h);
    cudaGetSymbolAddress((void**)&p_wag,    g_wag_h);
    cudaGetSymbolAddress((void**)&p_wl1,    g_wl1_h);
    cudaGetSymbolAddress((void**)&p_wl2,    g_wl2_h);

    cudaFuncSetAttribute(tc_gemm<1, 1, 0, 1>, cudaFuncAttributeMaxDynamicSharedMemorySize, DYN_SMEM);
    cudaFuncSetAttribute(tc_gemm<1, 1, 0, 2>, cudaFuncAttributeMaxDynamicSharedMemorySize, DYN_SMEM);
    cudaFuncSetAttribute(tc_gemm<0, 0, 2, 0>, cudaFuncAttributeMaxDynamicSharedMemorySize, DYN_SMEM);
    cudaFuncSetAttribute(tc_gemm<0, 0, 4, 0>, cudaFuncAttributeMaxDynamicSharedMemorySize, DYN_SMEM);
    cudaFuncSetAttribute(tc_gemm<1, 1, 0, 0>, cudaFuncAttributeMaxDynamicSharedMemorySize, DYN_SMEM);
    cudaFuncSetAttribute(tc_gemm<0, 0, 3, 0>, cudaFuncAttributeMaxDynamicSharedMemorySize, DYN_SMEM);

    // one-time fp16 conversions
    f32_to_f16_kernel<<<2048, 256>>>((const float4*)in_srcc, (__half2*)p_srcc_h, NTOK * ND / 4);
    f32_to_f16_kernel<<<2048, 256>>>((const float4*)in_src,  (__half2*)p_src0_h, NTOK * ND / 4);
    f32_to_f16_kernel<<<2048, 256>>>((const float4*)w_sp, (__half2*)p_wsp, NL * ND * ND / 4);
    f32_to_f16_kernel<<<2048, 256>>>((const float4*)w_tp, (__half2*)p_wtp, NL * ND * ND / 4);
    f32_to_f16_kernel<<<2048, 256>>>((const float4*)w_ag, (__half2*)p_wag, NL * ND * ND / 4);
    f32_to_f16_kernel<<<2048, 256>>>((const float4*)w_l1, (__half2*)p_wl1, NL * NDFF * ND / 4);
    f32_to_f16_kernel<<<2048, 256>>>((const float4*)w_l2, (__half2*)p_wl2, NL * ND * NDFF / 4);

    // ---- hoisted: ALL layers' s = relu(srcc @ sw_l^T + sb_l) + s-part scores
    // (srcc is layer-invariant) — one batched launch, 6144 CTAs.
    tc_gemm<1, 1, 0, 1><<<dim3(ND / BN, NTOK / BM, NL), 128, DYN_SMEM>>>(
        p_srcc_h, p_wsp, b_sp, nullptr, p_s_h, nullptr, w_at, p_scores, ND, ND);

    const dim3 gemm_dd(ND / BN, NTOK / BM);
    for (int l = 0; l < NL; l++) {
        const __half* srcA = (l == 0) ? p_src0_h : p_src_h;
        const float*  awl  = w_at + (size_t)l * NH * 2 * NSUB;
        float* sbl = p_scores + (size_t)l * NH * TT * NB;

        // t = relu(src @ tw^T + tb) [fp16 out] + ATOMIC-ADD t-part scores
        tc_gemm<1, 1, 0, 2><<<gemm_dd, 128, DYN_SMEM>>>(
            srcA, p_wtp + (size_t)l * ND * ND, b_tp + l * ND,
            nullptr, p_t_h, nullptr, awl, sbl, ND, ND);
        // softmax over batch
        softmax_kernel<<<NH * TT, NB>>>(sbl);
        // weighted message -> relu(wm) [B,T,D] fp16
        msg_kernel<<<dim3(NTOK / 64, NH), 256>>>(
            w_mg + (size_t)l * NH * NSUB * NSUB, b_mg + l * NH * NSUB,
            p_s_h + (size_t)l * NTOK * ND);
        // agg = wm @ gw^T + gb + src^T  [fp32 out, residual fused]
        if (l == 0)
            tc_gemm<0, 0, 2, 0><<<gemm_dd, 128, DYN_SMEM>>>(
                p_wm_h, p_wag + (size_t)l * ND * ND, b_ag + l * ND,
                p_agg, nullptr, in_src, nullptr, nullptr, ND, ND);
        else
            tc_gemm<0, 0, 4, 0><<<gemm_dd, 128, DYN_SMEM>>>(
                p_wm_h, p_wag + (size_t)l * ND * ND, b_ag + l * ND,
                p_agg, nullptr, p_src_h, nullptr, nullptr, ND, ND);
        // x = LN(agg')  [fp16 only]
        ln1_kernel<<<NTOK / 8, 256>>>(g_n1 + l * ND, bb_n1 + l * ND);
        // h1 = relu(x @ w1^T + b1)  [fp16 out]
        tc_gemm<1, 1, 0, 0><<<dim3(NDFF / BN, NTOK / BM), 128, DYN_SMEM>>>(
            p_x_h, p_wl1 + (size_t)l * NDFF * ND, b_l1 + l * NDFF,
            nullptr, p_h1_h, nullptr, nullptr, nullptr, ND, NDFF);
        // y = h1 @ w2^T + b2 + x(fp16)  [fp32 out, fp16 residual fused]
        tc_gemm<0, 0, 3, 0><<<gemm_dd, 128, DYN_SMEM>>>(
            p_h1_h, p_wl2 + (size_t)l * ND * NDFF, b_l2 + l * ND,
            p_y, nullptr, p_x_h, nullptr, nullptr, NDFF, ND);
        // out = LN(y') -> [T,B,D]: last layer fp32 d_out, else fp16 g_src_h
        ln2_kernel<<<NTOK / 8, 256>>>(g_n2 + l * ND, bb_n2 + l * ND,
                                      (float*)d_out, (l == NL - 1) ? 0 : 1);
    }
}

// round 9
// speedup vs baseline: 7.4431x; 1.1121x over previous
#include <cuda_runtime.h>
#include <cuda_fp16.h>
#include <cstdint>
#include <cstddef>

// Problem dims
#define NL   6
#define TT   128
#define NB   256
#define ND   512
#define NH   8
#define NDFF 2048
#define NSUB 64
#define NTOK (TT * NB)   // 32768 tokens
// All activation buffers use row index p = t*NB + b ("natural" [T,B,D] order).

// mma.sync GEMM tile config (fp16 in, fp32 accum)
#define BM 128
#define BN 128
#define BKH 64                         // 64 halves = 128B row
#define NSTAGE 3
#define A_BYTES (BM * BKH * 2)         // 16384
#define STAGE_BYTES (2 * A_BYTES)      // 32768
#define DYN_SMEM (NSTAGE * STAGE_BYTES)  // 98304

// ---------------------------------------------------------------------------
// Scratch (__device__ globals; no allocation allowed)
// ---------------------------------------------------------------------------
__device__ __align__(16) __half g_s_h [(size_t)NL * NTOK * ND];  // all layers
__device__ __align__(16) __half g_t_h [(size_t)NTOK * ND];
__device__ __align__(16) float  g_scores[(size_t)NL * NH * TT * NB];
__device__ __align__(16) float  g_wts   [NH * TT * NB];
__device__ __align__(16) __half g_wm_h[(size_t)NTOK * ND];
__device__ __align__(16) float  g_agg [(size_t)NTOK * ND];   // holds src + agg
__device__ __align__(16) __half g_x_h [(size_t)NTOK * ND];
__device__ __align__(16) __half g_h1_h[(size_t)NTOK * NDFF];
__device__ __align__(16) float  g_y   [(size_t)NTOK * ND];   // holds x + y
__device__ __align__(16) __half g_src_h[(size_t)NTOK * ND];
__device__ __align__(16) __half g_srcc_h[(size_t)NTOK * ND];
__device__ __align__(16) __half g_src0_h[(size_t)NTOK * ND];
// fp16 weights
__device__ __align__(16) __half g_wsp_h[(size_t)NL * ND * ND];
__device__ __align__(16) __half g_wtp_h[(size_t)NL * ND * ND];
__device__ __align__(16) __half g_wag_h[(size_t)NL * ND * ND];
__device__ __align__(16) __half g_wl1_h[(size_t)NL * NDFF * ND];
__device__ __align__(16) __half g_wl2_h[(size_t)NL * ND * NDFF];
__device__ __align__(16) __half g_wmg_h[(size_t)NL * NH * NSUB * NSUB];

// ---------------------------------------------------------------------------
// PTX helpers (baseline sm_80+ instructions only)
// ---------------------------------------------------------------------------
__device__ __forceinline__ uint32_t smem_u32(const void* p) {
    uint32_t a;
    asm("{ .reg .u64 t; cvta.to.shared.u64 t, %1; cvt.u32.u64 %0, t; }"
        : "=r"(a) : "l"(p));
    return a;
}
__device__ __forceinline__ void cp_async16(uint32_t dst, const void* src) {
    asm volatile("cp.async.cg.shared.global [%0], [%1], 16;" :: "r"(dst), "l"(src));
}
#define CP_COMMIT() asm volatile("cp.async.commit_group;" ::: "memory")
#define CP_WAIT1()  asm volatile("cp.async.wait_group 1;" ::: "memory")
#define CP_WAIT0()  asm volatile("cp.async.wait_group 0;" ::: "memory")

__device__ __forceinline__ void ldsm_x4(uint32_t* r, uint32_t addr) {
    asm volatile("ldmatrix.sync.aligned.m8n8.x4.shared.b16 {%0,%1,%2,%3}, [%4];"
                 : "=r"(r[0]), "=r"(r[1]), "=r"(r[2]), "=r"(r[3]) : "r"(addr));
}
__device__ __forceinline__ void mma16816(float* d, const uint32_t* a,
                                         uint32_t b0, uint32_t b1) {
    asm volatile(
        "mma.sync.aligned.m16n8k16.row.col.f32.f16.f16.f32 "
        "{%0,%1,%2,%3}, {%4,%5,%6,%7}, {%8,%9}, {%0,%1,%2,%3};"
        : "+f"(d[0]), "+f"(d[1]), "+f"(d[2]), "+f"(d[3])
        : "r"(a[0]), "r"(a[1]), "r"(a[2]), "r"(a[3]), "r"(b0), "r"(b1));
}

// ---------------------------------------------------------------------------
// cooperative stage loader (128 threads): A + B tile [128 x 64h], swizzled
// ---------------------------------------------------------------------------
__device__ __forceinline__ void load_stage(const __half* __restrict__ Ag,
                                           const __half* __restrict__ Wg,
                                           int K, uint32_t abase, uint32_t bbase,
                                           int tid) {
    #pragma unroll
    for (int it = 0; it < 8; it++) {
        int q = tid + it * 128;        // 0..1023 16B chunks per operand
        int r = q >> 3;                // row 0..127
        int c = q & 7;                 // logical 16B chunk in row
        uint32_t off = (uint32_t)(r * 128 + ((c ^ (r & 7)) << 4));
        cp_async16(abase + off, Ag + (size_t)r * K + c * 8);
        cp_async16(bbase + off, Wg + (size_t)r * K + c * 8);
    }
    CP_COMMIT();
}

// fragment loader: one k16 slice for this warp (64x64 warp tile)
__device__ __forceinline__ void load_frags(uint32_t aB, uint32_t bB, int ks,
                                           int arow, int brow, int axor, int bxor,
                                           int csel,
                                           uint32_t af[4][4], uint32_t bf[4][4]) {
    #pragma unroll
    for (int mt = 0; mt < 4; mt++) {
        uint32_t addr = aB + (uint32_t)((arow + mt * 16) * 128)
                      + (uint32_t)((((ks << 1) + csel) ^ axor) << 4);
        ldsm_x4(af[mt], addr);
    }
    #pragma unroll
    for (int np = 0; np < 4; np++) {
        uint32_t addr = bB + (uint32_t)((brow + np * 16) * 128)
                      + (uint32_t)((((ks << 1) + csel) ^ bxor) << 4);
        ldsm_x4(bf[np], addr);
    }
}

// ---------------------------------------------------------------------------
// fp16 tensor-core GEMM: C[M,N] = A[M,K]@W[N,K]^T + bias (+residual), opt relu.
// ADDMODE: 0 none; 1 fp32 residual same layout; 3 fp16 residual same layout.
// SCORE:   0 none; 1 store s-part scores (BATCHED over layers via blockIdx.z);
//          2 atomicAdd t-part scores.
// grid (N/128, M/128[, NL when SCORE==1]), 128 threads (4 warps, 2x2).
// ---------------------------------------------------------------------------
template <int RELU, int OUTH, int ADDMODE, int SCORE>
__global__ __launch_bounds__(128)
void tc_gemm(const __half* __restrict__ A, const __half* __restrict__ W,
             const float* __restrict__ bias, float* __restrict__ Cf,
             __half* __restrict__ Ch, const void* __restrict__ Res,
             const float* __restrict__ aw, float* __restrict__ sbuf,
             int K, int N) {
    __shared__ float s_bias[BN];
    extern __shared__ __align__(1024) char dynsmem[];
    const uint32_t dynbase = smem_u32(dynsmem);

    if (SCORE == 1) {                  // batched over layers
        const int zl = blockIdx.z;
        W    += (size_t)zl * ND * ND;
        bias += zl * ND;
        Ch   += (size_t)zl * NTOK * ND;
        aw   += zl * NH * 2 * NSUB;
        sbuf += (size_t)zl * NH * TT * NB;
    }

    const int tid = threadIdx.x;
    const int wid = tid >> 5, lid = tid & 31;
    const int wm_ = wid >> 1, wn_ = wid & 1;
    const int m0 = blockIdx.y * BM, n0 = blockIdx.x * BN;

    s_bias[tid] = bias[n0 + tid];

    const __half* Abase = A + (size_t)m0 * K;
    const __half* Wbase = W + (size_t)n0 * K;
    const int NCH = K / BKH;

    const int sub = lid >> 3, wi = lid & 7;
    const int csel = sub >> 1;
    const int arow = wm_ * 64 + (sub & 1) * 8 + wi;
    const int brow = wn_ * 64 + (sub & 1) * 8 + wi;
    const int axor = arow & 7, bxor = brow & 7;

    #pragma unroll
    for (int c = 0; c < NSTAGE - 1; c++)
        load_stage(Abase + c * BKH, Wbase + c * BKH, K,
                   dynbase + c * STAGE_BYTES,
                   dynbase + c * STAGE_BYTES + A_BYTES, tid);

    float acc[4][8][4] = {};
    uint32_t afr[2][4][4], bfr[2][4][4];

    int stage = 0;
    for (int i = 0; i < NCH; i++) {
        CP_WAIT1();
        __syncthreads();
        int j = i + NSTAGE - 1;
        int sj = stage + NSTAGE - 1; if (sj >= NSTAGE) sj -= NSTAGE;
        if (j < NCH) {
            load_stage(Abase + j * BKH, Wbase + j * BKH, K,
                       dynbase + sj * STAGE_BYTES,
                       dynbase + sj * STAGE_BYTES + A_BYTES, tid);
        } else {
            CP_COMMIT();
        }

        const uint32_t aB = dynbase + stage * STAGE_BYTES;
        const uint32_t bB = aB + A_BYTES;

        load_frags(aB, bB, 0, arow, brow, axor, bxor, csel, afr[0], bfr[0]);
        #pragma unroll
        for (int ks = 0; ks < 4; ks++) {
            int cur = ks & 1;
            if (ks < 3)
                load_frags(aB, bB, ks + 1, arow, brow, axor, bxor, csel,
                           afr[cur ^ 1], bfr[cur ^ 1]);
            #pragma unroll
            for (int mt = 0; mt < 4; mt++)
                #pragma unroll
                for (int nt = 0; nt < 8; nt++)
                    mma16816(acc[mt][nt], afr[cur][mt],
                             bfr[cur][nt >> 1][nt & 1],
                             bfr[cur][nt >> 1][(nt & 1) + 2]);
        }
        if (++stage == NSTAGE) stage = 0;
    }

    float waw[16];
    const int shead = (n0 >> 6) + wn_;
    if (SCORE) {
        const int off = (SCORE == 2) ? 64 : 0;
        #pragma unroll
        for (int nt = 0; nt < 8; nt++) {
            int u = nt * 8 + (lid & 3) * 2;
            waw[nt * 2]     = __ldg(aw + shead * 128 + off + u);
            waw[nt * 2 + 1] = __ldg(aw + shead * 128 + off + u + 1);
        }
    }

    #pragma unroll
    for (int mt = 0; mt < 4; mt++) {
        int row = m0 + wm_ * 64 + mt * 16 + (lid >> 2);
        size_t rb0 = (size_t)row * N;
        size_t rb1 = (size_t)(row + 8) * N;
        float sc0 = 0.f, sc1 = 0.f;
        #pragma unroll
        for (int nt = 0; nt < 8; nt++) {
            int coll = wn_ * 64 + nt * 8 + (lid & 3) * 2;
            int col = n0 + coll;
            float bx = s_bias[coll], by = s_bias[coll + 1];
            float v0 = acc[mt][nt][0] + bx, v1 = acc[mt][nt][1] + by;
            float v2 = acc[mt][nt][2] + bx, v3 = acc[mt][nt][3] + by;
            if (ADDMODE == 1) {
                const float* Rf = (const float*)Res;
                float2 r0 = *(const float2*)(Rf + rb0 + col);
                float2 r1 = *(const float2*)(Rf + rb1 + col);
                v0 += r0.x; v1 += r0.y; v2 += r1.x; v3 += r1.y;
            } else if (ADDMODE == 3) {
                const __half* Rh = (const __half*)Res;
                float2 r0 = __half22float2(*(const __half2*)(Rh + rb0 + col));
                float2 r1 = __half22float2(*(const __half2*)(Rh + rb1 + col));
                v0 += r0.x; v1 += r0.y; v2 += r1.x; v3 += r1.y;
            }
            if (RELU) {
                v0 = fmaxf(v0, 0.f); v1 = fmaxf(v1, 0.f);
                v2 = fmaxf(v2, 0.f); v3 = fmaxf(v3, 0.f);
            }
            if (SCORE) {
                sc0 += v0 * waw[nt * 2] + v1 * waw[nt * 2 + 1];
                sc1 += v2 * waw[nt * 2] + v3 * waw[nt * 2 + 1];
            }
            if (OUTH) {
                *(__half2*)(Ch + (size_t)row * N + col)       = __floats2half2_rn(v0, v1);
                *(__half2*)(Ch + (size_t)(row + 8) * N + col) = __floats2half2_rn(v2, v3);
            } else {
                *(float2*)(Cf + (size_t)row * N + col)       = make_float2(v0, v1);
                *(float2*)(Cf + (size_t)(row + 8) * N + col) = make_float2(v2, v3);
            }
        }
        if (SCORE) {
            sc0 += __shfl_xor_sync(0xffffffffu, sc0, 1);
            sc0 += __shfl_xor_sync(0xffffffffu, sc0, 2);
            sc1 += __shfl_xor_sync(0xffffffffu, sc1, 1);
            sc1 += __shfl_xor_sync(0xffffffffu, sc1, 2);
            if ((lid & 3) == 0) {
                int tok0 = row, tok1 = row + 8;        // tok = t*NB + b
                int t0_ = tok0 >> 8, b0_ = tok0 & 255;
                int t1_ = tok1 >> 8, b1_ = tok1 & 255;
                float* sp0 = sbuf + (shead * TT + t0_) * NB + b0_;
                float* sp1 = sbuf + (shead * TT + t1_) * NB + b1_;
                if (SCORE == 1) { *sp0 = sc0; *sp1 = sc1; }
                else           { atomicAdd(sp0, sc0); atomicAdd(sp1, sc1); }
            }
        }
    }
}

// ---------------------------------------------------------------------------
// msg tensor-core kernel: per (head, 128 tokens) block. Rows p = t*NB+b.
// wm[p, h*64+u] = relu(wts[h,t,b] * (sum_s prod[p,s]*mw[h,u,s] + mb[h,u]))
// prod = fp16(s)*fp16(t) (half2 mul), mw fp16, fp32 accumulation.
// ---------------------------------------------------------------------------
__global__ __launch_bounds__(128)
void msg_mma_kernel(const __half* __restrict__ mwh,
                    const float* __restrict__ mb,
                    const __half* __restrict__ s_h) {
    __shared__ __align__(16) __half prodS[128 * 64];
    __shared__ __align__(16) __half mwS[64 * 64];
    __shared__ float wtsS[128];
    __shared__ float mbS[64];

    const int h  = blockIdx.y;
    const int p0 = blockIdx.x * 128;
    const int tid = threadIdx.x;
    const int wid = tid >> 5, lid = tid & 31;

    {   // wts for rows p0..p0+127 (b contiguous within block)
        int p = p0 + tid;
        int t = p >> 8, b = p & 255;
        wtsS[tid] = g_wts[(h * TT + t) * NB + b];
    }
    if (tid < 64) mbS[tid] = mb[h * 64 + tid];

    {   // mw tile via cp.async (64 rows x 128B, swizzled)
        uint32_t base = smem_u32(mwS);
        #pragma unroll
        for (int it = 0; it < 4; it++) {
            int q = tid + it * 128;
            int r = q >> 3, c = q & 7;
            uint32_t off = (uint32_t)(r * 128 + ((c ^ (r & 7)) << 4));
            cp_async16(base + off, mwh + (size_t)(h * 64 + r) * 64 + c * 8);
        }
        CP_COMMIT();
    }
    {   // prod tile: s*t on load (coalesced 16B), swizzled store
        #pragma unroll
        for (int it = 0; it < 8; it++) {
            int q = tid + it * 128;
            int r = q >> 3, c = q & 7;
            size_t gidx = (size_t)(p0 + r) * ND + h * NSUB + c * 8;
            uint4 sr = *(const uint4*)(s_h + gidx);
            uint4 tr = *(const uint4*)(g_t_h + gidx);
            __half2 a0 = __hmul2(*(__half2*)&sr.x, *(__half2*)&tr.x);
            __half2 a1 = __hmul2(*(__half2*)&sr.y, *(__half2*)&tr.y);
            __half2 a2 = __hmul2(*(__half2*)&sr.z, *(__half2*)&tr.z);
            __half2 a3 = __hmul2(*(__half2*)&sr.w, *(__half2*)&tr.w);
            uint4 p4;
            p4.x = *(uint32_t*)&a0; p4.y = *(uint32_t*)&a1;
            p4.z = *(uint32_t*)&a2; p4.w = *(uint32_t*)&a3;
            uint32_t off = (uint32_t)(r * 128 + ((c ^ (r & 7)) << 4));
            *(uint4*)((char*)prodS + off) = p4;
        }
    }
    CP_WAIT0();
    __syncthreads();

    const int sub = lid >> 3, wi = lid & 7;
    const int csel = sub >> 1;
    const int arow = wid * 32 + (sub & 1) * 8 + wi;
    const int brow = (sub & 1) * 8 + wi;
    const int axor = arow & 7, bxor = brow & 7;
    const uint32_t aB = smem_u32(prodS), bB = smem_u32(mwS);

    float acc[2][8][4] = {};
    #pragma unroll
    for (int ks = 0; ks < 4; ks++) {
        uint32_t af[2][4], bf[4][4];
        #pragma unroll
        for (int mt = 0; mt < 2; mt++)
            ldsm_x4(af[mt], aB + (uint32_t)((arow + mt * 16) * 128)
                               + (uint32_t)((((ks << 1) + csel) ^ axor) << 4));
        #pragma unroll
        for (int np = 0; np < 4; np++)
            ldsm_x4(bf[np], bB + (uint32_t)((brow + np * 16) * 128)
                               + (uint32_t)((((ks << 1) + csel) ^ bxor) << 4));
        #pragma unroll
        for (int mt = 0; mt < 2; mt++)
            #pragma unroll
            for (int nt = 0; nt < 8; nt++)
                mma16816(acc[mt][nt], af[mt],
                         bf[nt >> 1][nt & 1], bf[nt >> 1][(nt & 1) + 2]);
    }

    #pragma unroll
    for (int mt = 0; mt < 2; mt++) {
        int rowl = wid * 32 + mt * 16 + (lid >> 2);
        float wt0 = wtsS[rowl], wt1 = wtsS[rowl + 8];
        size_t ob0 = (size_t)(p0 + rowl) * ND + h * NSUB;
        size_t ob1 = (size_t)(p0 + rowl + 8) * ND + h * NSUB;
        #pragma unroll
        for (int nt = 0; nt < 8; nt++) {
            int u = nt * 8 + (lid & 3) * 2;
            float m0 = acc[mt][nt][0] + mbS[u], m1 = acc[mt][nt][1] + mbS[u + 1];
            float m2 = acc[mt][nt][2] + mbS[u], m3 = acc[mt][nt][3] + mbS[u + 1];
            float v0 = fmaxf(wt0 * m0, 0.f), v1 = fmaxf(wt0 * m1, 0.f);
            float v2 = fmaxf(wt1 * m2, 0.f), v3 = fmaxf(wt1 * m3, 0.f);
            *(__half2*)(g_wm_h + ob0 + u) = __floats2half2_rn(v0, v1);
            *(__half2*)(g_wm_h + ob1 + u) = __floats2half2_rn(v2, v3);
        }
    }
}

// ---------------------------------------------------------------------------
__global__ __launch_bounds__(256)
void f32_to_f16_kernel(const float4* __restrict__ in, __half2* __restrict__ out, int n4) {
    for (int i = blockIdx.x * 256 + threadIdx.x; i < n4; i += gridDim.x * 256) {
        float4 v = in[i];
        out[2 * i]     = __floats2half2_rn(v.x, v.y);
        out[2 * i + 1] = __floats2half2_rn(v.z, v.w);
    }
}

// ---------------------------------------------------------------------------
__device__ __forceinline__ float block_reduce_sum256(float v) {
    __shared__ float sh[8];
    int lane = threadIdx.x & 31, wid = threadIdx.x >> 5;
    #pragma unroll
    for (int o = 16; o; o >>= 1) v += __shfl_xor_sync(0xffffffffu, v, o);
    if (lane == 0) sh[wid] = v;
    __syncthreads();
    float r = (lane < 8) ? sh[lane] : 0.0f;
    #pragma unroll
    for (int o = 4; o; o >>= 1) r += __shfl_xor_sync(0xffffffffu, r, o);
    r = __shfl_sync(0xffffffffu, r, 0);
    __syncthreads();
    return r;
}
__device__ __forceinline__ float block_reduce_max256(float v) {
    __shared__ float sh[8];
    int lane = threadIdx.x & 31, wid = threadIdx.x >> 5;
    #pragma unroll
    for (int o = 16; o; o >>= 1) v = fmaxf(v, __shfl_xor_sync(0xffffffffu, v, o));
    if (lane == 0) sh[wid] = v;
    __syncthreads();
    float r = (lane < 8) ? sh[lane] : -3.4e38f;
    #pragma unroll
    for (int o = 4; o; o >>= 1) r = fmaxf(r, __shfl_xor_sync(0xffffffffu, r, o));
    r = __shfl_sync(0xffffffffu, r, 0);
    __syncthreads();
    return r;
}

// softmax over b; attn bias ab[h] cancels in softmax.
__global__ __launch_bounds__(256)
void softmax_kernel(const float* __restrict__ sbuf) {
    int ht = blockIdx.x;
    float v = sbuf[(size_t)ht * NB + threadIdx.x];
    float m = block_reduce_max256(v);
    float e = __expf(v - m);
    float s = block_reduce_sum256(e);
    g_wts[(size_t)ht * NB + threadIdx.x] = e / s;
}

// ---------------------------------------------------------------------------
// Warp-per-token LayerNorms. 8 warps/block. Rows p (layout-agnostic).
// ---------------------------------------------------------------------------
__global__ __launch_bounds__(256)
void ln1_kernel(const float* __restrict__ gam, const float* __restrict__ bet) {
    const int tok = blockIdx.x * 8 + (threadIdx.x >> 5);
    const int l = threadIdx.x & 31;
    const float4* a = (const float4*)(g_agg + (size_t)tok * ND);
    float4 v[4];
    float s = 0.f;
    #pragma unroll
    for (int k = 0; k < 4; k++) {
        v[k] = a[l + 32 * k];
        s += (v[k].x + v[k].y) + (v[k].z + v[k].w);
    }
    #pragma unroll
    for (int o = 16; o; o >>= 1) s += __shfl_xor_sync(0xffffffffu, s, o);
    const float mean = s * (1.0f / ND);
    float q = 0.f;
    #pragma unroll
    for (int k = 0; k < 4; k++) {
        v[k].x -= mean; v[k].y -= mean; v[k].z -= mean; v[k].w -= mean;
        q += (v[k].x * v[k].x + v[k].y * v[k].y) + (v[k].z * v[k].z + v[k].w * v[k].w);
    }
    #pragma unroll
    for (int o = 16; o; o >>= 1) q += __shfl_xor_sync(0xffffffffu, q, o);
    const float rstd = rsqrtf(q * (1.0f / ND) + 1e-5f);
    uint2* xr = (uint2*)(g_x_h + (size_t)tok * ND);
    #pragma unroll
    for (int k = 0; k < 4; k++) {
        int idx = l + 32 * k;
        float4 gg = *(const float4*)(gam + idx * 4);
        float4 bb = *(const float4*)(bet + idx * 4);
        __half2 h0 = __floats2half2_rn(v[k].x * rstd * gg.x + bb.x,
                                       v[k].y * rstd * gg.y + bb.y);
        __half2 h1 = __floats2half2_rn(v[k].z * rstd * gg.z + bb.z,
                                       v[k].w * rstd * gg.w + bb.w);
        uint2 u; u.x = *(uint32_t*)&h0; u.y = *(uint32_t*)&h1;
        xr[idx] = u;
    }
}

__global__ __launch_bounds__(256)
void ln2_kernel(const float* __restrict__ gam, const float* __restrict__ bet,
                float* __restrict__ out, int mode) {
    const int p = blockIdx.x * 8 + (threadIdx.x >> 5);
    const int l = threadIdx.x & 31;
    const float4* a = (const float4*)(g_y + (size_t)p * ND);
    float4 v[4];
    float s = 0.f;
    #pragma unroll
    for (int k = 0; k < 4; k++) {
        v[k] = a[l + 32 * k];
        s += (v[k].x + v[k].y) + (v[k].z + v[k].w);
    }
    #pragma unroll
    for (int o = 16; o; o >>= 1) s += __shfl_xor_sync(0xffffffffu, s, o);
    const float mean = s * (1.0f / ND);
    float q = 0.f;
    #pragma unroll
    for (int k = 0; k < 4; k++) {
        v[k].x -= mean; v[k].y -= mean; v[k].z -= mean; v[k].w -= mean;
        q += (v[k].x * v[k].x + v[k].y * v[k].y) + (v[k].z * v[k].z + v[k].w * v[k].w);
    }
    #pragma unroll
    for (int o = 16; o; o >>= 1) q += __shfl_xor_sync(0xffffffffu, q, o);
    const float rstd = rsqrtf(q * (1.0f / ND) + 1e-5f);
    const size_t obase = (size_t)p * ND;
    float4* orow = (float4*)(out + obase);
    uint2*  hrow = (uint2*)(g_src_h + obase);
    #pragma unroll
    for (int k = 0; k < 4; k++) {
        int idx = l + 32 * k;
        float4 gg = *(const float4*)(gam + idx * 4);
        float4 bb = *(const float4*)(bet + idx * 4);
        float4 o4;
        o4.x = v[k].x * rstd * gg.x + bb.x;
        o4.y = v[k].y * rstd * gg.y + bb.y;
        o4.z = v[k].z * rstd * gg.z + bb.z;
        o4.w = v[k].w * rstd * gg.w + bb.w;
        if (mode == 0) {
            orow[idx] = o4;
        } else {
            __half2 h0 = __floats2half2_rn(o4.x, o4.y);
            __half2 h1 = __floats2half2_rn(o4.z, o4.w);
            uint2 u; u.x = *(uint32_t*)&h0; u.y = *(uint32_t*)&h1;
            hrow[idx] = u;
        }
    }
}

// ---------------------------------------------------------------------------
extern "C" void kernel_launch(void* const* d_in, const int* in_sizes, int n_in,
                              void* d_out, int out_size) {
    const float* in_src  = (const float*)d_in[0];
    const float* in_srcc = (const float*)d_in[1];
    const float* w_sp = (const float*)d_in[2];
    const float* b_sp = (const float*)d_in[3];
    const float* w_tp = (const float*)d_in[4];
    const float* b_tp = (const float*)d_in[5];
    const float* w_at = (const float*)d_in[6];
    const float* w_mg = (const float*)d_in[8];
    const float* b_mg = (const float*)d_in[9];
    const float* w_ag = (const float*)d_in[10];
    const float* b_ag = (const float*)d_in[11];
    const float* w_l1 = (const float*)d_in[12];
    const float* b_l1 = (const float*)d_in[13];
    const float* w_l2 = (const float*)d_in[14];
    const float* b_l2 = (const float*)d_in[15];
    const float* g_n1 = (const float*)d_in[16];
    const float* bb_n1 = (const float*)d_in[17];
    const float* g_n2 = (const float*)d_in[18];
    const float* bb_n2 = (const float*)d_in[19];

    float *p_agg, *p_y, *p_scores;
    __half *p_s_h, *p_t_h, *p_wm_h, *p_x_h, *p_h1_h, *p_src_h, *p_srcc_h, *p_src0_h;
    __half *p_wsp, *p_wtp, *p_wag, *p_wl1, *p_wl2, *p_wmg;
    cudaGetSymbolAddress((void**)&p_s_h,    g_s_h);
    cudaGetSymbolAddress((void**)&p_t_h,    g_t_h);
    cudaGetSymbolAddress((void**)&p_scores, g_scores);
    cudaGetSymbolAddress((void**)&p_agg,    g_agg);
    cudaGetSymbolAddress((void**)&p_y,      g_y);
    cudaGetSymbolAddress((void**)&p_wm_h,   g_wm_h);
    cudaGetSymbolAddress((void**)&p_x_h,    g_x_h);
    cudaGetSymbolAddress((void**)&p_h1_h,   g_h1_h);
    cudaGetSymbolAddress((void**)&p_src_h,  g_src_h);
    cudaGetSymbolAddress((void**)&p_srcc_h, g_srcc_h);
    cudaGetSymbolAddress((void**)&p_src0_h, g_src0_h);
    cudaGetSymbolAddress((void**)&p_wsp,    g_wsp_h);
    cudaGetSymbolAddress((void**)&p_wtp,    g_wtp_h);
    cudaGetSymbolAddress((void**)&p_wag,    g_wag_h);
    cudaGetSymbolAddress((void**)&p_wl1,    g_wl1_h);
    cudaGetSymbolAddress((void**)&p_wl2,    g_wl2_h);
    cudaGetSymbolAddress((void**)&p_wmg,    g_wmg_h);

    cudaFuncSetAttribute(tc_gemm<1, 1, 0, 1>, cudaFuncAttributeMaxDynamicSharedMemorySize, DYN_SMEM);
    cudaFuncSetAttribute(tc_gemm<1, 1, 0, 2>, cudaFuncAttributeMaxDynamicSharedMemorySize, DYN_SMEM);
    cudaFuncSetAttribute(tc_gemm<0, 0, 1, 0>, cudaFuncAttributeMaxDynamicSharedMemorySize, DYN_SMEM);
    cudaFuncSetAttribute(tc_gemm<1, 1, 0, 0>, cudaFuncAttributeMaxDynamicSharedMemorySize, DYN_SMEM);
    cudaFuncSetAttribute(tc_gemm<0, 0, 3, 0>, cudaFuncAttributeMaxDynamicSharedMemorySize, DYN_SMEM);

    // one-time fp16 conversions
    f32_to_f16_kernel<<<2048, 256>>>((const float4*)in_srcc, (__half2*)p_srcc_h, NTOK * ND / 4);
    f32_to_f16_kernel<<<2048, 256>>>((const float4*)in_src,  (__half2*)p_src0_h, NTOK * ND / 4);
    f32_to_f16_kernel<<<2048, 256>>>((const float4*)w_sp, (__half2*)p_wsp, NL * ND * ND / 4);
    f32_to_f16_kernel<<<2048, 256>>>((const float4*)w_tp, (__half2*)p_wtp, NL * ND * ND / 4);
    f32_to_f16_kernel<<<2048, 256>>>((const float4*)w_ag, (__half2*)p_wag, NL * ND * ND / 4);
    f32_to_f16_kernel<<<2048, 256>>>((const float4*)w_l1, (__half2*)p_wl1, NL * NDFF * ND / 4);
    f32_to_f16_kernel<<<2048, 256>>>((const float4*)w_l2, (__half2*)p_wl2, NL * ND * NDFF / 4);
    f32_to_f16_kernel<<<192, 256>>>((const float4*)w_mg, (__half2*)p_wmg,
                                    NL * NH * NSUB * NSUB / 4);

    // hoisted: ALL layers' s = relu(srcc @ sw_l^T + sb_l) + s-part scores
    tc_gemm<1, 1, 0, 1><<<dim3(ND / BN, NTOK / BM, NL), 128, DYN_SMEM>>>(
        p_srcc_h, p_wsp, b_sp, nullptr, p_s_h, nullptr, w_at, p_scores, ND, ND);

    const dim3 gemm_dd(ND / BN, NTOK / BM);
    for (int l = 0; l < NL; l++) {
        const __half* srcA = (l == 0) ? p_src0_h : p_src_h;
        const float*  awl  = w_at + (size_t)l * NH * 2 * NSUB;
        float* sbl = p_scores + (size_t)l * NH * TT * NB;

        // t = relu(src @ tw^T + tb) [fp16 out] + ATOMIC-ADD t-part scores
        tc_gemm<1, 1, 0, 2><<<gemm_dd, 128, DYN_SMEM>>>(
            srcA, p_wtp + (size_t)l * ND * ND, b_tp + l * ND,
            nullptr, p_t_h, nullptr, awl, sbl, ND, ND);
        // softmax over batch
        softmax_kernel<<<NH * TT, NB>>>(sbl);
        // weighted message via tensor cores -> relu(wm) fp16, rows p
        msg_mma_kernel<<<dim3(NTOK / 128, NH), 128>>>(
            p_wmg + (size_t)l * NH * NSUB * NSUB, b_mg + l * NH * NSUB,
            p_s_h + (size_t)l * NTOK * ND);
        // agg = wm @ gw^T + gb + src  [fp32 out, same-layout residual fused]
        if (l == 0)
            tc_gemm<0, 0, 1, 0><<<gemm_dd, 128, DYN_SMEM>>>(
                p_wm_h, p_wag + (size_t)l * ND * ND, b_ag + l * ND,
                p_agg, nullptr, in_src, nullptr, nullptr, ND, ND);
        else
            tc_gemm<0, 0, 3, 0><<<gemm_dd, 128, DYN_SMEM>>>(
                p_wm_h, p_wag + (size_t)l * ND * ND, b_ag + l * ND,
                p_agg, nullptr, p_src_h, nullptr, nullptr, ND, ND);
        // x = LN(agg')  [fp16 only]
        ln1_kernel<<<NTOK / 8, 256>>>(g_n1 + l * ND, bb_n1 + l * ND);
        // h1 = relu(x @ w1^T + b1)  [fp16 out]
        tc_gemm<1, 1, 0, 0><<<dim3(NDFF / BN, NTOK / BM), 128, DYN_SMEM>>>(
            p_x_h, p_wl1 + (size_t)l * NDFF * ND, b_l1 + l * NDFF,
            nullptr, p_h1_h, nullptr, nullptr, nullptr, ND, NDFF);
        // y = h1 @ w2^T + b2 + x(fp16)  [fp32 out, fp16 residual fused]
        tc_gemm<0, 0, 3, 0><<<gemm_dd, 128, DYN_SMEM>>>(
            p_h1_h, p_wl2 + (size_t)l * ND * NDFF, b_l2 + l * ND,
            p_y, nullptr, p_x_h, nullptr, nullptr, NDFF, ND);
        // out = LN(y') row p: last layer fp32 d_out, else fp16 g_src_h
        ln2_kernel<<<NTOK / 8, 256>>>(g_n2 + l * ND, bb_n2 + l * ND,
                                      (float*)d_out, (l == NL - 1) ? 0 : 1);
    }
}